// round 1
// baseline (speedup 1.0000x reference)
#include <cuda_runtime.h>
#include <math.h>

#define B 2
#define S 2048
#define D 2048
#define H 16
#define HKV 4
#define HD 128
#define M_ROWS (B*S)     // 4096
#define QN (H*HD)        // 2048
#define KN (HKV*HD)      // 512

// Scratch (allocation-free: device globals)
__device__ float g_q[(size_t)M_ROWS * QN];
__device__ float g_k[(size_t)M_ROWS * KN];
__device__ float g_v[(size_t)M_ROWS * KN];
__device__ float g_attn[(size_t)M_ROWS * QN];

// ---------------------------------------------------------------------------
// SGEMM: C[M,N] = A[M,K] @ B[K,N], all row-major fp32.
// 128x128 block tile, BK=16, 8x8 microtile, 256 threads.
// ---------------------------------------------------------------------------
#define GBM 128
#define GBN 128
#define GBK 16

__global__ void __launch_bounds__(256)
sgemm_kernel(const float* __restrict__ A, const float* __restrict__ Bm,
             float* __restrict__ C, int M, int N, int K) {
  __shared__ float As[GBK][GBM + 4];
  __shared__ float Bs[GBK][GBN + 4];
  const int tid = threadIdx.x;
  const int tx = tid & 15, ty = tid >> 4;
  const int bx = blockIdx.x, by = blockIdx.y;
  const float* Ab = A + (size_t)by * GBM * K;
  const float* Bb = Bm + (size_t)bx * GBN;

  float acc[8][8];
#pragma unroll
  for (int i = 0; i < 8; i++)
#pragma unroll
    for (int j = 0; j < 8; j++) acc[i][j] = 0.f;

  for (int k0 = 0; k0 < K; k0 += GBK) {
#pragma unroll
    for (int l = 0; l < 2; l++) {
      int idx = tid + l * 256;
      int ar = idx >> 2, ac4 = idx & 3;
      float4 av = *(const float4*)(Ab + (size_t)ar * K + k0 + ac4 * 4);
      As[ac4 * 4 + 0][ar] = av.x;
      As[ac4 * 4 + 1][ar] = av.y;
      As[ac4 * 4 + 2][ar] = av.z;
      As[ac4 * 4 + 3][ar] = av.w;
      int br = idx >> 5, bc4 = idx & 31;
      float4 bv = *(const float4*)(Bb + (size_t)(k0 + br) * N + bc4 * 4);
      *(float4*)(&Bs[br][bc4 * 4]) = bv;
    }
    __syncthreads();
#pragma unroll
    for (int kk = 0; kk < GBK; kk++) {
      float4 a0 = *(const float4*)(&As[kk][ty * 8]);
      float4 a1 = *(const float4*)(&As[kk][ty * 8 + 4]);
      float4 b0 = *(const float4*)(&Bs[kk][tx * 8]);
      float4 b1 = *(const float4*)(&Bs[kk][tx * 8 + 4]);
      float a[8] = {a0.x, a0.y, a0.z, a0.w, a1.x, a1.y, a1.z, a1.w};
      float b[8] = {b0.x, b0.y, b0.z, b0.w, b1.x, b1.y, b1.z, b1.w};
#pragma unroll
      for (int i = 0; i < 8; i++)
#pragma unroll
        for (int j = 0; j < 8; j++) acc[i][j] += a[i] * b[j];
    }
    __syncthreads();
  }
  float* Cb = C + (size_t)(by * GBM + ty * 8) * N + bx * GBN + tx * 8;
#pragma unroll
  for (int i = 0; i < 8; i++) {
    float4 c0 = make_float4(acc[i][0], acc[i][1], acc[i][2], acc[i][3]);
    float4 c1 = make_float4(acc[i][4], acc[i][5], acc[i][6], acc[i][7]);
    *(float4*)(Cb + (size_t)i * N) = c0;
    *(float4*)(Cb + (size_t)i * N + 4) = c1;
  }
}

// ---------------------------------------------------------------------------
// RoPE, in place on q and k. One block (64 threads) per (b,s,head) row.
// out[j]    = x[2j]*cos - x[2j+1]*sin
// out[64+j] = x[2j]*sin + x[2j+1]*cos
// ---------------------------------------------------------------------------
__global__ void rope_kernel(float* __restrict__ q, float* __restrict__ k) {
  const int row = blockIdx.x;                 // 0 .. B*S*(H+HKV)-1
  const int nh = H + HKV;
  const int bs = row / nh;
  const int hh = row - bs * nh;
  const int s = bs & (S - 1);
  float* p = (hh < H) ? (q + (size_t)bs * QN + hh * HD)
                      : (k + (size_t)bs * KN + (hh - H) * HD);
  const int j = threadIdx.x;                  // 0..63
  const float x1 = p[2 * j];
  const float x2 = p[2 * j + 1];
  // theta_j = 10000^(-j/64); log2(10000)/64 = 0.20762050593045983
  const float theta = exp2f(-(float)j * 0.20762050593045983f);
  const float ang = (float)s * theta;
  float sn, cs;
  sincosf(ang, &sn, &cs);                     // accurate version: args up to 2048 rad
  __syncthreads();                            // all reads before in-place writes
  p[j] = x1 * cs - x2 * sn;
  p[j + 64] = x1 * sn + x2 * cs;
}

// ---------------------------------------------------------------------------
// Flash attention (causal, GQA). One block per (q-tile of 128 rows, b*h).
// BM=128, BN=64, 256 threads. Online softmax. O accum in registers (8x8/thr).
// Q/K smem XOR-swizzled for conflict-free float4 fragment loads.
// ---------------------------------------------------------------------------
#define ATTN_SMEM_FLOATS (128*128 + 64*128 + 64*128 + 128*68 + 3*128)
#define ATTN_SMEM_BYTES  (ATTN_SMEM_FLOATS * 4)

__global__ void __launch_bounds__(256, 1)
attn_kernel(const float* __restrict__ Q, const float* __restrict__ K,
            const float* __restrict__ V, float* __restrict__ O) {
  extern __shared__ float sm[];
  float* Qs = sm;                   // [128][128], col-group XOR (r&7)
  float* Ks = Qs + 128 * 128;       // [64][128],  col-group XOR ((n>>2)&7)
  float* Vs = Ks + 64 * 128;        // [64][128],  plain
  float* Ps = Vs + 64 * 128;        // [128][68]   scores -> probabilities
  float* mrow = Ps + 128 * 68;      // [128]
  float* lrow = mrow + 128;         // [128]
  float* asc  = lrow + 128;         // [128] per-tile rescale factor

  const int tid = threadIdx.x;
  const int qi = (int)gridDim.x - 1 - (int)blockIdx.x;  // heavy tiles first
  const int bh = blockIdx.y;
  const int b = bh >> 4;
  const int h = bh & 15;
  const int hk = h >> 2;            // GQA: rep = H/HKV = 4
  const int q0 = qi * 128;

  const float* qb = Q + (size_t)b * S * QN + h * HD;
  const float* kb = K + (size_t)b * S * KN + hk * HD;
  const float* vb = V + (size_t)b * S * KN + hk * HD;

  // Load Q tile (128x128) swizzled
#pragma unroll
  for (int i = 0; i < 16; i++) {
    int idx = tid + i * 256;
    int r = idx >> 5, d4 = idx & 31;
    float4 val = *(const float4*)(qb + (size_t)(q0 + r) * QN + d4 * 4);
    *(float4*)(Qs + r * 128 + ((d4 ^ (r & 7)) << 2)) = val;
  }
  if (tid < 128) { mrow[tid] = -INFINITY; lrow[tid] = 0.f; }

  const int ty = tid >> 4, tx = tid & 15;   // rows 8*ty+i, score cols 4*tx+j
  const int ck = (tx & 7) << 2;
  float acc[8][8];
#pragma unroll
  for (int i = 0; i < 8; i++)
#pragma unroll
    for (int j = 0; j < 8; j++) acc[i][j] = 0.f;

  const float qk_scale = 0.08838834764831845f;  // 1/sqrt(128)

  for (int k0 = 0; k0 <= q0 + 64; k0 += 64) {
    __syncthreads();  // previous tile's Ps/Vs consumers done
    // Load K,V tiles (64x128 each)
#pragma unroll
    for (int i = 0; i < 8; i++) {
      int idx = tid + i * 256;
      int n = idx >> 5, d4 = idx & 31;
      float4 kv = *(const float4*)(kb + (size_t)(k0 + n) * KN + d4 * 4);
      *(float4*)(Ks + n * 128 + ((d4 ^ ((n >> 2) & 7)) << 2)) = kv;
      float4 vv = *(const float4*)(vb + (size_t)(k0 + n) * KN + d4 * 4);
      *(float4*)(Vs + n * 128 + d4 * 4) = vv;
    }
    __syncthreads();

    // ---- scores: S[8ty+i][4tx+j] = Q . K ----
    float s[8][4];
#pragma unroll
    for (int i = 0; i < 8; i++)
#pragma unroll
      for (int j = 0; j < 4; j++) s[i][j] = 0.f;

#pragma unroll 2
    for (int kk = 0; kk < 128; kk += 4) {
      float4 bf[4];
#pragma unroll
      for (int j = 0; j < 4; j++)
        bf[j] = *(const float4*)(Ks + (4 * tx + j) * 128 + (kk ^ ck));
#pragma unroll
      for (int i = 0; i < 8; i++) {
        float4 a = *(const float4*)(Qs + (8 * ty + i) * 128 + (kk ^ (i << 2)));
#pragma unroll
        for (int j = 0; j < 4; j++) {
          s[i][j] += a.x * bf[j].x;
          s[i][j] += a.y * bf[j].y;
          s[i][j] += a.z * bf[j].z;
          s[i][j] += a.w * bf[j].w;
        }
      }
    }

    // ---- write scaled+masked scores to Ps ----
    if (k0 + 63 > q0) {
#pragma unroll
      for (int i = 0; i < 8; i++) {
        int qr = q0 + 8 * ty + i;
#pragma unroll
        for (int j = 0; j < 4; j++) {
          int kc = k0 + 4 * tx + j;
          Ps[(8 * ty + i) * 68 + 4 * tx + j] =
              (kc <= qr) ? s[i][j] * qk_scale : -1e30f;
        }
      }
    } else {
#pragma unroll
      for (int i = 0; i < 8; i++)
#pragma unroll
        for (int j = 0; j < 4; j++)
          Ps[(8 * ty + i) * 68 + 4 * tx + j] = s[i][j] * qk_scale;
    }
    __syncthreads();

    // ---- online softmax: 2 threads per row ----
    {
      int r = tid >> 1;
      float* prow = Ps + r * 68 + (tid & 1) * 32;
      float mloc = -INFINITY;
#pragma unroll
      for (int j = 0; j < 32; j++) mloc = fmaxf(mloc, prow[j]);
      mloc = fmaxf(mloc, __shfl_xor_sync(0xffffffffu, mloc, 1));
      float mold = mrow[r];
      float mnew = fmaxf(mold, mloc);
      float lloc = 0.f;
#pragma unroll
      for (int j = 0; j < 32; j++) {
        float e = __expf(prow[j] - mnew);
        prow[j] = e;
        lloc += e;
      }
      lloc += __shfl_xor_sync(0xffffffffu, lloc, 1);
      if ((tid & 1) == 0) {
        float al = __expf(mold - mnew);  // exp(-inf)=0 on first tile
        asc[r] = al;
        mrow[r] = mnew;
        lrow[r] = lrow[r] * al + lloc;
      }
    }
    __syncthreads();

    // ---- PV accumulate: acc[i][0..7] over cols 8*tx.. ----
    {
      float al[8];
#pragma unroll
      for (int i = 0; i < 8; i++) al[i] = asc[8 * ty + i];
#pragma unroll
      for (int i = 0; i < 8; i++)
#pragma unroll
        for (int j = 0; j < 8; j++) acc[i][j] *= al[i];

#pragma unroll 2
      for (int kk = 0; kk < 64; kk++) {
        float4 v0 = *(const float4*)(Vs + kk * 128 + 8 * tx);
        float4 v1 = *(const float4*)(Vs + kk * 128 + 8 * tx + 4);
#pragma unroll
        for (int i = 0; i < 8; i++) {
          float p = Ps[(8 * ty + i) * 68 + kk];
          acc[i][0] += p * v0.x;
          acc[i][1] += p * v0.y;
          acc[i][2] += p * v0.z;
          acc[i][3] += p * v0.w;
          acc[i][4] += p * v1.x;
          acc[i][5] += p * v1.y;
          acc[i][6] += p * v1.z;
          acc[i][7] += p * v1.w;
        }
      }
    }
  }

  // ---- finalize: O = acc / l ----
#pragma unroll
  for (int i = 0; i < 8; i++) {
    int r = 8 * ty + i;
    float inv = 1.f / lrow[r];
    float4 o0 = make_float4(acc[i][0] * inv, acc[i][1] * inv,
                            acc[i][2] * inv, acc[i][3] * inv);
    float4 o1 = make_float4(acc[i][4] * inv, acc[i][5] * inv,
                            acc[i][6] * inv, acc[i][7] * inv);
    float* orow = O + (size_t)(b * S + q0 + r) * QN + h * HD + 8 * tx;
    *(float4*)orow = o0;
    *(float4*)(orow + 4) = o1;
  }
}

// ---------------------------------------------------------------------------
extern "C" void kernel_launch(void* const* d_in, const int* in_sizes, int n_in,
                              void* d_out, int out_size) {
  const float* x  = (const float*)d_in[0];
  const float* Wq = (const float*)d_in[1];
  const float* Wk = (const float*)d_in[2];
  const float* Wv = (const float*)d_in[3];
  const float* Wo = (const float*)d_in[4];
  float* out = (float*)d_out;

  float *q, *k, *v, *attn;
  cudaGetSymbolAddress((void**)&q, g_q);
  cudaGetSymbolAddress((void**)&k, g_k);
  cudaGetSymbolAddress((void**)&v, g_v);
  cudaGetSymbolAddress((void**)&attn, g_attn);

  dim3 blk(256);
  // QKV projections
  sgemm_kernel<<<dim3(QN / GBN, M_ROWS / GBM), blk>>>(x, Wq, q, M_ROWS, QN, D);
  sgemm_kernel<<<dim3(KN / GBN, M_ROWS / GBM), blk>>>(x, Wk, k, M_ROWS, KN, D);
  sgemm_kernel<<<dim3(KN / GBN, M_ROWS / GBM), blk>>>(x, Wv, v, M_ROWS, KN, D);
  // RoPE on q and k
  rope_kernel<<<B * S * (H + HKV), 64>>>(q, k);
  // Flash attention
  cudaFuncSetAttribute(attn_kernel, cudaFuncAttributeMaxDynamicSharedMemorySize,
                       ATTN_SMEM_BYTES);
  attn_kernel<<<dim3(S / 128, B * H), blk, ATTN_SMEM_BYTES>>>(q, k, v, attn);
  // Output projection
  sgemm_kernel<<<dim3(D / GBN, M_ROWS / GBM), blk>>>(attn, Wo, out, M_ROWS, D, QN);
}

// round 3
// speedup vs baseline: 2.5628x; 2.5628x over previous
#include <cuda_runtime.h>
#include <math.h>
#include <stdint.h>

#define B 2
#define S 2048
#define D 2048
#define H 16
#define HKV 4
#define HD 128
#define M_ROWS (B*S)     // 4096
#define QN (H*HD)        // 2048
#define KN (HKV*HD)      // 512

// Scratch (allocation-free: device globals)
__device__ float g_q[(size_t)M_ROWS * QN];
__device__ float g_k[(size_t)M_ROWS * KN];
__device__ float g_v[(size_t)M_ROWS * KN];
__device__ float g_attn[(size_t)M_ROWS * QN];

__device__ __forceinline__ float ftf(float x) {
  float r;
  asm("cvt.rna.tf32.f32 %0, %1;" : "=f"(r) : "f"(x));
  return r;
}
__device__ __forceinline__ uint32_t fu(float x) { return __float_as_uint(x); }

#define MMA_TF32(c, a, b)                                                     \
  asm("mma.sync.aligned.m16n8k8.row.col.f32.tf32.tf32.f32 "                   \
      "{%0,%1,%2,%3},{%4,%5,%6,%7},{%8,%9},{%0,%1,%2,%3};"                    \
      : "+f"(c[0]), "+f"(c[1]), "+f"(c[2]), "+f"(c[3])                        \
      : "r"(a[0]), "r"(a[1]), "r"(a[2]), "r"(a[3]), "r"(b[0]), "r"(b[1]))

// ---------------------------------------------------------------------------
// tf32 MMA GEMM: C[M,N] = A[M,K] @ B[K,N], row-major fp32 in/out.
// 128x128x32 block tile, 256 threads = 8 warps (4M x 2N), warp tile 32x64.
// ---------------------------------------------------------------------------
__global__ void __launch_bounds__(256)
mma_gemm(const float* __restrict__ A, const float* __restrict__ Bm,
         float* __restrict__ C, int M, int N, int K) {
  __shared__ float As[128][36];   // [m][k], pad 4
  __shared__ float Bs[32][132];   // [k][n], pad 4

  const int tid = threadIdx.x;
  const int lane = tid & 31;
  const int w = tid >> 5;
  const int g = lane >> 2;        // 0..7
  const int t4 = lane & 3;        // 0..3
  const int warp_m = w & 3, warp_n = w >> 2;
  const int m0w = warp_m * 32, n0w = warp_n * 64;
  const int row0 = blockIdx.y * 128;
  const int col0 = blockIdx.x * 128;

  float acc[2][8][4];
#pragma unroll
  for (int mi = 0; mi < 2; mi++)
#pragma unroll
    for (int ni = 0; ni < 8; ni++)
#pragma unroll
      for (int e = 0; e < 4; e++) acc[mi][ni][e] = 0.f;

  for (int k0 = 0; k0 < K; k0 += 32) {
#pragma unroll
    for (int l = 0; l < 4; l++) {
      int idx = tid + l * 256;
      // A tile: 128x32 floats = 1024 float4
      int ar = idx >> 3, ac = (idx & 7) << 2;
      float4 av = *(const float4*)(A + (size_t)(row0 + ar) * K + k0 + ac);
      *(float4*)(&As[ar][ac]) =
          make_float4(ftf(av.x), ftf(av.y), ftf(av.z), ftf(av.w));
      // B tile: 32x128 floats = 1024 float4   (FIXED: was float2/half-filled)
      int br = idx >> 5, bc = (idx & 31) << 2;
      float4 bv = *(const float4*)(Bm + (size_t)(k0 + br) * N + col0 + bc);
      *(float4*)(&Bs[br][bc]) =
          make_float4(ftf(bv.x), ftf(bv.y), ftf(bv.z), ftf(bv.w));
    }
    __syncthreads();
#pragma unroll
    for (int ks = 0; ks < 4; ks++) {
      const int kk = ks * 8;
      uint32_t a[2][4];
#pragma unroll
      for (int mi = 0; mi < 2; mi++) {
        int m = m0w + mi * 16;
        a[mi][0] = fu(As[m + g][kk + t4]);
        a[mi][1] = fu(As[m + g + 8][kk + t4]);
        a[mi][2] = fu(As[m + g][kk + t4 + 4]);
        a[mi][3] = fu(As[m + g + 8][kk + t4 + 4]);
      }
      uint32_t b[8][2];
#pragma unroll
      for (int ni = 0; ni < 8; ni++) {
        int n = n0w + ni * 8 + g;
        b[ni][0] = fu(Bs[kk + t4][n]);
        b[ni][1] = fu(Bs[kk + t4 + 4][n]);
      }
#pragma unroll
      for (int mi = 0; mi < 2; mi++)
#pragma unroll
        for (int ni = 0; ni < 8; ni++) MMA_TF32(acc[mi][ni], a[mi], b[ni]);
    }
    __syncthreads();
  }

#pragma unroll
  for (int mi = 0; mi < 2; mi++) {
    int r0 = row0 + m0w + mi * 16 + g;
#pragma unroll
    for (int ni = 0; ni < 8; ni++) {
      int col = col0 + n0w + ni * 8 + 2 * t4;
      *(float2*)(C + (size_t)r0 * N + col) =
          make_float2(acc[mi][ni][0], acc[mi][ni][1]);
      *(float2*)(C + (size_t)(r0 + 8) * N + col) =
          make_float2(acc[mi][ni][2], acc[mi][ni][3]);
    }
  }
}

// ---------------------------------------------------------------------------
// RoPE, in place on q and k. One block (64 threads) per (b,s,head) row.
// ---------------------------------------------------------------------------
__global__ void rope_kernel(float* __restrict__ q, float* __restrict__ k) {
  const int row = blockIdx.x;
  const int nh = H + HKV;
  const int bs = row / nh;
  const int hh = row - bs * nh;
  const int s = bs & (S - 1);
  float* p = (hh < H) ? (q + (size_t)bs * QN + hh * HD)
                      : (k + (size_t)bs * KN + (hh - H) * HD);
  const int j = threadIdx.x;  // 0..63
  const float x1 = p[2 * j];
  const float x2 = p[2 * j + 1];
  const float theta = exp2f(-(float)j * 0.20762050593045983f);
  const float ang = (float)s * theta;
  float sn, cs;
  sincosf(ang, &sn, &cs);
  __syncthreads();
  p[j] = x1 * cs - x2 * sn;
  p[j + 64] = x1 * sn + x2 * cs;
}

// ---------------------------------------------------------------------------
// Flash attention (causal, GQA) with tf32 MMA for QK^T and PV.
// Block: 128 q-rows x 64 k-cols per iteration, 256 threads (8 warps).
// ---------------------------------------------------------------------------
#define QS_STRIDE 132
#define PS_STRIDE 68
#define ATTN_SMEM_FLOATS (128*QS_STRIDE + 64*QS_STRIDE + 64*QS_STRIDE + 128*PS_STRIDE + 3*128)
#define ATTN_SMEM_BYTES  (ATTN_SMEM_FLOATS * 4)

__global__ void __launch_bounds__(256, 1)
attn_kernel(const float* __restrict__ Q, const float* __restrict__ K,
            const float* __restrict__ V, float* __restrict__ O) {
  extern __shared__ float sm[];
  float* Qs = sm;                          // [128][132]
  float* Ks = Qs + 128 * QS_STRIDE;        // [64][132]
  float* Vs = Ks + 64 * QS_STRIDE;         // [64][132]
  float* Ps = Vs + 64 * QS_STRIDE;         // [128][68]
  float* mrow = Ps + 128 * PS_STRIDE;      // [128]
  float* lrow = mrow + 128;                // [128]
  float* asc  = lrow + 128;                // [128]

  const int tid = threadIdx.x;
  const int lane = tid & 31;
  const int w = tid >> 5;
  const int g = lane >> 2;
  const int t4 = lane & 3;
  const int warp_m = w & 3, warp_n = w >> 2;
  const int m0w = warp_m * 32;

  const int qi = (int)gridDim.x - 1 - (int)blockIdx.x;  // heavy tiles first
  const int bh = blockIdx.y;
  const int b = bh >> 4;
  const int h = bh & 15;
  const int hk = h >> 2;
  const int q0 = qi * 128;

  const float* qb = Q + (size_t)b * S * QN + h * HD;
  const float* kb = K + (size_t)b * S * KN + hk * HD;
  const float* vb = V + (size_t)b * S * KN + hk * HD;

  // Load Q tile (128x128), tf32-rounded
#pragma unroll
  for (int i = 0; i < 16; i++) {
    int idx = tid + i * 256;
    int r = idx >> 5, d4 = (idx & 31) << 2;
    float4 val = *(const float4*)(qb + (size_t)(q0 + r) * QN + d4);
    *(float4*)(Qs + r * QS_STRIDE + d4) =
        make_float4(ftf(val.x), ftf(val.y), ftf(val.z), ftf(val.w));
  }
  if (tid < 128) { mrow[tid] = -INFINITY; lrow[tid] = 0.f; }

  float oacc[2][8][4];
#pragma unroll
  for (int mi = 0; mi < 2; mi++)
#pragma unroll
    for (int ni = 0; ni < 8; ni++)
#pragma unroll
      for (int e = 0; e < 4; e++) oacc[mi][ni][e] = 0.f;

  const float qk_scale = 0.08838834764831845f;  // 1/sqrt(128)

  for (int k0 = 0; k0 <= q0 + 64; k0 += 64) {
    __syncthreads();
    // Load K,V tiles (64x128 each), tf32-rounded
#pragma unroll
    for (int i = 0; i < 8; i++) {
      int idx = tid + i * 256;
      int n = idx >> 5, d4 = (idx & 31) << 2;
      float4 kv = *(const float4*)(kb + (size_t)(k0 + n) * KN + d4);
      *(float4*)(Ks + n * QS_STRIDE + d4) =
          make_float4(ftf(kv.x), ftf(kv.y), ftf(kv.z), ftf(kv.w));
      float4 vv = *(const float4*)(vb + (size_t)(k0 + n) * KN + d4);
      *(float4*)(Vs + n * QS_STRIDE + d4) =
          make_float4(ftf(vv.x), ftf(vv.y), ftf(vv.z), ftf(vv.w));
    }
    __syncthreads();

    // ---- scores: warp tile 32x32 (2 mi x 4 ni mma tiles) ----
    float sacc[2][4][4];
#pragma unroll
    for (int mi = 0; mi < 2; mi++)
#pragma unroll
      for (int ni = 0; ni < 4; ni++)
#pragma unroll
        for (int e = 0; e < 4; e++) sacc[mi][ni][e] = 0.f;

    const int n0s = warp_n * 32;
#pragma unroll
    for (int ks = 0; ks < 16; ks++) {
      const int kk = ks * 8;
      uint32_t a[2][4];
#pragma unroll
      for (int mi = 0; mi < 2; mi++) {
        int m = m0w + mi * 16;
        a[mi][0] = fu(Qs[(m + g) * QS_STRIDE + kk + t4]);
        a[mi][1] = fu(Qs[(m + g + 8) * QS_STRIDE + kk + t4]);
        a[mi][2] = fu(Qs[(m + g) * QS_STRIDE + kk + t4 + 4]);
        a[mi][3] = fu(Qs[(m + g + 8) * QS_STRIDE + kk + t4 + 4]);
      }
      uint32_t bfr[4][2];
#pragma unroll
      for (int ni = 0; ni < 4; ni++) {
        int n = n0s + ni * 8 + g;
        bfr[ni][0] = fu(Ks[n * QS_STRIDE + kk + t4]);
        bfr[ni][1] = fu(Ks[n * QS_STRIDE + kk + t4 + 4]);
      }
#pragma unroll
      for (int mi = 0; mi < 2; mi++)
#pragma unroll
        for (int ni = 0; ni < 4; ni++) MMA_TF32(sacc[mi][ni], a[mi], bfr[ni]);
    }

    // ---- write scaled+masked scores to Ps ----
    const bool diag = (k0 + 63 > q0);
#pragma unroll
    for (int mi = 0; mi < 2; mi++) {
      int r0 = m0w + mi * 16 + g;
#pragma unroll
      for (int ni = 0; ni < 4; ni++) {
        int col = n0s + ni * 8 + 2 * t4;
        float v0 = sacc[mi][ni][0] * qk_scale;
        float v1 = sacc[mi][ni][1] * qk_scale;
        float v2 = sacc[mi][ni][2] * qk_scale;
        float v3 = sacc[mi][ni][3] * qk_scale;
        if (diag) {
          int kc = k0 + col;
          int qr0 = q0 + r0, qr1 = qr0 + 8;
          if (kc > qr0) v0 = -1e30f;
          if (kc + 1 > qr0) v1 = -1e30f;
          if (kc > qr1) v2 = -1e30f;
          if (kc + 1 > qr1) v3 = -1e30f;
        }
        *(float2*)(Ps + r0 * PS_STRIDE + col) = make_float2(v0, v1);
        *(float2*)(Ps + (r0 + 8) * PS_STRIDE + col) = make_float2(v2, v3);
      }
    }
    __syncthreads();

    // ---- online softmax: 2 threads per row ----
    {
      int r = tid >> 1;
      float* prow = Ps + r * PS_STRIDE + (tid & 1) * 32;
      float mloc = -INFINITY;
#pragma unroll
      for (int j = 0; j < 32; j++) mloc = fmaxf(mloc, prow[j]);
      mloc = fmaxf(mloc, __shfl_xor_sync(0xffffffffu, mloc, 1));
      float mold = mrow[r];
      float mnew = fmaxf(mold, mloc);
      float lloc = 0.f;
#pragma unroll
      for (int j = 0; j < 32; j++) {
        float e = ftf(__expf(prow[j] - mnew));
        prow[j] = e;
        lloc += e;
      }
      lloc += __shfl_xor_sync(0xffffffffu, lloc, 1);
      if ((tid & 1) == 0) {
        float al = __expf(mold - mnew);
        asc[r] = al;
        mrow[r] = mnew;
        lrow[r] = lrow[r] * al + lloc;
      }
    }
    __syncthreads();

    // ---- PV: warp tile 32x64 (2 mi x 8 ni), k = 64 ----
    {
      const int n0v = warp_n * 64;
#pragma unroll
      for (int mi = 0; mi < 2; mi++) {
        float al0 = asc[m0w + mi * 16 + g];
        float al1 = asc[m0w + mi * 16 + g + 8];
#pragma unroll
        for (int ni = 0; ni < 8; ni++) {
          oacc[mi][ni][0] *= al0;
          oacc[mi][ni][1] *= al0;
          oacc[mi][ni][2] *= al1;
          oacc[mi][ni][3] *= al1;
        }
      }
#pragma unroll
      for (int ks = 0; ks < 8; ks++) {
        const int kk = ks * 8;
        uint32_t a[2][4];
#pragma unroll
        for (int mi = 0; mi < 2; mi++) {
          int m = m0w + mi * 16;
          a[mi][0] = fu(Ps[(m + g) * PS_STRIDE + kk + t4]);
          a[mi][1] = fu(Ps[(m + g + 8) * PS_STRIDE + kk + t4]);
          a[mi][2] = fu(Ps[(m + g) * PS_STRIDE + kk + t4 + 4]);
          a[mi][3] = fu(Ps[(m + g + 8) * PS_STRIDE + kk + t4 + 4]);
        }
        uint32_t bfr[8][2];
#pragma unroll
        for (int ni = 0; ni < 8; ni++) {
          int n = n0v + ni * 8 + g;
          bfr[ni][0] = fu(Vs[(kk + t4) * QS_STRIDE + n]);
          bfr[ni][1] = fu(Vs[(kk + t4 + 4) * QS_STRIDE + n]);
        }
#pragma unroll
        for (int mi = 0; mi < 2; mi++)
#pragma unroll
          for (int ni = 0; ni < 8; ni++) MMA_TF32(oacc[mi][ni], a[mi], bfr[ni]);
      }
    }
  }

  // ---- finalize: O = oacc / l ----
  {
    const int n0v = warp_n * 64;
#pragma unroll
    for (int mi = 0; mi < 2; mi++) {
      int r0 = m0w + mi * 16 + g;
      float inv0 = 1.f / lrow[r0];
      float inv1 = 1.f / lrow[r0 + 8];
#pragma unroll
      for (int ni = 0; ni < 8; ni++) {
        int col = h * HD + n0v + ni * 8 + 2 * t4;
        float* o0 = O + (size_t)(b * S + q0 + r0) * QN + col;
        float* o1 = O + (size_t)(b * S + q0 + r0 + 8) * QN + col;
        *(float2*)o0 = make_float2(oacc[mi][ni][0] * inv0, oacc[mi][ni][1] * inv0);
        *(float2*)o1 = make_float2(oacc[mi][ni][2] * inv1, oacc[mi][ni][3] * inv1);
      }
    }
  }
}

// ---------------------------------------------------------------------------
extern "C" void kernel_launch(void* const* d_in, const int* in_sizes, int n_in,
                              void* d_out, int out_size) {
  const float* x  = (const float*)d_in[0];
  const float* Wq = (const float*)d_in[1];
  const float* Wk = (const float*)d_in[2];
  const float* Wv = (const float*)d_in[3];
  const float* Wo = (const float*)d_in[4];
  float* out = (float*)d_out;

  float *q, *k, *v, *attn;
  cudaGetSymbolAddress((void**)&q, g_q);
  cudaGetSymbolAddress((void**)&k, g_k);
  cudaGetSymbolAddress((void**)&v, g_v);
  cudaGetSymbolAddress((void**)&attn, g_attn);

  dim3 blk(256);
  mma_gemm<<<dim3(QN / 128, M_ROWS / 128), blk>>>(x, Wq, q, M_ROWS, QN, D);
  mma_gemm<<<dim3(KN / 128, M_ROWS / 128), blk>>>(x, Wk, k, M_ROWS, KN, D);
  mma_gemm<<<dim3(KN / 128, M_ROWS / 128), blk>>>(x, Wv, v, M_ROWS, KN, D);
  rope_kernel<<<B * S * (H + HKV), 64>>>(q, k);
  cudaFuncSetAttribute(attn_kernel, cudaFuncAttributeMaxDynamicSharedMemorySize,
                       ATTN_SMEM_BYTES);
  attn_kernel<<<dim3(S / 128, B * H), blk, ATTN_SMEM_BYTES>>>(q, k, v, attn);
  mma_gemm<<<dim3(D / 128, M_ROWS / 128), blk>>>(attn, Wo, out, M_ROWS, D, QN);
}

// round 4
// speedup vs baseline: 3.3068x; 1.2903x over previous
#include <cuda_runtime.h>
#include <math.h>
#include <stdint.h>

#define B 2
#define S 2048
#define D 2048
#define H 16
#define HKV 4
#define HD 128
#define M_ROWS (B*S)     // 4096
#define QN (H*HD)        // 2048
#define KN (HKV*HD)      // 512

// Scratch (allocation-free: device globals)
__device__ float g_q[(size_t)M_ROWS * QN];
__device__ float g_k[(size_t)M_ROWS * KN];
__device__ float g_v[(size_t)M_ROWS * KN];
__device__ float g_attn[(size_t)M_ROWS * QN];
// tf32-pre-rounded copies of GEMM inputs (cp.async moves raw bytes)
__device__ float g_xr[(size_t)M_ROWS * D];
__device__ float g_wqr[(size_t)D * QN];
__device__ float g_wkr[(size_t)D * KN];
__device__ float g_wvr[(size_t)D * KN];
__device__ float g_wor[(size_t)QN * D];

__device__ __forceinline__ float ftf(float x) {
  float r;
  asm("cvt.rna.tf32.f32 %0, %1;" : "=f"(r) : "f"(x));
  return r;
}
__device__ __forceinline__ uint32_t fu(float x) { return __float_as_uint(x); }

#define MMA_TF32(c, a, b)                                                     \
  asm("mma.sync.aligned.m16n8k8.row.col.f32.tf32.tf32.f32 "                   \
      "{%0,%1,%2,%3},{%4,%5,%6,%7},{%8,%9},{%0,%1,%2,%3};"                    \
      : "+f"(c[0]), "+f"(c[1]), "+f"(c[2]), "+f"(c[3])                        \
      : "r"(a[0]), "r"(a[1]), "r"(a[2]), "r"(a[3]), "r"(b[0]), "r"(b[1]))

#define CP16(dst, src)                                                        \
  asm volatile("cp.async.cg.shared.global [%0], [%1], 16;" ::"r"(dst), "l"(src))
#define CP_COMMIT() asm volatile("cp.async.commit_group;")
#define CP_WAIT1()  asm volatile("cp.async.wait_group 1;")

// ---------------------------------------------------------------------------
// tf32 pre-rounding pass (float4 grid-stride-free: n % 1024 == 0 everywhere)
// ---------------------------------------------------------------------------
__global__ void round_tf32(const float* __restrict__ src,
                           float* __restrict__ dst, int n4) {
  int i = blockIdx.x * blockDim.x + threadIdx.x;
  if (i < n4) {
    float4 v = *(const float4*)(src + 4 * (size_t)i);
    *(float4*)(dst + 4 * (size_t)i) =
        make_float4(ftf(v.x), ftf(v.y), ftf(v.z), ftf(v.w));
  }
}

// ---------------------------------------------------------------------------
// Pipelined tf32 MMA GEMM body: C[M,N] = A[M,K] @ B[K,N], inputs pre-rounded.
// 128x128x32 tile, 2-stage cp.async, 256 threads = 8 warps (4M x 2N).
// ---------------------------------------------------------------------------
#define AS_STRIDE 36
#define BS_STRIDE 136
#define AS_SZ (128 * AS_STRIDE)
#define BS_SZ (32 * BS_STRIDE)
#define GEMM_SMEM_BYTES ((2 * AS_SZ + 2 * BS_SZ) * 4)

__device__ __forceinline__ void gemm_issue_slab(
    int tid, const float* __restrict__ A, const float* __restrict__ Bm,
    int K, int N, int row0, int col0, int k0, float* as, float* bs) {
#pragma unroll
  for (int l = 0; l < 4; l++) {
    int idx = tid + l * 256;
    int ar = idx >> 3, ac = (idx & 7) << 2;
    const float* asrc = A + (size_t)(row0 + ar) * K + k0 + ac;
    uint32_t adst = (uint32_t)__cvta_generic_to_shared(as + ar * AS_STRIDE + ac);
    CP16(adst, asrc);
    int br = idx >> 5, bc = (idx & 31) << 2;
    const float* bsrc = Bm + (size_t)(k0 + br) * N + col0 + bc;
    uint32_t bdst = (uint32_t)__cvta_generic_to_shared(bs + br * BS_STRIDE + bc);
    CP16(bdst, bsrc);
  }
}

__device__ __forceinline__ void gemm_body(
    const float* __restrict__ A, const float* __restrict__ Bm,
    float* __restrict__ C, int N, int K, int row0, int col0, float* smp) {
  float* As = smp;                 // 2 x [128][36]
  float* Bs = smp + 2 * AS_SZ;     // 2 x [32][136]

  const int tid = threadIdx.x;
  const int lane = tid & 31;
  const int w = tid >> 5;
  const int g = lane >> 2;
  const int t4 = lane & 3;
  const int warp_m = w & 3, warp_n = w >> 2;
  const int m0w = warp_m * 32, n0w = warp_n * 64;

  float acc[2][8][4];
#pragma unroll
  for (int mi = 0; mi < 2; mi++)
#pragma unroll
    for (int ni = 0; ni < 8; ni++)
#pragma unroll
      for (int e = 0; e < 4; e++) acc[mi][ni][e] = 0.f;

  gemm_issue_slab(tid, A, Bm, K, N, row0, col0, 0, As, Bs);
  CP_COMMIT();
  gemm_issue_slab(tid, A, Bm, K, N, row0, col0, 32, As + AS_SZ, Bs + BS_SZ);
  CP_COMMIT();

  const int nslab = K >> 5;
  for (int it = 0; it < nslab; it++) {
    CP_WAIT1();
    __syncthreads();
    const float* as = As + (it & 1) * AS_SZ;
    const float* bs = Bs + (it & 1) * BS_SZ;
#pragma unroll
    for (int ks = 0; ks < 4; ks++) {
      const int kk = ks * 8;
      uint32_t a[2][4];
#pragma unroll
      for (int mi = 0; mi < 2; mi++) {
        int m = m0w + mi * 16;
        a[mi][0] = fu(as[(m + g) * AS_STRIDE + kk + t4]);
        a[mi][1] = fu(as[(m + g + 8) * AS_STRIDE + kk + t4]);
        a[mi][2] = fu(as[(m + g) * AS_STRIDE + kk + t4 + 4]);
        a[mi][3] = fu(as[(m + g + 8) * AS_STRIDE + kk + t4 + 4]);
      }
      uint32_t b[8][2];
#pragma unroll
      for (int ni = 0; ni < 8; ni++) {
        int n = n0w + ni * 8 + g;
        b[ni][0] = fu(bs[(kk + t4) * BS_STRIDE + n]);
        b[ni][1] = fu(bs[(kk + t4 + 4) * BS_STRIDE + n]);
      }
#pragma unroll
      for (int mi = 0; mi < 2; mi++)
#pragma unroll
        for (int ni = 0; ni < 8; ni++) MMA_TF32(acc[mi][ni], a[mi], b[ni]);
    }
    __syncthreads();
    int kn = (it + 2) << 5;
    if (kn < K)
      gemm_issue_slab(tid, A, Bm, K, N, row0, col0, kn,
                      As + (it & 1) * AS_SZ, Bs + (it & 1) * BS_SZ);
    CP_COMMIT();
  }

#pragma unroll
  for (int mi = 0; mi < 2; mi++) {
    int r0 = row0 + m0w + mi * 16 + g;
#pragma unroll
    for (int ni = 0; ni < 8; ni++) {
      int col = col0 + n0w + ni * 8 + 2 * t4;
      *(float2*)(C + (size_t)r0 * N + col) =
          make_float2(acc[mi][ni][0], acc[mi][ni][1]);
      *(float2*)(C + (size_t)(r0 + 8) * N + col) =
          make_float2(acc[mi][ni][2], acc[mi][ni][3]);
    }
  }
}

// Merged QKV projection: grid.x = 16 (Q) + 4 (K) + 4 (V) = 24, grid.y = 32
__global__ void __launch_bounds__(256)
qkv_gemm(const float* __restrict__ xr, const float* __restrict__ wq,
         const float* __restrict__ wk, const float* __restrict__ wv,
         float* __restrict__ q, float* __restrict__ k, float* __restrict__ v) {
  extern __shared__ float smp[];
  const int bx = blockIdx.x;
  const int row0 = blockIdx.y * 128;
  const float* Bm;
  float* C;
  int N, col0;
  if (bx < 16)      { Bm = wq; C = q; N = QN; col0 = bx * 128; }
  else if (bx < 20) { Bm = wk; C = k; N = KN; col0 = (bx - 16) * 128; }
  else              { Bm = wv; C = v; N = KN; col0 = (bx - 20) * 128; }
  gemm_body(xr, Bm, C, N, D, row0, col0, smp);
}

__global__ void __launch_bounds__(256)
o_gemm(const float* __restrict__ attn, const float* __restrict__ wo,
       float* __restrict__ out) {
  extern __shared__ float smp[];
  gemm_body(attn, wo, out, D, QN, blockIdx.y * 128, blockIdx.x * 128, smp);
}

// ---------------------------------------------------------------------------
// RoPE, in place on q and k; writes tf32-rounded (attention re-rounds, no-op).
// ---------------------------------------------------------------------------
__global__ void rope_kernel(float* __restrict__ q, float* __restrict__ k) {
  const int row = blockIdx.x;
  const int nh = H + HKV;
  const int bs = row / nh;
  const int hh = row - bs * nh;
  const int s = bs & (S - 1);
  float* p = (hh < H) ? (q + (size_t)bs * QN + hh * HD)
                      : (k + (size_t)bs * KN + (hh - H) * HD);
  const int j = threadIdx.x;  // 0..63
  const float x1 = p[2 * j];
  const float x2 = p[2 * j + 1];
  const float theta = exp2f(-(float)j * 0.20762050593045983f);
  const float ang = (float)s * theta;
  float sn, cs;
  sincosf(ang, &sn, &cs);
  __syncthreads();
  p[j] = ftf(x1 * cs - x2 * sn);
  p[j + 64] = ftf(x1 * sn + x2 * cs);
}

// ---------------------------------------------------------------------------
// Flash attention (causal, GQA) with tf32 MMA for QK^T and PV.
// Output written tf32-rounded (it is the O-projection's cp.async input).
// ---------------------------------------------------------------------------
#define QS_STRIDE 132
#define VS_STRIDE 136
#define PS_STRIDE 68
#define ATTN_SMEM_FLOATS (128*QS_STRIDE + 64*QS_STRIDE + 64*VS_STRIDE + 128*PS_STRIDE + 3*128)
#define ATTN_SMEM_BYTES  (ATTN_SMEM_FLOATS * 4)

__global__ void __launch_bounds__(256, 1)
attn_kernel(const float* __restrict__ Q, const float* __restrict__ K,
            const float* __restrict__ V, float* __restrict__ O) {
  extern __shared__ float sm[];
  float* Qs = sm;                          // [128][132]
  float* Ks = Qs + 128 * QS_STRIDE;        // [64][132]
  float* Vs = Ks + 64 * QS_STRIDE;         // [64][136]
  float* Ps = Vs + 64 * VS_STRIDE;         // [128][68]
  float* mrow = Ps + 128 * PS_STRIDE;      // [128]
  float* lrow = mrow + 128;                // [128]
  float* asc  = lrow + 128;                // [128]

  const int tid = threadIdx.x;
  const int lane = tid & 31;
  const int w = tid >> 5;
  const int g = lane >> 2;
  const int t4 = lane & 3;
  const int warp_m = w & 3, warp_n = w >> 2;
  const int m0w = warp_m * 32;

  const int qi = (int)gridDim.x - 1 - (int)blockIdx.x;  // heavy tiles first
  const int bh = blockIdx.y;
  const int b = bh >> 4;
  const int h = bh & 15;
  const int hk = h >> 2;
  const int q0 = qi * 128;

  const float* qb = Q + (size_t)b * S * QN + h * HD;
  const float* kb = K + (size_t)b * S * KN + hk * HD;
  const float* vb = V + (size_t)b * S * KN + hk * HD;

  // Load Q tile (128x128), tf32-rounded
#pragma unroll
  for (int i = 0; i < 16; i++) {
    int idx = tid + i * 256;
    int r = idx >> 5, d4 = (idx & 31) << 2;
    float4 val = *(const float4*)(qb + (size_t)(q0 + r) * QN + d4);
    *(float4*)(Qs + r * QS_STRIDE + d4) =
        make_float4(ftf(val.x), ftf(val.y), ftf(val.z), ftf(val.w));
  }
  if (tid < 128) { mrow[tid] = -INFINITY; lrow[tid] = 0.f; }

  float oacc[2][8][4];
#pragma unroll
  for (int mi = 0; mi < 2; mi++)
#pragma unroll
    for (int ni = 0; ni < 8; ni++)
#pragma unroll
      for (int e = 0; e < 4; e++) oacc[mi][ni][e] = 0.f;

  const float qk_scale = 0.08838834764831845f;  // 1/sqrt(128)

  for (int k0 = 0; k0 <= q0 + 64; k0 += 64) {
    __syncthreads();
#pragma unroll
    for (int i = 0; i < 8; i++) {
      int idx = tid + i * 256;
      int n = idx >> 5, d4 = (idx & 31) << 2;
      float4 kv = *(const float4*)(kb + (size_t)(k0 + n) * KN + d4);
      *(float4*)(Ks + n * QS_STRIDE + d4) =
          make_float4(ftf(kv.x), ftf(kv.y), ftf(kv.z), ftf(kv.w));
      float4 vv = *(const float4*)(vb + (size_t)(k0 + n) * KN + d4);
      *(float4*)(Vs + n * VS_STRIDE + d4) =
          make_float4(ftf(vv.x), ftf(vv.y), ftf(vv.z), ftf(vv.w));
    }
    __syncthreads();

    // ---- scores: warp tile 32x32 (2 mi x 4 ni mma tiles) ----
    float sacc[2][4][4];
#pragma unroll
    for (int mi = 0; mi < 2; mi++)
#pragma unroll
      for (int ni = 0; ni < 4; ni++)
#pragma unroll
        for (int e = 0; e < 4; e++) sacc[mi][ni][e] = 0.f;

    const int n0s = warp_n * 32;
#pragma unroll
    for (int ks = 0; ks < 16; ks++) {
      const int kk = ks * 8;
      uint32_t a[2][4];
#pragma unroll
      for (int mi = 0; mi < 2; mi++) {
        int m = m0w + mi * 16;
        a[mi][0] = fu(Qs[(m + g) * QS_STRIDE + kk + t4]);
        a[mi][1] = fu(Qs[(m + g + 8) * QS_STRIDE + kk + t4]);
        a[mi][2] = fu(Qs[(m + g) * QS_STRIDE + kk + t4 + 4]);
        a[mi][3] = fu(Qs[(m + g + 8) * QS_STRIDE + kk + t4 + 4]);
      }
      uint32_t bfr[4][2];
#pragma unroll
      for (int ni = 0; ni < 4; ni++) {
        int n = n0s + ni * 8 + g;
        bfr[ni][0] = fu(Ks[n * QS_STRIDE + kk + t4]);
        bfr[ni][1] = fu(Ks[n * QS_STRIDE + kk + t4 + 4]);
      }
#pragma unroll
      for (int mi = 0; mi < 2; mi++)
#pragma unroll
        for (int ni = 0; ni < 4; ni++) MMA_TF32(sacc[mi][ni], a[mi], bfr[ni]);
    }

    // ---- write scaled+masked scores to Ps ----
    const bool diag = (k0 + 63 > q0);
#pragma unroll
    for (int mi = 0; mi < 2; mi++) {
      int r0 = m0w + mi * 16 + g;
#pragma unroll
      for (int ni = 0; ni < 4; ni++) {
        int col = n0s + ni * 8 + 2 * t4;
        float v0 = sacc[mi][ni][0] * qk_scale;
        float v1 = sacc[mi][ni][1] * qk_scale;
        float v2 = sacc[mi][ni][2] * qk_scale;
        float v3 = sacc[mi][ni][3] * qk_scale;
        if (diag) {
          int kc = k0 + col;
          int qr0 = q0 + r0, qr1 = qr0 + 8;
          if (kc > qr0) v0 = -1e30f;
          if (kc + 1 > qr0) v1 = -1e30f;
          if (kc > qr1) v2 = -1e30f;
          if (kc + 1 > qr1) v3 = -1e30f;
        }
        *(float2*)(Ps + r0 * PS_STRIDE + col) = make_float2(v0, v1);
        *(float2*)(Ps + (r0 + 8) * PS_STRIDE + col) = make_float2(v2, v3);
      }
    }
    __syncthreads();

    // ---- online softmax: 2 threads per row ----
    {
      int r = tid >> 1;
      float* prow = Ps + r * PS_STRIDE + (tid & 1) * 32;
      float mloc = -INFINITY;
#pragma unroll
      for (int j = 0; j < 32; j++) mloc = fmaxf(mloc, prow[j]);
      mloc = fmaxf(mloc, __shfl_xor_sync(0xffffffffu, mloc, 1));
      float mold = mrow[r];
      float mnew = fmaxf(mold, mloc);
      float lloc = 0.f;
#pragma unroll
      for (int j = 0; j < 32; j++) {
        float e = ftf(__expf(prow[j] - mnew));
        prow[j] = e;
        lloc += e;
      }
      lloc += __shfl_xor_sync(0xffffffffu, lloc, 1);
      if ((tid & 1) == 0) {
        float al = __expf(mold - mnew);
        asc[r] = al;
        mrow[r] = mnew;
        lrow[r] = lrow[r] * al + lloc;
      }
    }
    __syncthreads();

    // ---- PV: warp tile 32x64 (2 mi x 8 ni), k = 64 ----
    {
      const int n0v = warp_n * 64;
#pragma unroll
      for (int mi = 0; mi < 2; mi++) {
        float al0 = asc[m0w + mi * 16 + g];
        float al1 = asc[m0w + mi * 16 + g + 8];
#pragma unroll
        for (int ni = 0; ni < 8; ni++) {
          oacc[mi][ni][0] *= al0;
          oacc[mi][ni][1] *= al0;
          oacc[mi][ni][2] *= al1;
          oacc[mi][ni][3] *= al1;
        }
      }
#pragma unroll
      for (int ks = 0; ks < 8; ks++) {
        const int kk = ks * 8;
        uint32_t a[2][4];
#pragma unroll
        for (int mi = 0; mi < 2; mi++) {
          int m = m0w + mi * 16;
          a[mi][0] = fu(Ps[(m + g) * PS_STRIDE + kk + t4]);
          a[mi][1] = fu(Ps[(m + g + 8) * PS_STRIDE + kk + t4]);
          a[mi][2] = fu(Ps[(m + g) * PS_STRIDE + kk + t4 + 4]);
          a[mi][3] = fu(Ps[(m + g + 8) * PS_STRIDE + kk + t4 + 4]);
        }
        uint32_t bfr[8][2];
#pragma unroll
        for (int ni = 0; ni < 8; ni++) {
          int n = n0v + ni * 8 + g;
          bfr[ni][0] = fu(Vs[(kk + t4) * VS_STRIDE + n]);
          bfr[ni][1] = fu(Vs[(kk + t4 + 4) * VS_STRIDE + n]);
        }
#pragma unroll
        for (int mi = 0; mi < 2; mi++)
#pragma unroll
          for (int ni = 0; ni < 8; ni++) MMA_TF32(oacc[mi][ni], a[mi], bfr[ni]);
      }
    }
  }

  // ---- finalize: O = ftf(oacc / l) ----
  {
    const int n0v = warp_n * 64;
#pragma unroll
    for (int mi = 0; mi < 2; mi++) {
      int r0 = m0w + mi * 16 + g;
      float inv0 = 1.f / lrow[r0];
      float inv1 = 1.f / lrow[r0 + 8];
#pragma unroll
      for (int ni = 0; ni < 8; ni++) {
        int col = h * HD + n0v + ni * 8 + 2 * t4;
        float* o0 = O + (size_t)(b * S + q0 + r0) * QN + col;
        float* o1 = O + (size_t)(b * S + q0 + r0 + 8) * QN + col;
        *(float2*)o0 = make_float2(ftf(oacc[mi][ni][0] * inv0),
                                   ftf(oacc[mi][ni][1] * inv0));
        *(float2*)o1 = make_float2(ftf(oacc[mi][ni][2] * inv1),
                                   ftf(oacc[mi][ni][3] * inv1));
      }
    }
  }
}

// ---------------------------------------------------------------------------
extern "C" void kernel_launch(void* const* d_in, const int* in_sizes, int n_in,
                              void* d_out, int out_size) {
  const float* x  = (const float*)d_in[0];
  const float* Wq = (const float*)d_in[1];
  const float* Wk = (const float*)d_in[2];
  const float* Wv = (const float*)d_in[3];
  const float* Wo = (const float*)d_in[4];
  float* out = (float*)d_out;

  float *q, *k, *v, *attn, *xr, *wqr, *wkr, *wvr, *wor;
  cudaGetSymbolAddress((void**)&q, g_q);
  cudaGetSymbolAddress((void**)&k, g_k);
  cudaGetSymbolAddress((void**)&v, g_v);
  cudaGetSymbolAddress((void**)&attn, g_attn);
  cudaGetSymbolAddress((void**)&xr, g_xr);
  cudaGetSymbolAddress((void**)&wqr, g_wqr);
  cudaGetSymbolAddress((void**)&wkr, g_wkr);
  cudaGetSymbolAddress((void**)&wvr, g_wvr);
  cudaGetSymbolAddress((void**)&wor, g_wor);

  cudaFuncSetAttribute(qkv_gemm, cudaFuncAttributeMaxDynamicSharedMemorySize,
                       GEMM_SMEM_BYTES);
  cudaFuncSetAttribute(o_gemm, cudaFuncAttributeMaxDynamicSharedMemorySize,
                       GEMM_SMEM_BYTES);
  cudaFuncSetAttribute(attn_kernel, cudaFuncAttributeMaxDynamicSharedMemorySize,
                       ATTN_SMEM_BYTES);

  // tf32 pre-rounding of all cp.async GEMM inputs
  round_tf32<<<(M_ROWS * D / 4 + 255) / 256, 256>>>(x, xr, M_ROWS * D / 4);
  round_tf32<<<(D * QN / 4 + 255) / 256, 256>>>(Wq, wqr, D * QN / 4);
  round_tf32<<<(D * KN / 4 + 255) / 256, 256>>>(Wk, wkr, D * KN / 4);
  round_tf32<<<(D * KN / 4 + 255) / 256, 256>>>(Wv, wvr, D * KN / 4);
  round_tf32<<<(QN * D / 4 + 255) / 256, 256>>>(Wo, wor, QN * D / 4);

  dim3 blk(256);
  qkv_gemm<<<dim3(24, 32), blk, GEMM_SMEM_BYTES>>>(xr, wqr, wkr, wvr, q, k, v);
  rope_kernel<<<B * S * (H + HKV), 64>>>(q, k);
  attn_kernel<<<dim3(S / 128, B * H), blk, ATTN_SMEM_BYTES>>>(q, k, v, attn);
  o_gemm<<<dim3(D / 128, M_ROWS / 128), blk, GEMM_SMEM_BYTES>>>(attn, wor, out);
}

// round 5
// speedup vs baseline: 3.5272x; 1.0667x over previous
#include <cuda_runtime.h>
#include <math.h>
#include <stdint.h>

#define B 2
#define S 2048
#define D 2048
#define H 16
#define HKV 4
#define HD 128
#define M_ROWS (B*S)     // 4096
#define QN (H*HD)        // 2048
#define KN (HKV*HD)      // 512

// Scratch (allocation-free: device globals)
__device__ float g_q[(size_t)M_ROWS * QN];
__device__ float g_k[(size_t)M_ROWS * KN];
__device__ float g_v[(size_t)M_ROWS * KN];
__device__ float g_attn[(size_t)M_ROWS * QN];
// tf32-pre-rounded copies of GEMM inputs (cp.async moves raw bytes)
__device__ float g_xr[(size_t)M_ROWS * D];
__device__ float g_wqr[(size_t)D * QN];
__device__ float g_wkr[(size_t)D * KN];
__device__ float g_wvr[(size_t)D * KN];
__device__ float g_wor[(size_t)QN * D];

__device__ __forceinline__ float ftf(float x) {
  float r;
  asm("cvt.rna.tf32.f32 %0, %1;" : "=f"(r) : "f"(x));
  return r;
}
__device__ __forceinline__ uint32_t fu(float x) { return __float_as_uint(x); }

#define MMA_TF32(c, a, b)                                                     \
  asm("mma.sync.aligned.m16n8k8.row.col.f32.tf32.tf32.f32 "                   \
      "{%0,%1,%2,%3},{%4,%5,%6,%7},{%8,%9},{%0,%1,%2,%3};"                    \
      : "+f"(c[0]), "+f"(c[1]), "+f"(c[2]), "+f"(c[3])                        \
      : "r"(a[0]), "r"(a[1]), "r"(a[2]), "r"(a[3]), "r"(b[0]), "r"(b[1]))

#define CP16(dst, src)                                                        \
  asm volatile("cp.async.cg.shared.global [%0], [%1], 16;" ::"r"(dst), "l"(src))
#define CP_COMMIT() asm volatile("cp.async.commit_group;")
#define CP_WAIT1()  asm volatile("cp.async.wait_group 1;")

// ---------------------------------------------------------------------------
// tf32 pre-rounding pass
// ---------------------------------------------------------------------------
__global__ void round_tf32(const float* __restrict__ src,
                           float* __restrict__ dst, int n4) {
  int i = blockIdx.x * blockDim.x + threadIdx.x;
  if (i < n4) {
    float4 v = *(const float4*)(src + 4 * (size_t)i);
    *(float4*)(dst + 4 * (size_t)i) =
        make_float4(ftf(v.x), ftf(v.y), ftf(v.z), ftf(v.w));
  }
}

// ---------------------------------------------------------------------------
// Pipelined tf32 MMA GEMM: C[M,N] = A[M,K] @ B[K,N], inputs pre-rounded.
// 256x128x32 block tile, 2-stage cp.async, 256 threads = 8 warps (4M x 2N),
// warp tile 64x64 (4 mi x 8 ni m16n8k8 tiles).
// ---------------------------------------------------------------------------
#define AS_STRIDE 36
#define BS_STRIDE 136
#define AS_SZ (256 * AS_STRIDE)
#define BS_SZ (32 * BS_STRIDE)
#define GEMM_SMEM_BYTES ((2 * AS_SZ + 2 * BS_SZ) * 4)

__device__ __forceinline__ void gemm_issue_slab(
    int tid, const float* __restrict__ A, const float* __restrict__ Bm,
    int K, int N, int row0, int col0, int k0, float* as, float* bs) {
#pragma unroll
  for (int l = 0; l < 8; l++) {
    int idx = tid + l * 256;
    int ar = idx >> 3, ac = (idx & 7) << 2;
    const float* asrc = A + (size_t)(row0 + ar) * K + k0 + ac;
    uint32_t adst = (uint32_t)__cvta_generic_to_shared(as + ar * AS_STRIDE + ac);
    CP16(adst, asrc);
  }
#pragma unroll
  for (int l = 0; l < 4; l++) {
    int idx = tid + l * 256;
    int br = idx >> 5, bc = (idx & 31) << 2;
    const float* bsrc = Bm + (size_t)(k0 + br) * N + col0 + bc;
    uint32_t bdst = (uint32_t)__cvta_generic_to_shared(bs + br * BS_STRIDE + bc);
    CP16(bdst, bsrc);
  }
}

__device__ __forceinline__ void gemm_body(
    const float* __restrict__ A, const float* __restrict__ Bm,
    float* __restrict__ C, int N, int K, int row0, int col0, float* smp,
    bool round_out) {
  float* As = smp;                 // 2 x [256][36]
  float* Bs = smp + 2 * AS_SZ;     // 2 x [32][136]

  const int tid = threadIdx.x;
  const int lane = tid & 31;
  const int w = tid >> 5;
  const int g = lane >> 2;
  const int t4 = lane & 3;
  const int warp_m = w & 3, warp_n = w >> 2;
  const int m0w = warp_m * 64, n0w = warp_n * 64;

  float acc[4][8][4];
#pragma unroll
  for (int mi = 0; mi < 4; mi++)
#pragma unroll
    for (int ni = 0; ni < 8; ni++)
#pragma unroll
      for (int e = 0; e < 4; e++) acc[mi][ni][e] = 0.f;

  gemm_issue_slab(tid, A, Bm, K, N, row0, col0, 0, As, Bs);
  CP_COMMIT();
  gemm_issue_slab(tid, A, Bm, K, N, row0, col0, 32, As + AS_SZ, Bs + BS_SZ);
  CP_COMMIT();

  const int nslab = K >> 5;
  for (int it = 0; it < nslab; it++) {
    CP_WAIT1();
    __syncthreads();
    const float* as = As + (it & 1) * AS_SZ;
    const float* bs = Bs + (it & 1) * BS_SZ;
#pragma unroll
    for (int ks = 0; ks < 4; ks++) {
      const int kk = ks * 8;
      uint32_t a[4][4];
#pragma unroll
      for (int mi = 0; mi < 4; mi++) {
        int m = m0w + mi * 16;
        a[mi][0] = fu(as[(m + g) * AS_STRIDE + kk + t4]);
        a[mi][1] = fu(as[(m + g + 8) * AS_STRIDE + kk + t4]);
        a[mi][2] = fu(as[(m + g) * AS_STRIDE + kk + t4 + 4]);
        a[mi][3] = fu(as[(m + g + 8) * AS_STRIDE + kk + t4 + 4]);
      }
      uint32_t b[8][2];
#pragma unroll
      for (int ni = 0; ni < 8; ni++) {
        int n = n0w + ni * 8 + g;
        b[ni][0] = fu(bs[(kk + t4) * BS_STRIDE + n]);
        b[ni][1] = fu(bs[(kk + t4 + 4) * BS_STRIDE + n]);
      }
#pragma unroll
      for (int mi = 0; mi < 4; mi++)
#pragma unroll
        for (int ni = 0; ni < 8; ni++) MMA_TF32(acc[mi][ni], a[mi], b[ni]);
    }
    __syncthreads();
    int kn = (it + 2) << 5;
    if (kn < K)
      gemm_issue_slab(tid, A, Bm, K, N, row0, col0, kn,
                      As + (it & 1) * AS_SZ, Bs + (it & 1) * BS_SZ);
    CP_COMMIT();
  }

#pragma unroll
  for (int mi = 0; mi < 4; mi++) {
    int r0 = row0 + m0w + mi * 16 + g;
#pragma unroll
    for (int ni = 0; ni < 8; ni++) {
      int col = col0 + n0w + ni * 8 + 2 * t4;
      float c0 = acc[mi][ni][0], c1 = acc[mi][ni][1];
      float c2 = acc[mi][ni][2], c3 = acc[mi][ni][3];
      if (round_out) { c0 = ftf(c0); c1 = ftf(c1); c2 = ftf(c2); c3 = ftf(c3); }
      *(float2*)(C + (size_t)r0 * N + col) = make_float2(c0, c1);
      *(float2*)(C + (size_t)(r0 + 8) * N + col) = make_float2(c2, c3);
    }
  }
}

// Merged QKV projection: grid.x = 16 (Q) + 4 (K) + 4 (V) = 24, grid.y = 16
__global__ void __launch_bounds__(256, 1)
qkv_gemm(const float* __restrict__ xr, const float* __restrict__ wq,
         const float* __restrict__ wk, const float* __restrict__ wv,
         float* __restrict__ q, float* __restrict__ k, float* __restrict__ v) {
  extern __shared__ float smp[];
  const int bx = blockIdx.x;
  const int row0 = blockIdx.y * 256;
  const float* Bm;
  float* C;
  int N, col0;
  bool rnd = false;
  if (bx < 16)      { Bm = wq; C = q; N = QN; col0 = bx * 128; }
  else if (bx < 20) { Bm = wk; C = k; N = KN; col0 = (bx - 16) * 128; }
  else              { Bm = wv; C = v; N = KN; col0 = (bx - 20) * 128; rnd = true; }
  // V written tf32-rounded (same values attn would produce at load)
  gemm_body(xr, Bm, C, N, D, row0, col0, smp, rnd);
}

__global__ void __launch_bounds__(256, 1)
o_gemm(const float* __restrict__ attn, const float* __restrict__ wo,
       float* __restrict__ out) {
  extern __shared__ float smp[];
  gemm_body(attn, wo, out, D, QN, blockIdx.y * 256, blockIdx.x * 128, smp, false);
}

// ---------------------------------------------------------------------------
// RoPE, in place on q and k; writes tf32-rounded. 256 threads = 4 rows/block.
// ---------------------------------------------------------------------------
__global__ void __launch_bounds__(256)
rope_kernel(float* __restrict__ q, float* __restrict__ k) {
  const int row = blockIdx.x * 4 + (threadIdx.x >> 6);
  const int nh = H + HKV;
  const int bs = row / nh;
  const int hh = row - bs * nh;
  const int s = bs & (S - 1);
  float* p = (hh < H) ? (q + (size_t)bs * QN + hh * HD)
                      : (k + (size_t)bs * KN + (hh - H) * HD);
  const int j = threadIdx.x & 63;
  const float x1 = p[2 * j];
  const float x2 = p[2 * j + 1];
  const float theta = exp2f(-(float)j * 0.20762050593045983f);
  const float ang = (float)s * theta;
  float sn, cs;
  sincosf(ang, &sn, &cs);
  __syncwarp();
  p[j] = ftf(x1 * cs - x2 * sn);
  p[j + 64] = ftf(x1 * sn + x2 * cs);
}

// ---------------------------------------------------------------------------
// Flash attention (causal, GQA) with tf32 MMA and cp.async phase pipelining.
// All gmem inputs are already tf32-rounded. Single-buffered K/V: K_{t+1}
// prefetch overlaps softmax+PV; V_{t+1} prefetch overlaps next scores.
// ---------------------------------------------------------------------------
#define QS_STRIDE 132
#define VS_STRIDE 136
#define PS_STRIDE 68
#define ATTN_SMEM_FLOATS (128*QS_STRIDE + 64*QS_STRIDE + 64*VS_STRIDE + 128*PS_STRIDE + 3*128)
#define ATTN_SMEM_BYTES  (ATTN_SMEM_FLOATS * 4)

__device__ __forceinline__ void attn_issue_tile(
    int tid, const float* __restrict__ src, float* dst, int stride) {
#pragma unroll
  for (int i = 0; i < 8; i++) {
    int idx = tid + i * 256;
    int n = idx >> 5, d4 = (idx & 31) << 2;
    uint32_t d = (uint32_t)__cvta_generic_to_shared(dst + n * stride + d4);
    CP16(d, src + (size_t)n * KN + d4);
  }
}

__global__ void __launch_bounds__(256, 1)
attn_kernel(const float* __restrict__ Q, const float* __restrict__ K,
            const float* __restrict__ V, float* __restrict__ O) {
  extern __shared__ float sm[];
  float* Qs = sm;                          // [128][132]
  float* Ks = Qs + 128 * QS_STRIDE;        // [64][132]
  float* Vs = Ks + 64 * QS_STRIDE;         // [64][136]
  float* Ps = Vs + 64 * VS_STRIDE;         // [128][68]
  float* mrow = Ps + 128 * PS_STRIDE;      // [128]
  float* lrow = mrow + 128;                // [128]
  float* asc  = lrow + 128;                // [128]

  const int tid = threadIdx.x;
  const int lane = tid & 31;
  const int w = tid >> 5;
  const int g = lane >> 2;
  const int t4 = lane & 3;
  const int warp_m = w & 3, warp_n = w >> 2;
  const int m0w = warp_m * 32;

  const int qi = (int)gridDim.x - 1 - (int)blockIdx.x;  // heavy tiles first
  const int bh = blockIdx.y;
  const int b = bh >> 4;
  const int h = bh & 15;
  const int hk = h >> 2;
  const int q0 = qi * 128;

  const float* qb = Q + (size_t)b * S * QN + h * HD;
  const float* kb = K + (size_t)b * S * KN + hk * HD;
  const float* vb = V + (size_t)b * S * KN + hk * HD;

  // Prologue: async Q tile (raw; already tf32-rounded by rope)
#pragma unroll
  for (int i = 0; i < 16; i++) {
    int idx = tid + i * 256;
    int r = idx >> 5, d4 = (idx & 31) << 2;
    uint32_t d = (uint32_t)__cvta_generic_to_shared(Qs + r * QS_STRIDE + d4);
    CP16(d, qb + (size_t)(q0 + r) * QN + d4);
  }
  CP_COMMIT();
  attn_issue_tile(tid, kb, Ks, QS_STRIDE);   // K_0
  CP_COMMIT();
  attn_issue_tile(tid, vb, Vs, VS_STRIDE);   // V_0
  CP_COMMIT();

  if (tid < 128) { mrow[tid] = -INFINITY; lrow[tid] = 0.f; }

  float oacc[2][8][4];
#pragma unroll
  for (int mi = 0; mi < 2; mi++)
#pragma unroll
    for (int ni = 0; ni < 8; ni++)
#pragma unroll
      for (int e = 0; e < 4; e++) oacc[mi][ni][e] = 0.f;

  const float qk_scale = 0.08838834764831845f;  // 1/sqrt(128)
  const int T = (q0 >> 6) + 2;

  for (int t = 0; t < T; t++) {
    const int k0 = t << 6;
    // K_t (and Q on t=0) ready; V_t may still be in flight.
    CP_WAIT1();
    __syncthreads();

    // ---- scores: warp tile 32x32 (2 mi x 4 ni mma tiles) ----
    float sacc[2][4][4];
#pragma unroll
    for (int mi = 0; mi < 2; mi++)
#pragma unroll
      for (int ni = 0; ni < 4; ni++)
#pragma unroll
        for (int e = 0; e < 4; e++) sacc[mi][ni][e] = 0.f;

    const int n0s = warp_n * 32;
#pragma unroll
    for (int ks = 0; ks < 16; ks++) {
      const int kk = ks * 8;
      uint32_t a[2][4];
#pragma unroll
      for (int mi = 0; mi < 2; mi++) {
        int m = m0w + mi * 16;
        a[mi][0] = fu(Qs[(m + g) * QS_STRIDE + kk + t4]);
        a[mi][1] = fu(Qs[(m + g + 8) * QS_STRIDE + kk + t4]);
        a[mi][2] = fu(Qs[(m + g) * QS_STRIDE + kk + t4 + 4]);
        a[mi][3] = fu(Qs[(m + g + 8) * QS_STRIDE + kk + t4 + 4]);
      }
      uint32_t bfr[4][2];
#pragma unroll
      for (int ni = 0; ni < 4; ni++) {
        int n = n0s + ni * 8 + g;
        bfr[ni][0] = fu(Ks[n * QS_STRIDE + kk + t4]);
        bfr[ni][1] = fu(Ks[n * QS_STRIDE + kk + t4 + 4]);
      }
#pragma unroll
      for (int mi = 0; mi < 2; mi++)
#pragma unroll
        for (int ni = 0; ni < 4; ni++) MMA_TF32(sacc[mi][ni], a[mi], bfr[ni]);
    }

    // ---- write scaled+masked scores to Ps ----
    const bool diag = (k0 + 63 > q0);
#pragma unroll
    for (int mi = 0; mi < 2; mi++) {
      int r0 = m0w + mi * 16 + g;
#pragma unroll
      for (int ni = 0; ni < 4; ni++) {
        int col = n0s + ni * 8 + 2 * t4;
        float v0 = sacc[mi][ni][0] * qk_scale;
        float v1 = sacc[mi][ni][1] * qk_scale;
        float v2 = sacc[mi][ni][2] * qk_scale;
        float v3 = sacc[mi][ni][3] * qk_scale;
        if (diag) {
          int kc = k0 + col;
          int qr0 = q0 + r0, qr1 = qr0 + 8;
          if (kc > qr0) v0 = -1e30f;
          if (kc + 1 > qr0) v1 = -1e30f;
          if (kc > qr1) v2 = -1e30f;
          if (kc + 1 > qr1) v3 = -1e30f;
        }
        *(float2*)(Ps + r0 * PS_STRIDE + col) = make_float2(v0, v1);
        *(float2*)(Ps + (r0 + 8) * PS_STRIDE + col) = make_float2(v2, v3);
      }
    }
    __syncthreads();   // scores done: Ks free, Ps visible

    // Prefetch K_{t+1} (overlaps softmax + PV). Empty commit keeps counts.
    if (t + 1 < T) attn_issue_tile(tid, kb + ((size_t)(k0 + 64)) * KN, Ks, QS_STRIDE);
    CP_COMMIT();

    // ---- online softmax: 2 threads per row ----
    {
      int r = tid >> 1;
      float* prow = Ps + r * PS_STRIDE + (tid & 1) * 32;
      float mloc = -INFINITY;
#pragma unroll
      for (int j = 0; j < 32; j++) mloc = fmaxf(mloc, prow[j]);
      mloc = fmaxf(mloc, __shfl_xor_sync(0xffffffffu, mloc, 1));
      float mold = mrow[r];
      float mnew = fmaxf(mold, mloc);
      float lloc = 0.f;
#pragma unroll
      for (int j = 0; j < 32; j++) {
        float e = ftf(__expf(prow[j] - mnew));
        prow[j] = e;
        lloc += e;
      }
      lloc += __shfl_xor_sync(0xffffffffu, lloc, 1);
      if ((tid & 1) == 0) {
        float al = __expf(mold - mnew);
        asc[r] = al;
        mrow[r] = mnew;
        lrow[r] = lrow[r] * al + lloc;
      }
    }

    // V_t ready (K_{t+1} may remain in flight)
    CP_WAIT1();
    __syncthreads();

    // ---- PV: warp tile 32x64 (2 mi x 8 ni), k = 64 ----
    {
      const int n0v = warp_n * 64;
#pragma unroll
      for (int mi = 0; mi < 2; mi++) {
        float al0 = asc[m0w + mi * 16 + g];
        float al1 = asc[m0w + mi * 16 + g + 8];
#pragma unroll
        for (int ni = 0; ni < 8; ni++) {
          oacc[mi][ni][0] *= al0;
          oacc[mi][ni][1] *= al0;
          oacc[mi][ni][2] *= al1;
          oacc[mi][ni][3] *= al1;
        }
      }
#pragma unroll
      for (int ks = 0; ks < 8; ks++) {
        const int kk = ks * 8;
        uint32_t a[2][4];
#pragma unroll
        for (int mi = 0; mi < 2; mi++) {
          int m = m0w + mi * 16;
          a[mi][0] = fu(Ps[(m + g) * PS_STRIDE + kk + t4]);
          a[mi][1] = fu(Ps[(m + g + 8) * PS_STRIDE + kk + t4]);
          a[mi][2] = fu(Ps[(m + g) * PS_STRIDE + kk + t4 + 4]);
          a[mi][3] = fu(Ps[(m + g + 8) * PS_STRIDE + kk + t4 + 4]);
        }
        uint32_t bfr[8][2];
#pragma unroll
        for (int ni = 0; ni < 8; ni++) {
          int n = n0v + ni * 8 + g;
          bfr[ni][0] = fu(Vs[(kk + t4) * VS_STRIDE + n]);
          bfr[ni][1] = fu(Vs[(kk + t4 + 4) * VS_STRIDE + n]);
        }
#pragma unroll
        for (int mi = 0; mi < 2; mi++)
#pragma unroll
          for (int ni = 0; ni < 8; ni++) MMA_TF32(oacc[mi][ni], a[mi], bfr[ni]);
      }
    }
    __syncthreads();   // PV done: Vs free

    // Prefetch V_{t+1} (overlaps next scores). Empty commit keeps counts.
    if (t + 1 < T) attn_issue_tile(tid, vb + ((size_t)(k0 + 64)) * KN, Vs, VS_STRIDE);
    CP_COMMIT();
  }

  // ---- finalize: O = ftf(oacc / l) ----
  {
    const int n0v = warp_n * 64;
#pragma unroll
    for (int mi = 0; mi < 2; mi++) {
      int r0 = m0w + mi * 16 + g;
      float inv0 = 1.f / lrow[r0];
      float inv1 = 1.f / lrow[r0 + 8];
#pragma unroll
      for (int ni = 0; ni < 8; ni++) {
        int col = h * HD + n0v + ni * 8 + 2 * t4;
        float* o0 = O + (size_t)(b * S + q0 + r0) * QN + col;
        float* o1 = O + (size_t)(b * S + q0 + r0 + 8) * QN + col;
        *(float2*)o0 = make_float2(ftf(oacc[mi][ni][0] * inv0),
                                   ftf(oacc[mi][ni][1] * inv0));
        *(float2*)o1 = make_float2(ftf(oacc[mi][ni][2] * inv1),
                                   ftf(oacc[mi][ni][3] * inv1));
      }
    }
  }
}

// ---------------------------------------------------------------------------
extern "C" void kernel_launch(void* const* d_in, const int* in_sizes, int n_in,
                              void* d_out, int out_size) {
  const float* x  = (const float*)d_in[0];
  const float* Wq = (const float*)d_in[1];
  const float* Wk = (const float*)d_in[2];
  const float* Wv = (const float*)d_in[3];
  const float* Wo = (const float*)d_in[4];
  float* out = (float*)d_out;

  float *q, *k, *v, *attn, *xr, *wqr, *wkr, *wvr, *wor;
  cudaGetSymbolAddress((void**)&q, g_q);
  cudaGetSymbolAddress((void**)&k, g_k);
  cudaGetSymbolAddress((void**)&v, g_v);
  cudaGetSymbolAddress((void**)&attn, g_attn);
  cudaGetSymbolAddress((void**)&xr, g_xr);
  cudaGetSymbolAddress((void**)&wqr, g_wqr);
  cudaGetSymbolAddress((void**)&wkr, g_wkr);
  cudaGetSymbolAddress((void**)&wvr, g_wvr);
  cudaGetSymbolAddress((void**)&wor, g_wor);

  cudaFuncSetAttribute(qkv_gemm, cudaFuncAttributeMaxDynamicSharedMemorySize,
                       GEMM_SMEM_BYTES);
  cudaFuncSetAttribute(o_gemm, cudaFuncAttributeMaxDynamicSharedMemorySize,
                       GEMM_SMEM_BYTES);
  cudaFuncSetAttribute(attn_kernel, cudaFuncAttributeMaxDynamicSharedMemorySize,
                       ATTN_SMEM_BYTES);

  // tf32 pre-rounding of all cp.async GEMM inputs
  round_tf32<<<(M_ROWS * D / 4 + 255) / 256, 256>>>(x, xr, M_ROWS * D / 4);
  round_tf32<<<(D * QN / 4 + 255) / 256, 256>>>(Wq, wqr, D * QN / 4);
  round_tf32<<<(D * KN / 4 + 255) / 256, 256>>>(Wk, wkr, D * KN / 4);
  round_tf32<<<(D * KN / 4 + 255) / 256, 256>>>(Wv, wvr, D * KN / 4);
  round_tf32<<<(QN * D / 4 + 255) / 256, 256>>>(Wo, wor, QN * D / 4);

  dim3 blk(256);
  qkv_gemm<<<dim3(24, M_ROWS / 256), blk, GEMM_SMEM_BYTES>>>(xr, wqr, wkr, wvr,
                                                             q, k, v);
  rope_kernel<<<B * S * (H + HKV) / 4, blk>>>(q, k);
  attn_kernel<<<dim3(S / 128, B * H), blk, ATTN_SMEM_BYTES>>>(q, k, v, attn);
  o_gemm<<<dim3(D / 128, M_ROWS / 256), blk, GEMM_SMEM_BYTES>>>(attn, wor, out);
}

// round 6
// speedup vs baseline: 4.8194x; 1.3663x over previous
#include <cuda_runtime.h>
#include <cuda_fp16.h>
#include <math.h>
#include <stdint.h>

#define B 2
#define S 2048
#define D 2048
#define H 16
#define HKV 4
#define HD 128
#define M_ROWS (B*S)     // 4096
#define QN (H*HD)        // 2048
#define KN (HKV*HD)      // 512

// Scratch (allocation-free: device globals), fp16 operands everywhere
__device__ __half g_xh[(size_t)M_ROWS * D];
__device__ __half g_wqT[(size_t)QN * D];    // [N][K]
__device__ __half g_wkT[(size_t)KN * D];
__device__ __half g_wvT[(size_t)KN * D];
__device__ __half g_woT[(size_t)D * QN];
__device__ __half g_qh[(size_t)M_ROWS * QN];
__device__ __half g_kh[(size_t)M_ROWS * KN];
__device__ __half g_vT[(size_t)B * HKV * HD * S];  // [b][hk][d][s]
__device__ __half g_attnh[(size_t)M_ROWS * QN];

#define MMA_F16(c, a, b)                                                      \
  asm("mma.sync.aligned.m16n8k16.row.col.f32.f16.f16.f32 "                    \
      "{%0,%1,%2,%3},{%4,%5,%6,%7},{%8,%9},{%0,%1,%2,%3};"                    \
      : "+f"(c[0]), "+f"(c[1]), "+f"(c[2]), "+f"(c[3])                        \
      : "r"(a[0]), "r"(a[1]), "r"(a[2]), "r"(a[3]), "r"(b[0]), "r"(b[1]))

#define CP16(dst, src)                                                        \
  asm volatile("cp.async.cg.shared.global [%0], [%1], 16;" ::"r"(dst), "l"(src))
#define CP_COMMIT() asm volatile("cp.async.commit_group;")
#define CP_WAIT1()  asm volatile("cp.async.wait_group 1;")

__device__ __forceinline__ uint32_t ldu32(const __half* p) {
  return *(const uint32_t*)p;
}

// ---------------------------------------------------------------------------
// fp32 -> fp16 convert (x) and tiled transpose+convert (weights)
// ---------------------------------------------------------------------------
__global__ void conv_half(const float* __restrict__ src,
                          __half* __restrict__ dst, int n4) {
  int i = blockIdx.x * blockDim.x + threadIdx.x;
  if (i < n4) {
    float4 v = *(const float4*)(src + 4 * (size_t)i);
    *(__half2*)(dst + 4 * (size_t)i) = __floats2half2_rn(v.x, v.y);
    *(__half2*)(dst + 4 * (size_t)i + 2) = __floats2half2_rn(v.z, v.w);
  }
}

// src[R][C] fp32 -> dst[C][R] half
__global__ void transpose_half(const float* __restrict__ src,
                               __half* __restrict__ dst, int R, int C) {
  __shared__ float t[32][33];
  int c0 = blockIdx.x * 32, r0 = blockIdx.y * 32;
  int x = threadIdx.x, y = threadIdx.y;  // 32 x 8
#pragma unroll
  for (int i = 0; i < 32; i += 8)
    t[y + i][x] = src[(size_t)(r0 + y + i) * C + c0 + x];
  __syncthreads();
#pragma unroll
  for (int i = 0; i < 32; i += 8)
    dst[(size_t)(c0 + y + i) * R + r0 + x] = __float2half_rn(t[x][y + i]);
}

// ---------------------------------------------------------------------------
// fp16 MMA GEMM: C[M,N] = A[M,K] @ B[K,N] with A [M][K] half, BT [N][K] half.
// 256x128x32 block tile, 2-stage cp.async, 256 threads = 8 warps (4M x 2N),
// warp tile 64x64 (4 mi x 8 ni m16n8k16 tiles, 2 ksteps/slab).
// Epilogue modes: 0 = half row-major, 1 = half transposed (V^T), 2 = fp32.
// ---------------------------------------------------------------------------
#define AS_STRIDE 40
#define BS_STRIDE 40
#define AS_SZ (256 * AS_STRIDE)   // halves
#define BS_SZ (128 * BS_STRIDE)
#define GEMM_SMEM_BYTES ((2 * AS_SZ + 2 * BS_SZ) * 2)

__device__ __forceinline__ void gemm_issue_slab(
    int tid, const __half* __restrict__ A, const __half* __restrict__ BT,
    int K, int row0, int col0, int k0, __half* as, __half* bs) {
#pragma unroll
  for (int l = 0; l < 4; l++) {   // A: 256 rows x 4 chunks
    int idx = tid + l * 256;
    int ar = idx >> 2, ac = (idx & 3) << 3;
    const __half* asrc = A + (size_t)(row0 + ar) * K + k0 + ac;
    uint32_t adst = (uint32_t)__cvta_generic_to_shared(as + ar * AS_STRIDE + ac);
    CP16(adst, asrc);
  }
#pragma unroll
  for (int l = 0; l < 2; l++) {   // B: 128 rows x 4 chunks
    int idx = tid + l * 256;
    int br = idx >> 2, bc = (idx & 3) << 3;
    const __half* bsrc = BT + (size_t)(col0 + br) * K + k0 + bc;
    uint32_t bdst = (uint32_t)__cvta_generic_to_shared(bs + br * BS_STRIDE + bc);
    CP16(bdst, bsrc);
  }
}

template <int MODE>
__device__ __forceinline__ void gemm_body(
    const __half* __restrict__ A, const __half* __restrict__ BT,
    void* __restrict__ Cv, int N, int K, int row0, int col0, __half* smp,
    int vb_base, int vhk_col0) {
  __half* As = smp;
  __half* Bs = smp + 2 * AS_SZ;

  const int tid = threadIdx.x;
  const int lane = tid & 31;
  const int w = tid >> 5;
  const int g = lane >> 2;
  const int t4 = lane & 3;
  const int warp_m = w & 3, warp_n = w >> 2;
  const int m0w = warp_m * 64, n0w = warp_n * 64;

  float acc[4][8][4];
#pragma unroll
  for (int mi = 0; mi < 4; mi++)
#pragma unroll
    for (int ni = 0; ni < 8; ni++)
#pragma unroll
      for (int e = 0; e < 4; e++) acc[mi][ni][e] = 0.f;

  gemm_issue_slab(tid, A, BT, K, row0, col0, 0, As, Bs);
  CP_COMMIT();
  gemm_issue_slab(tid, A, BT, K, row0, col0, 32, As + AS_SZ, Bs + BS_SZ);
  CP_COMMIT();

  const int nslab = K >> 5;
  for (int it = 0; it < nslab; it++) {
    CP_WAIT1();
    __syncthreads();
    const __half* as = As + (it & 1) * AS_SZ;
    const __half* bs = Bs + (it & 1) * BS_SZ;
#pragma unroll
    for (int ks = 0; ks < 2; ks++) {
      const int kk = ks * 16;
      uint32_t a[4][4];
#pragma unroll
      for (int mi = 0; mi < 4; mi++) {
        int m = m0w + mi * 16;
        a[mi][0] = ldu32(as + (m + g) * AS_STRIDE + kk + 2 * t4);
        a[mi][1] = ldu32(as + (m + g + 8) * AS_STRIDE + kk + 2 * t4);
        a[mi][2] = ldu32(as + (m + g) * AS_STRIDE + kk + 2 * t4 + 8);
        a[mi][3] = ldu32(as + (m + g + 8) * AS_STRIDE + kk + 2 * t4 + 8);
      }
      uint32_t b[8][2];
#pragma unroll
      for (int ni = 0; ni < 8; ni++) {
        int n = n0w + ni * 8 + g;
        b[ni][0] = ldu32(bs + n * BS_STRIDE + kk + 2 * t4);
        b[ni][1] = ldu32(bs + n * BS_STRIDE + kk + 2 * t4 + 8);
      }
#pragma unroll
      for (int mi = 0; mi < 4; mi++)
#pragma unroll
        for (int ni = 0; ni < 8; ni++) MMA_F16(acc[mi][ni], a[mi], b[ni]);
    }
    __syncthreads();
    int kn = (it + 2) << 5;
    if (kn < K)
      gemm_issue_slab(tid, A, BT, K, row0, col0, kn,
                      As + (it & 1) * AS_SZ, Bs + (it & 1) * BS_SZ);
    CP_COMMIT();
  }

#pragma unroll
  for (int mi = 0; mi < 4; mi++) {
    int r0 = row0 + m0w + mi * 16 + g;
#pragma unroll
    for (int ni = 0; ni < 8; ni++) {
      int col = col0 + n0w + ni * 8 + 2 * t4;
      if (MODE == 0) {   // half row-major
        __half* C = (__half*)Cv;
        *(__half2*)(C + (size_t)r0 * N + col) =
            __floats2half2_rn(acc[mi][ni][0], acc[mi][ni][1]);
        *(__half2*)(C + (size_t)(r0 + 8) * N + col) =
            __floats2half2_rn(acc[mi][ni][2], acc[mi][ni][3]);
      } else if (MODE == 1) {  // V^T: [b][hk][d][s]; caller guarantees single hk per col block
        __half* C = (__half*)Cv;
        int s0 = r0 & (S - 1);
        int b0 = r0 >> 11;
        int d = vhk_col0 + (col & (HD - 1));
        __half* base = C + ((size_t)(b0 * HKV) + vb_base) * HD * S;
        base[(size_t)d * S + s0] = __float2half_rn(acc[mi][ni][0]);
        base[(size_t)(d + 1) * S + s0] = __float2half_rn(acc[mi][ni][1]);
        base[(size_t)d * S + s0 + 8] = __float2half_rn(acc[mi][ni][2]);
        base[(size_t)(d + 1) * S + s0 + 8] = __float2half_rn(acc[mi][ni][3]);
      } else {  // fp32
        float* C = (float*)Cv;
        *(float2*)(C + (size_t)r0 * N + col) =
            make_float2(acc[mi][ni][0], acc[mi][ni][1]);
        *(float2*)(C + (size_t)(r0 + 8) * N + col) =
            make_float2(acc[mi][ni][2], acc[mi][ni][3]);
      }
    }
  }
}

// Merged QKV projection: grid.x = 16 (Q) + 4 (K) + 4 (V), grid.y = 16
__global__ void __launch_bounds__(256, 1)
qkv_gemm(const __half* __restrict__ xh, const __half* __restrict__ wqT,
         const __half* __restrict__ wkT, const __half* __restrict__ wvT,
         __half* __restrict__ q, __half* __restrict__ k,
         __half* __restrict__ vT) {
  extern __shared__ __half smp[];
  const int bx = blockIdx.x;
  const int row0 = blockIdx.y * 256;
  if (bx < 16) {
    gemm_body<0>(xh, wqT, q, QN, D, row0, bx * 128, smp, 0, 0);
  } else if (bx < 20) {
    gemm_body<0>(xh, wkT, k, KN, D, row0, (bx - 16) * 128, smp, 0, 0);
  } else {
    int col0 = (bx - 20) * 128;           // 128-wide => exactly one hk head
    gemm_body<1>(xh, wvT, vT, KN, D, row0, col0, smp, col0 >> 7,
                 0 /* d offset within head = col & 127 */);
  }
}

__global__ void __launch_bounds__(256, 1)
o_gemm(const __half* __restrict__ attnh, const __half* __restrict__ woT,
       float* __restrict__ out) {
  extern __shared__ __half smp[];
  gemm_body<2>(attnh, woT, out, D, QN, blockIdx.y * 256, blockIdx.x * 128, smp,
               0, 0);
}

// ---------------------------------------------------------------------------
// RoPE, in place on half q and k. 256 threads = 4 rows/block.
// ---------------------------------------------------------------------------
__global__ void __launch_bounds__(256)
rope_kernel(__half* __restrict__ q, __half* __restrict__ k) {
  const int row = blockIdx.x * 4 + (threadIdx.x >> 6);
  const int nh = H + HKV;
  const int bs = row / nh;
  const int hh = row - bs * nh;
  const int s = bs & (S - 1);
  __half* p = (hh < H) ? (q + (size_t)bs * QN + hh * HD)
                       : (k + (size_t)bs * KN + (hh - H) * HD);
  const int j = threadIdx.x & 63;
  const float x1 = __half2float(p[2 * j]);
  const float x2 = __half2float(p[2 * j + 1]);
  const float theta = exp2f(-(float)j * 0.20762050593045983f);
  const float ang = (float)s * theta;
  float sn, cs;
  sincosf(ang, &sn, &cs);
  __syncthreads();  // rows span 2 warps; block-wide barrier before in-place writes
  p[j] = __float2half_rn(x1 * cs - x2 * sn);
  p[j + 64] = __float2half_rn(x1 * sn + x2 * cs);
}

// ---------------------------------------------------------------------------
// Flash attention (causal, GQA), fp16 MMA, cp.async phase pipelining.
// Q [128][128]h, K [64][128]h (n-major = natural), V^T [128 d][64 s]h.
// ---------------------------------------------------------------------------
#define QS_STRIDE 136
#define KS_STRIDE 136
#define VT_STRIDE 72
#define PS_STRIDE 68   // fp32 scores
#define PH_STRIDE 72   // half probabilities
#define ATTN_SMEM_BYTES                                                        \
  ((128 * QS_STRIDE + 64 * KS_STRIDE + 128 * VT_STRIDE + 128 * PH_STRIDE) * 2 \
   + 128 * PS_STRIDE * 4 + 3 * 128 * 4)

__global__ void __launch_bounds__(256, 1)
attn_kernel(const __half* __restrict__ Q, const __half* __restrict__ K,
            const __half* __restrict__ VT, __half* __restrict__ O) {
  extern __shared__ __half smh[];
  __half* Qs = smh;                          // [128][136]
  __half* Ks = Qs + 128 * QS_STRIDE;         // [64][136]
  __half* Vs = Ks + 64 * KS_STRIDE;          // [128][72]  (V^T: d rows, s cols)
  __half* Ph = Vs + 128 * VT_STRIDE;         // [128][72]
  float* Ps = (float*)(Ph + 128 * PH_STRIDE);// [128][68]
  float* mrow = Ps + 128 * PS_STRIDE;
  float* lrow = mrow + 128;
  float* asc  = lrow + 128;

  const int tid = threadIdx.x;
  const int lane = tid & 31;
  const int w = tid >> 5;
  const int g = lane >> 2;
  const int t4 = lane & 3;
  const int warp_m = w & 3, warp_n = w >> 2;
  const int m0w = warp_m * 32;

  const int qi = (int)gridDim.x - 1 - (int)blockIdx.x;
  const int bh = blockIdx.y;
  const int b = bh >> 4;
  const int h = bh & 15;
  const int hk = h >> 2;
  const int q0 = qi * 128;

  const __half* qb = Q + (size_t)b * S * QN + h * HD;
  const __half* kb = K + (size_t)b * S * KN + hk * HD;
  const __half* vtb = VT + ((size_t)(b * HKV + hk)) * HD * S;

  // Prologue: Q tile (128 rows x 256B = 8 chunks/thread)
#pragma unroll
  for (int i = 0; i < 8; i++) {
    int idx = tid + i * 256;
    int r = idx >> 4, c8 = (idx & 15) << 3;
    uint32_t d = (uint32_t)__cvta_generic_to_shared(Qs + r * QS_STRIDE + c8);
    CP16(d, qb + (size_t)(q0 + r) * QN + c8);
  }
  CP_COMMIT();
  // K_0: 64 rows x 16 chunks
#pragma unroll
  for (int i = 0; i < 4; i++) {
    int idx = tid + i * 256;
    int n = idx >> 4, c8 = (idx & 15) << 3;
    uint32_t d = (uint32_t)__cvta_generic_to_shared(Ks + n * KS_STRIDE + c8);
    CP16(d, kb + (size_t)n * KN + c8);
  }
  CP_COMMIT();
  // V_0^T: 128 rows x 8 chunks
#pragma unroll
  for (int i = 0; i < 4; i++) {
    int idx = tid + i * 256;
    int dd = idx >> 3, c8 = (idx & 7) << 3;
    uint32_t d = (uint32_t)__cvta_generic_to_shared(Vs + dd * VT_STRIDE + c8);
    CP16(d, vtb + (size_t)dd * S + c8);
  }
  CP_COMMIT();

  if (tid < 128) { mrow[tid] = -INFINITY; lrow[tid] = 0.f; }

  float oacc[2][8][4];
#pragma unroll
  for (int mi = 0; mi < 2; mi++)
#pragma unroll
    for (int ni = 0; ni < 8; ni++)
#pragma unroll
      for (int e = 0; e < 4; e++) oacc[mi][ni][e] = 0.f;

  const float qk_scale = 0.08838834764831845f;
  const int T = (q0 >> 6) + 2;

  for (int t = 0; t < T; t++) {
    const int k0 = t << 6;
    CP_WAIT1();        // K_t (and Q on t=0) ready
    __syncthreads();

    // ---- scores: warp tile 32x32 (2 mi x 4 ni), 8 ksteps of 16 ----
    float sacc[2][4][4];
#pragma unroll
    for (int mi = 0; mi < 2; mi++)
#pragma unroll
      for (int ni = 0; ni < 4; ni++)
#pragma unroll
        for (int e = 0; e < 4; e++) sacc[mi][ni][e] = 0.f;

    const int n0s = warp_n * 32;
#pragma unroll
    for (int ks = 0; ks < 8; ks++) {
      const int kk = ks * 16;
      uint32_t a[2][4];
#pragma unroll
      for (int mi = 0; mi < 2; mi++) {
        int m = m0w + mi * 16;
        a[mi][0] = ldu32(Qs + (m + g) * QS_STRIDE + kk + 2 * t4);
        a[mi][1] = ldu32(Qs + (m + g + 8) * QS_STRIDE + kk + 2 * t4);
        a[mi][2] = ldu32(Qs + (m + g) * QS_STRIDE + kk + 2 * t4 + 8);
        a[mi][3] = ldu32(Qs + (m + g + 8) * QS_STRIDE + kk + 2 * t4 + 8);
      }
      uint32_t bfr[4][2];
#pragma unroll
      for (int ni = 0; ni < 4; ni++) {
        int n = n0s + ni * 8 + g;
        bfr[ni][0] = ldu32(Ks + n * KS_STRIDE + kk + 2 * t4);
        bfr[ni][1] = ldu32(Ks + n * KS_STRIDE + kk + 2 * t4 + 8);
      }
#pragma unroll
      for (int mi = 0; mi < 2; mi++)
#pragma unroll
        for (int ni = 0; ni < 4; ni++) MMA_F16(sacc[mi][ni], a[mi], bfr[ni]);
    }

    // ---- write scaled+masked scores (fp32) ----
    const bool diag = (k0 + 63 > q0);
#pragma unroll
    for (int mi = 0; mi < 2; mi++) {
      int r0 = m0w + mi * 16 + g;
#pragma unroll
      for (int ni = 0; ni < 4; ni++) {
        int col = n0s + ni * 8 + 2 * t4;
        float v0 = sacc[mi][ni][0] * qk_scale;
        float v1 = sacc[mi][ni][1] * qk_scale;
        float v2 = sacc[mi][ni][2] * qk_scale;
        float v3 = sacc[mi][ni][3] * qk_scale;
        if (diag) {
          int kc = k0 + col;
          int qr0 = q0 + r0, qr1 = qr0 + 8;
          if (kc > qr0) v0 = -1e30f;
          if (kc + 1 > qr0) v1 = -1e30f;
          if (kc > qr1) v2 = -1e30f;
          if (kc + 1 > qr1) v3 = -1e30f;
        }
        *(float2*)(Ps + r0 * PS_STRIDE + col) = make_float2(v0, v1);
        *(float2*)(Ps + (r0 + 8) * PS_STRIDE + col) = make_float2(v2, v3);
      }
    }
    __syncthreads();   // Ks free, Ps visible

    // Prefetch K_{t+1} (overlaps softmax + PV)
    if (t + 1 < T) {
#pragma unroll
      for (int i = 0; i < 4; i++) {
        int idx = tid + i * 256;
        int n = idx >> 4, c8 = (idx & 15) << 3;
        uint32_t d = (uint32_t)__cvta_generic_to_shared(Ks + n * KS_STRIDE + c8);
        CP16(d, kb + (size_t)(k0 + 64 + n) * KN + c8);
      }
    }
    CP_COMMIT();

    // ---- online softmax: 2 threads per row; probabilities -> half Ph ----
    {
      int r = tid >> 1;
      float* prow = Ps + r * PS_STRIDE + (tid & 1) * 32;
      __half* phrow = Ph + r * PH_STRIDE + (tid & 1) * 32;
      float mloc = -INFINITY;
#pragma unroll
      for (int j = 0; j < 32; j++) mloc = fmaxf(mloc, prow[j]);
      mloc = fmaxf(mloc, __shfl_xor_sync(0xffffffffu, mloc, 1));
      float mold = mrow[r];
      float mnew = fmaxf(mold, mloc);
      float lloc = 0.f;
#pragma unroll
      for (int j = 0; j < 32; j++) {
        __half eh = __float2half_rn(__expf(prow[j] - mnew));
        phrow[j] = eh;
        lloc += __half2float(eh);
      }
      lloc += __shfl_xor_sync(0xffffffffu, lloc, 1);
      if ((tid & 1) == 0) {
        float al = __expf(mold - mnew);
        asc[r] = al;
        mrow[r] = mnew;
        lrow[r] = lrow[r] * al + lloc;
      }
    }

    CP_WAIT1();        // V_t ready (K_{t+1} may remain in flight)
    __syncthreads();

    // ---- PV: warp tile 32x64 (2 mi x 8 ni), 4 ksteps of 16 ----
    {
      const int n0v = warp_n * 64;
#pragma unroll
      for (int mi = 0; mi < 2; mi++) {
        float al0 = asc[m0w + mi * 16 + g];
        float al1 = asc[m0w + mi * 16 + g + 8];
#pragma unroll
        for (int ni = 0; ni < 8; ni++) {
          oacc[mi][ni][0] *= al0;
          oacc[mi][ni][1] *= al0;
          oacc[mi][ni][2] *= al1;
          oacc[mi][ni][3] *= al1;
        }
      }
#pragma unroll
      for (int ks = 0; ks < 4; ks++) {
        const int kk = ks * 16;
        uint32_t a[2][4];
#pragma unroll
        for (int mi = 0; mi < 2; mi++) {
          int m = m0w + mi * 16;
          a[mi][0] = ldu32(Ph + (m + g) * PH_STRIDE + kk + 2 * t4);
          a[mi][1] = ldu32(Ph + (m + g + 8) * PH_STRIDE + kk + 2 * t4);
          a[mi][2] = ldu32(Ph + (m + g) * PH_STRIDE + kk + 2 * t4 + 8);
          a[mi][3] = ldu32(Ph + (m + g + 8) * PH_STRIDE + kk + 2 * t4 + 8);
        }
        uint32_t bfr[8][2];
#pragma unroll
        for (int ni = 0; ni < 8; ni++) {
          int n = n0v + ni * 8 + g;   // n = output dim d; Vs rows are d
          bfr[ni][0] = ldu32(Vs + n * VT_STRIDE + kk + 2 * t4);
          bfr[ni][1] = ldu32(Vs + n * VT_STRIDE + kk + 2 * t4 + 8);
        }
#pragma unroll
        for (int mi = 0; mi < 2; mi++)
#pragma unroll
          for (int ni = 0; ni < 8; ni++) MMA_F16(oacc[mi][ni], a[mi], bfr[ni]);
      }
    }
    __syncthreads();   // Vs free

    // Prefetch V_{t+1}^T (overlaps next scores)
    if (t + 1 < T) {
#pragma unroll
      for (int i = 0; i < 4; i++) {
        int idx = tid + i * 256;
        int dd = idx >> 3, c8 = (idx & 7) << 3;
        uint32_t d = (uint32_t)__cvta_generic_to_shared(Vs + dd * VT_STRIDE + c8);
        CP16(d, vtb + (size_t)dd * S + k0 + 64 + c8);
      }
    }
    CP_COMMIT();
  }

  // ---- finalize: O = half(oacc / l) ----
  {
    const int n0v = warp_n * 64;
#pragma unroll
    for (int mi = 0; mi < 2; mi++) {
      int r0 = m0w + mi * 16 + g;
      float inv0 = 1.f / lrow[r0];
      float inv1 = 1.f / lrow[r0 + 8];
#pragma unroll
      for (int ni = 0; ni < 8; ni++) {
        int col = h * HD + n0v + ni * 8 + 2 * t4;
        __half* o0 = O + (size_t)(b * S + q0 + r0) * QN + col;
        __half* o1 = O + (size_t)(b * S + q0 + r0 + 8) * QN + col;
        *(__half2*)o0 =
            __floats2half2_rn(oacc[mi][ni][0] * inv0, oacc[mi][ni][1] * inv0);
        *(__half2*)o1 =
            __floats2half2_rn(oacc[mi][ni][2] * inv1, oacc[mi][ni][3] * inv1);
      }
    }
  }
}

// ---------------------------------------------------------------------------
extern "C" void kernel_launch(void* const* d_in, const int* in_sizes, int n_in,
                              void* d_out, int out_size) {
  const float* x  = (const float*)d_in[0];
  const float* Wq = (const float*)d_in[1];
  const float* Wk = (const float*)d_in[2];
  const float* Wv = (const float*)d_in[3];
  const float* Wo = (const float*)d_in[4];
  float* out = (float*)d_out;

  __half *xh, *wqT, *wkT, *wvT, *woT, *qh, *kh, *vT, *attnh;
  cudaGetSymbolAddress((void**)&xh, g_xh);
  cudaGetSymbolAddress((void**)&wqT, g_wqT);
  cudaGetSymbolAddress((void**)&wkT, g_wkT);
  cudaGetSymbolAddress((void**)&wvT, g_wvT);
  cudaGetSymbolAddress((void**)&woT, g_woT);
  cudaGetSymbolAddress((void**)&qh, g_qh);
  cudaGetSymbolAddress((void**)&kh, g_kh);
  cudaGetSymbolAddress((void**)&vT, g_vT);
  cudaGetSymbolAddress((void**)&attnh, g_attnh);

  cudaFuncSetAttribute(qkv_gemm, cudaFuncAttributeMaxDynamicSharedMemorySize,
                       GEMM_SMEM_BYTES);
  cudaFuncSetAttribute(o_gemm, cudaFuncAttributeMaxDynamicSharedMemorySize,
                       GEMM_SMEM_BYTES);
  cudaFuncSetAttribute(attn_kernel, cudaFuncAttributeMaxDynamicSharedMemorySize,
                       ATTN_SMEM_BYTES);

  // fp16 operand prep
  conv_half<<<(M_ROWS * D / 4 + 255) / 256, 256>>>(x, xh, M_ROWS * D / 4);
  dim3 tb(32, 8);
  transpose_half<<<dim3(QN / 32, D / 32), tb>>>(Wq, wqT, D, QN);
  transpose_half<<<dim3(KN / 32, D / 32), tb>>>(Wk, wkT, D, KN);
  transpose_half<<<dim3(KN / 32, D / 32), tb>>>(Wv, wvT, D, KN);
  transpose_half<<<dim3(D / 32, QN / 32), tb>>>(Wo, woT, QN, D);

  dim3 blk(256);
  qkv_gemm<<<dim3(24, M_ROWS / 256), blk, GEMM_SMEM_BYTES>>>(xh, wqT, wkT, wvT,
                                                             qh, kh, vT);
  rope_kernel<<<B * S * (H + HKV) / 4, blk>>>(qh, kh);
  attn_kernel<<<dim3(S / 128, B * H), blk, ATTN_SMEM_BYTES>>>(qh, kh, vT, attnh);
  o_gemm<<<dim3(D / 128, M_ROWS / 256), blk, GEMM_SMEM_BYTES>>>(attnh, woT, out);
}

// round 7
// speedup vs baseline: 4.8865x; 1.0139x over previous
#include <cuda_runtime.h>
#include <cuda_fp16.h>
#include <math.h>
#include <stdint.h>

#define B 2
#define S 2048
#define D 2048
#define H 16
#define HKV 4
#define HD 128
#define M_ROWS (B*S)     // 4096
#define QN (H*HD)        // 2048
#define KN (HKV*HD)      // 512

// Scratch (allocation-free: device globals), fp16 operands everywhere
__device__ __half g_xh[(size_t)M_ROWS * D];
__device__ __half g_wqT[(size_t)QN * D];    // [N][K]
__device__ __half g_wkT[(size_t)KN * D];
__device__ __half g_wvT[(size_t)KN * D];
__device__ __half g_woT[(size_t)D * QN];
__device__ __half g_qh[(size_t)M_ROWS * QN];
__device__ __half g_kh[(size_t)M_ROWS * KN];
__device__ __half g_vT[(size_t)B * HKV * HD * S];  // [b][hk][d][s]
__device__ __half g_attnh[(size_t)M_ROWS * QN];

#define MMA_F16(c, a, b)                                                      \
  asm("mma.sync.aligned.m16n8k16.row.col.f32.f16.f16.f32 "                    \
      "{%0,%1,%2,%3},{%4,%5,%6,%7},{%8,%9},{%0,%1,%2,%3};"                    \
      : "+f"(c[0]), "+f"(c[1]), "+f"(c[2]), "+f"(c[3])                        \
      : "r"(a[0]), "r"(a[1]), "r"(a[2]), "r"(a[3]), "r"(b[0]), "r"(b[1]))

#define LDSM4(r0, r1, r2, r3, addr)                                           \
  asm volatile("ldmatrix.sync.aligned.m8n8.x4.shared.b16 {%0,%1,%2,%3}, [%4];"\
               : "=r"(r0), "=r"(r1), "=r"(r2), "=r"(r3) : "r"(addr))

#define CP16(dst, src)                                                        \
  asm volatile("cp.async.cg.shared.global [%0], [%1], 16;" ::"r"(dst), "l"(src))
#define CP_COMMIT() asm volatile("cp.async.commit_group;")
#define CP_WAIT1()  asm volatile("cp.async.wait_group 1;")

// ---------------------------------------------------------------------------
// fp32 -> fp16 convert (x), batched tiled transpose+convert (all 4 weights)
// ---------------------------------------------------------------------------
__global__ void conv_half(const float* __restrict__ src,
                          __half* __restrict__ dst, int n4) {
  int i = blockIdx.x * blockDim.x + threadIdx.x;
  if (i < n4) {
    float4 v = *(const float4*)(src + 4 * (size_t)i);
    *(__half2*)(dst + 4 * (size_t)i) = __floats2half2_rn(v.x, v.y);
    *(__half2*)(dst + 4 * (size_t)i + 2) = __floats2half2_rn(v.z, v.w);
  }
}

// 4 jobs (z): Wq, Wk, Wv, Wo. src[R][C] fp32 -> dst[C][R] half.
__global__ void transpose_all(const float* __restrict__ Wq,
                              const float* __restrict__ Wk,
                              const float* __restrict__ Wv,
                              const float* __restrict__ Wo,
                              __half* __restrict__ wqT, __half* __restrict__ wkT,
                              __half* __restrict__ wvT, __half* __restrict__ woT) {
  __shared__ float t[32][33];
  const float* src;
  __half* dst;
  int R, C;
  switch (blockIdx.z) {
    case 0: src = Wq; dst = wqT; R = D;  C = QN; break;
    case 1: src = Wk; dst = wkT; R = D;  C = KN; break;
    case 2: src = Wv; dst = wvT; R = D;  C = KN; break;
    default: src = Wo; dst = woT; R = QN; C = D;  break;
  }
  int c0 = blockIdx.x * 32, r0 = blockIdx.y * 32;
  if (c0 >= C || r0 >= R) return;
  int x = threadIdx.x, y = threadIdx.y;  // 32 x 8
#pragma unroll
  for (int i = 0; i < 32; i += 8)
    t[y + i][x] = src[(size_t)(r0 + y + i) * C + c0 + x];
  __syncthreads();
#pragma unroll
  for (int i = 0; i < 32; i += 8)
    dst[(size_t)(c0 + y + i) * R + r0 + x] = __float2half_rn(t[x][y + i]);
}

// ---------------------------------------------------------------------------
// fp16 MMA GEMM: C[M,N] = A[M,K] @ B[K,N] with A [M][K] half, BT [N][K] half.
// 256x128x32 block tile, 2-stage cp.async, 8 warps (4M x 2N), warp 64x64.
// Fragment loads via ldmatrix.x4. Epilogues: 0 half, 1 V^T half, 2 fp32.
// ---------------------------------------------------------------------------
#define AS_STRIDE 40
#define BS_STRIDE 40
#define AS_SZ (256 * AS_STRIDE)   // halves
#define BS_SZ (128 * BS_STRIDE)
#define GEMM_SMEM_BYTES ((2 * AS_SZ + 2 * BS_SZ) * 2)

__device__ __forceinline__ void gemm_issue_slab(
    int tid, const __half* __restrict__ A, const __half* __restrict__ BT,
    int K, int row0, int col0, int k0, __half* as, __half* bs) {
#pragma unroll
  for (int l = 0; l < 4; l++) {
    int idx = tid + l * 256;
    int ar = idx >> 2, ac = (idx & 3) << 3;
    const __half* asrc = A + (size_t)(row0 + ar) * K + k0 + ac;
    uint32_t adst = (uint32_t)__cvta_generic_to_shared(as + ar * AS_STRIDE + ac);
    CP16(adst, asrc);
  }
#pragma unroll
  for (int l = 0; l < 2; l++) {
    int idx = tid + l * 256;
    int br = idx >> 2, bc = (idx & 3) << 3;
    const __half* bsrc = BT + (size_t)(col0 + br) * K + k0 + bc;
    uint32_t bdst = (uint32_t)__cvta_generic_to_shared(bs + br * BS_STRIDE + bc);
    CP16(bdst, bsrc);
  }
}

template <int MODE>
__device__ __forceinline__ void gemm_body(
    const __half* __restrict__ A, const __half* __restrict__ BT,
    void* __restrict__ Cv, int N, int K, int row0, int col0, __half* smp,
    int vb_base) {
  __half* As = smp;
  __half* Bs = smp + 2 * AS_SZ;

  const int tid = threadIdx.x;
  const int lane = tid & 31;
  const int w = tid >> 5;
  const int g = lane >> 2;
  const int t4 = lane & 3;
  const int warp_m = w & 3, warp_n = w >> 2;
  const int m0w = warp_m * 64, n0w = warp_n * 64;

  // ldmatrix lane-address components
  const int a_lrow = (lane & 7) + ((lane >> 3) & 1) * 8;
  const int a_koff = (lane >> 4) * 8;
  const int b_lrow = (lane & 7) + (lane >> 4) * 8;
  const int b_koff = ((lane >> 3) & 1) * 8;

  float acc[4][8][4];
#pragma unroll
  for (int mi = 0; mi < 4; mi++)
#pragma unroll
    for (int ni = 0; ni < 8; ni++)
#pragma unroll
      for (int e = 0; e < 4; e++) acc[mi][ni][e] = 0.f;

  gemm_issue_slab(tid, A, BT, K, row0, col0, 0, As, Bs);
  CP_COMMIT();
  gemm_issue_slab(tid, A, BT, K, row0, col0, 32, As + AS_SZ, Bs + BS_SZ);
  CP_COMMIT();

  const uint32_t asu0 = (uint32_t)__cvta_generic_to_shared(As);
  const uint32_t bsu0 = (uint32_t)__cvta_generic_to_shared(Bs);

  const int nslab = K >> 5;
  for (int it = 0; it < nslab; it++) {
    CP_WAIT1();
    __syncthreads();
    const uint32_t asu = asu0 + (it & 1) * AS_SZ * 2;
    const uint32_t bsu = bsu0 + (it & 1) * BS_SZ * 2;
#pragma unroll
    for (int ks = 0; ks < 2; ks++) {
      const int kk = ks * 16;
      uint32_t a[4][4];
#pragma unroll
      for (int mi = 0; mi < 4; mi++) {
        uint32_t ad = asu +
            ((m0w + mi * 16 + a_lrow) * AS_STRIDE + kk + a_koff) * 2;
        LDSM4(a[mi][0], a[mi][1], a[mi][2], a[mi][3], ad);
      }
      uint32_t b[8][2];
#pragma unroll
      for (int nip = 0; nip < 4; nip++) {
        uint32_t bd = bsu +
            ((n0w + nip * 16 + b_lrow) * BS_STRIDE + kk + b_koff) * 2;
        LDSM4(b[2 * nip][0], b[2 * nip][1], b[2 * nip + 1][0],
              b[2 * nip + 1][1], bd);
      }
#pragma unroll
      for (int mi = 0; mi < 4; mi++)
#pragma unroll
        for (int ni = 0; ni < 8; ni++) MMA_F16(acc[mi][ni], a[mi], b[ni]);
    }
    __syncthreads();
    int kn = (it + 2) << 5;
    if (kn < K)
      gemm_issue_slab(tid, A, BT, K, row0, col0, kn,
                      As + (it & 1) * AS_SZ, Bs + (it & 1) * BS_SZ);
    CP_COMMIT();
  }

#pragma unroll
  for (int mi = 0; mi < 4; mi++) {
    int r0 = row0 + m0w + mi * 16 + g;
#pragma unroll
    for (int ni = 0; ni < 8; ni++) {
      int col = col0 + n0w + ni * 8 + 2 * t4;
      if (MODE == 0) {
        __half* C = (__half*)Cv;
        *(__half2*)(C + (size_t)r0 * N + col) =
            __floats2half2_rn(acc[mi][ni][0], acc[mi][ni][1]);
        *(__half2*)(C + (size_t)(r0 + 8) * N + col) =
            __floats2half2_rn(acc[mi][ni][2], acc[mi][ni][3]);
      } else if (MODE == 1) {
        __half* C = (__half*)Cv;
        int s0 = r0 & (S - 1);
        int b0 = r0 >> 11;
        int d = col & (HD - 1);
        __half* base = C + ((size_t)(b0 * HKV) + vb_base) * HD * S;
        base[(size_t)d * S + s0] = __float2half_rn(acc[mi][ni][0]);
        base[(size_t)(d + 1) * S + s0] = __float2half_rn(acc[mi][ni][1]);
        base[(size_t)d * S + s0 + 8] = __float2half_rn(acc[mi][ni][2]);
        base[(size_t)(d + 1) * S + s0 + 8] = __float2half_rn(acc[mi][ni][3]);
      } else {
        float* C = (float*)Cv;
        *(float2*)(C + (size_t)r0 * N + col) =
            make_float2(acc[mi][ni][0], acc[mi][ni][1]);
        *(float2*)(C + (size_t)(r0 + 8) * N + col) =
            make_float2(acc[mi][ni][2], acc[mi][ni][3]);
      }
    }
  }
}

__global__ void __launch_bounds__(256, 1)
qkv_gemm(const __half* __restrict__ xh, const __half* __restrict__ wqT,
         const __half* __restrict__ wkT, const __half* __restrict__ wvT,
         __half* __restrict__ q, __half* __restrict__ k,
         __half* __restrict__ vT) {
  extern __shared__ __half smp[];
  const int bx = blockIdx.x;
  const int row0 = blockIdx.y * 256;
  if (bx < 16) {
    gemm_body<0>(xh, wqT, q, QN, D, row0, bx * 128, smp, 0);
  } else if (bx < 20) {
    gemm_body<0>(xh, wkT, k, KN, D, row0, (bx - 16) * 128, smp, 0);
  } else {
    int col0 = (bx - 20) * 128;
    gemm_body<1>(xh, wvT, vT, KN, D, row0, col0, smp, col0 >> 7);
  }
}

__global__ void __launch_bounds__(256, 1)
o_gemm(const __half* __restrict__ attnh, const __half* __restrict__ woT,
       float* __restrict__ out) {
  extern __shared__ __half smp[];
  gemm_body<2>(attnh, woT, out, D, QN, blockIdx.y * 256, blockIdx.x * 128, smp, 0);
}

// ---------------------------------------------------------------------------
// RoPE, in place on half q and k. 256 threads = 4 rows/block.
// ---------------------------------------------------------------------------
__global__ void __launch_bounds__(256)
rope_kernel(__half* __restrict__ q, __half* __restrict__ k) {
  const int row = blockIdx.x * 4 + (threadIdx.x >> 6);
  const int nh = H + HKV;
  const int bs = row / nh;
  const int hh = row - bs * nh;
  const int s = bs & (S - 1);
  __half* p = (hh < H) ? (q + (size_t)bs * QN + hh * HD)
                       : (k + (size_t)bs * KN + (hh - H) * HD);
  const int j = threadIdx.x & 63;
  const float x1 = __half2float(p[2 * j]);
  const float x2 = __half2float(p[2 * j + 1]);
  const float theta = exp2f(-(float)j * 0.20762050593045983f);
  const float ang = (float)s * theta;
  float sn, cs;
  sincosf(ang, &sn, &cs);
  __syncthreads();
  p[j] = __float2half_rn(x1 * cs - x2 * sn);
  p[j + 64] = __float2half_rn(x1 * sn + x2 * cs);
}

// ---------------------------------------------------------------------------
// Flash attention (causal, GQA), fp16 MMA + ldmatrix, cp.async pipelining.
// ---------------------------------------------------------------------------
#define QS_STRIDE 136
#define KS_STRIDE 136
#define VT_STRIDE 72
#define PS_STRIDE 68   // fp32 scores
#define PH_STRIDE 72   // half probabilities
#define ATTN_SMEM_BYTES                                                        \
  ((128 * QS_STRIDE + 64 * KS_STRIDE + 128 * VT_STRIDE + 128 * PH_STRIDE) * 2 \
   + 128 * PS_STRIDE * 4 + 3 * 128 * 4)

__global__ void __launch_bounds__(256, 1)
attn_kernel(const __half* __restrict__ Q, const __half* __restrict__ K,
            const __half* __restrict__ VT, __half* __restrict__ O) {
  extern __shared__ __half smh[];
  __half* Qs = smh;                          // [128][136]
  __half* Ks = Qs + 128 * QS_STRIDE;         // [64][136]
  __half* Vs = Ks + 64 * KS_STRIDE;          // [128][72]  (V^T)
  __half* Ph = Vs + 128 * VT_STRIDE;         // [128][72]
  float* Ps = (float*)(Ph + 128 * PH_STRIDE);// [128][68]
  float* mrow = Ps + 128 * PS_STRIDE;
  float* lrow = mrow + 128;
  float* asc  = lrow + 128;

  const int tid = threadIdx.x;
  const int lane = tid & 31;
  const int w = tid >> 5;
  const int g = lane >> 2;
  const int t4 = lane & 3;
  const int warp_m = w & 3, warp_n = w >> 2;
  const int m0w = warp_m * 32;

  const int a_lrow = (lane & 7) + ((lane >> 3) & 1) * 8;
  const int a_koff = (lane >> 4) * 8;
  const int b_lrow = (lane & 7) + (lane >> 4) * 8;
  const int b_koff = ((lane >> 3) & 1) * 8;

  const uint32_t qsu = (uint32_t)__cvta_generic_to_shared(Qs);
  const uint32_t ksu = (uint32_t)__cvta_generic_to_shared(Ks);
  const uint32_t vsu = (uint32_t)__cvta_generic_to_shared(Vs);
  const uint32_t phu = (uint32_t)__cvta_generic_to_shared(Ph);

  const int qi = (int)gridDim.x - 1 - (int)blockIdx.x;
  const int bh = blockIdx.y;
  const int b = bh >> 4;
  const int h = bh & 15;
  const int hk = h >> 2;
  const int q0 = qi * 128;

  const __half* qb = Q + (size_t)b * S * QN + h * HD;
  const __half* kb = K + (size_t)b * S * KN + hk * HD;
  const __half* vtb = VT + ((size_t)(b * HKV + hk)) * HD * S;

#pragma unroll
  for (int i = 0; i < 8; i++) {
    int idx = tid + i * 256;
    int r = idx >> 4, c8 = (idx & 15) << 3;
    uint32_t d = (uint32_t)__cvta_generic_to_shared(Qs + r * QS_STRIDE + c8);
    CP16(d, qb + (size_t)(q0 + r) * QN + c8);
  }
  CP_COMMIT();
#pragma unroll
  for (int i = 0; i < 4; i++) {
    int idx = tid + i * 256;
    int n = idx >> 4, c8 = (idx & 15) << 3;
    uint32_t d = (uint32_t)__cvta_generic_to_shared(Ks + n * KS_STRIDE + c8);
    CP16(d, kb + (size_t)n * KN + c8);
  }
  CP_COMMIT();
#pragma unroll
  for (int i = 0; i < 4; i++) {
    int idx = tid + i * 256;
    int dd = idx >> 3, c8 = (idx & 7) << 3;
    uint32_t d = (uint32_t)__cvta_generic_to_shared(Vs + dd * VT_STRIDE + c8);
    CP16(d, vtb + (size_t)dd * S + c8);
  }
  CP_COMMIT();

  if (tid < 128) { mrow[tid] = -INFINITY; lrow[tid] = 0.f; }

  float oacc[2][8][4];
#pragma unroll
  for (int mi = 0; mi < 2; mi++)
#pragma unroll
    for (int ni = 0; ni < 8; ni++)
#pragma unroll
      for (int e = 0; e < 4; e++) oacc[mi][ni][e] = 0.f;

  const float qk_scale = 0.08838834764831845f;
  const int T = (q0 >> 6) + 2;

  for (int t = 0; t < T; t++) {
    const int k0 = t << 6;
    CP_WAIT1();
    __syncthreads();

    // ---- scores ----
    float sacc[2][4][4];
#pragma unroll
    for (int mi = 0; mi < 2; mi++)
#pragma unroll
      for (int ni = 0; ni < 4; ni++)
#pragma unroll
        for (int e = 0; e < 4; e++) sacc[mi][ni][e] = 0.f;

    const int n0s = warp_n * 32;
#pragma unroll
    for (int ks = 0; ks < 8; ks++) {
      const int kk = ks * 16;
      uint32_t a[2][4];
#pragma unroll
      for (int mi = 0; mi < 2; mi++) {
        uint32_t ad = qsu +
            ((m0w + mi * 16 + a_lrow) * QS_STRIDE + kk + a_koff) * 2;
        LDSM4(a[mi][0], a[mi][1], a[mi][2], a[mi][3], ad);
      }
      uint32_t bfr[4][2];
#pragma unroll
      for (int nip = 0; nip < 2; nip++) {
        uint32_t bd = ksu +
            ((n0s + nip * 16 + b_lrow) * KS_STRIDE + kk + b_koff) * 2;
        LDSM4(bfr[2 * nip][0], bfr[2 * nip][1], bfr[2 * nip + 1][0],
              bfr[2 * nip + 1][1], bd);
      }
#pragma unroll
      for (int mi = 0; mi < 2; mi++)
#pragma unroll
        for (int ni = 0; ni < 4; ni++) MMA_F16(sacc[mi][ni], a[mi], bfr[ni]);
    }

    // ---- write scaled+masked scores (fp32) ----
    const bool diag = (k0 + 63 > q0);
#pragma unroll
    for (int mi = 0; mi < 2; mi++) {
      int r0 = m0w + mi * 16 + g;
#pragma unroll
      for (int ni = 0; ni < 4; ni++) {
        int col = n0s + ni * 8 + 2 * t4;
        float v0 = sacc[mi][ni][0] * qk_scale;
        float v1 = sacc[mi][ni][1] * qk_scale;
        float v2 = sacc[mi][ni][2] * qk_scale;
        float v3 = sacc[mi][ni][3] * qk_scale;
        if (diag) {
          int kc = k0 + col;
          int qr0 = q0 + r0, qr1 = qr0 + 8;
          if (kc > qr0) v0 = -1e30f;
          if (kc + 1 > qr0) v1 = -1e30f;
          if (kc > qr1) v2 = -1e30f;
          if (kc + 1 > qr1) v3 = -1e30f;
        }
        *(float2*)(Ps + r0 * PS_STRIDE + col) = make_float2(v0, v1);
        *(float2*)(Ps + (r0 + 8) * PS_STRIDE + col) = make_float2(v2, v3);
      }
    }
    __syncthreads();

    if (t + 1 < T) {
#pragma unroll
      for (int i = 0; i < 4; i++) {
        int idx = tid + i * 256;
        int n = idx >> 4, c8 = (idx & 15) << 3;
        uint32_t d = (uint32_t)__cvta_generic_to_shared(Ks + n * KS_STRIDE + c8);
        CP16(d, kb + (size_t)(k0 + 64 + n) * KN + c8);
      }
    }
    CP_COMMIT();

    // ---- online softmax ----
    {
      int r = tid >> 1;
      float* prow = Ps + r * PS_STRIDE + (tid & 1) * 32;
      __half* phrow = Ph + r * PH_STRIDE + (tid & 1) * 32;
      float mloc = -INFINITY;
#pragma unroll
      for (int j = 0; j < 32; j++) mloc = fmaxf(mloc, prow[j]);
      mloc = fmaxf(mloc, __shfl_xor_sync(0xffffffffu, mloc, 1));
      float mold = mrow[r];
      float mnew = fmaxf(mold, mloc);
      float lloc = 0.f;
#pragma unroll
      for (int j = 0; j < 32; j++) {
        __half eh = __float2half_rn(__expf(prow[j] - mnew));
        phrow[j] = eh;
        lloc += __half2float(eh);
      }
      lloc += __shfl_xor_sync(0xffffffffu, lloc, 1);
      if ((tid & 1) == 0) {
        float al = __expf(mold - mnew);
        asc[r] = al;
        mrow[r] = mnew;
        lrow[r] = lrow[r] * al + lloc;
      }
    }

    CP_WAIT1();
    __syncthreads();

    // ---- PV ----
    {
      const int n0v = warp_n * 64;
#pragma unroll
      for (int mi = 0; mi < 2; mi++) {
        float al0 = asc[m0w + mi * 16 + g];
        float al1 = asc[m0w + mi * 16 + g + 8];
#pragma unroll
        for (int ni = 0; ni < 8; ni++) {
          oacc[mi][ni][0] *= al0;
          oacc[mi][ni][1] *= al0;
          oacc[mi][ni][2] *= al1;
          oacc[mi][ni][3] *= al1;
        }
      }
#pragma unroll
      for (int ks = 0; ks < 4; ks++) {
        const int kk = ks * 16;
        uint32_t a[2][4];
#pragma unroll
        for (int mi = 0; mi < 2; mi++) {
          uint32_t ad = phu +
              ((m0w + mi * 16 + a_lrow) * PH_STRIDE + kk + a_koff) * 2;
          LDSM4(a[mi][0], a[mi][1], a[mi][2], a[mi][3], ad);
        }
        uint32_t bfr[8][2];
#pragma unroll
        for (int nip = 0; nip < 4; nip++) {
          uint32_t bd = vsu +
              ((n0v + nip * 16 + b_lrow) * VT_STRIDE + kk + b_koff) * 2;
          LDSM4(bfr[2 * nip][0], bfr[2 * nip][1], bfr[2 * nip + 1][0],
                bfr[2 * nip + 1][1], bd);
        }
#pragma unroll
        for (int mi = 0; mi < 2; mi++)
#pragma unroll
          for (int ni = 0; ni < 8; ni++) MMA_F16(oacc[mi][ni], a[mi], bfr[ni]);
      }
    }
    __syncthreads();

    if (t + 1 < T) {
#pragma unroll
      for (int i = 0; i < 4; i++) {
        int idx = tid + i * 256;
        int dd = idx >> 3, c8 = (idx & 7) << 3;
        uint32_t d = (uint32_t)__cvta_generic_to_shared(Vs + dd * VT_STRIDE + c8);
        CP16(d, vtb + (size_t)dd * S + k0 + 64 + c8);
      }
    }
    CP_COMMIT();
  }

  // ---- finalize ----
  {
    const int n0v = warp_n * 64;
#pragma unroll
    for (int mi = 0; mi < 2; mi++) {
      int r0 = m0w + mi * 16 + g;
      float inv0 = 1.f / lrow[r0];
      float inv1 = 1.f / lrow[r0 + 8];
#pragma unroll
      for (int ni = 0; ni < 8; ni++) {
        int col = h * HD + n0v + ni * 8 + 2 * t4;
        __half* o0 = O + (size_t)(b * S + q0 + r0) * QN + col;
        __half* o1 = O + (size_t)(b * S + q0 + r0 + 8) * QN + col;
        *(__half2*)o0 =
            __floats2half2_rn(oacc[mi][ni][0] * inv0, oacc[mi][ni][1] * inv0);
        *(__half2*)o1 =
            __floats2half2_rn(oacc[mi][ni][2] * inv1, oacc[mi][ni][3] * inv1);
      }
    }
  }
}

// ---------------------------------------------------------------------------
extern "C" void kernel_launch(void* const* d_in, const int* in_sizes, int n_in,
                              void* d_out, int out_size) {
  const float* x  = (const float*)d_in[0];
  const float* Wq = (const float*)d_in[1];
  const float* Wk = (const float*)d_in[2];
  const float* Wv = (const float*)d_in[3];
  const float* Wo = (const float*)d_in[4];
  float* out = (float*)d_out;

  __half *xh, *wqT, *wkT, *wvT, *woT, *qh, *kh, *vT, *attnh;
  cudaGetSymbolAddress((void**)&xh, g_xh);
  cudaGetSymbolAddress((void**)&wqT, g_wqT);
  cudaGetSymbolAddress((void**)&wkT, g_wkT);
  cudaGetSymbolAddress((void**)&wvT, g_wvT);
  cudaGetSymbolAddress((void**)&woT, g_woT);
  cudaGetSymbolAddress((void**)&qh, g_qh);
  cudaGetSymbolAddress((void**)&kh, g_kh);
  cudaGetSymbolAddress((void**)&vT, g_vT);
  cudaGetSymbolAddress((void**)&attnh, g_attnh);

  cudaFuncSetAttribute(qkv_gemm, cudaFuncAttributeMaxDynamicSharedMemorySize,
                       GEMM_SMEM_BYTES);
  cudaFuncSetAttribute(o_gemm, cudaFuncAttributeMaxDynamicSharedMemorySize,
                       GEMM_SMEM_BYTES);
  cudaFuncSetAttribute(attn_kernel, cudaFuncAttributeMaxDynamicSharedMemorySize,
                       ATTN_SMEM_BYTES);

  // operand prep (2 launches)
  conv_half<<<(M_ROWS * D / 4 + 255) / 256, 256>>>(x, xh, M_ROWS * D / 4);
  transpose_all<<<dim3(64, 64, 4), dim3(32, 8)>>>(Wq, Wk, Wv, Wo,
                                                  wqT, wkT, wvT, woT);

  dim3 blk(256);
  qkv_gemm<<<dim3(24, M_ROWS / 256), blk, GEMM_SMEM_BYTES>>>(xh, wqT, wkT, wvT,
                                                             qh, kh, vT);
  rope_kernel<<<B * S * (H + HKV) / 4, blk>>>(qh, kh);
  attn_kernel<<<dim3(S / 128, B * H), blk, ATTN_SMEM_BYTES>>>(qh, kh, vT, attnh);
  o_gemm<<<dim3(D / 128, M_ROWS / 256), blk, GEMM_SMEM_BYTES>>>(attnh, woT, out);
}

// round 8
// speedup vs baseline: 5.7054x; 1.1676x over previous
#include <cuda_runtime.h>
#include <cuda_fp16.h>
#include <math.h>
#include <stdint.h>

#define B 2
#define S 2048
#define D 2048
#define H 16
#define HKV 4
#define HD 128
#define M_ROWS (B*S)     // 4096
#define QN (H*HD)        // 2048
#define KN (HKV*HD)      // 512

// Scratch (allocation-free: device globals), fp16 operands everywhere
__device__ __half g_xh[(size_t)M_ROWS * D];
__device__ __half g_wqT[(size_t)QN * D];    // [N][K]
__device__ __half g_wkT[(size_t)KN * D];
__device__ __half g_wvT[(size_t)KN * D];
__device__ __half g_woT[(size_t)D * QN];
__device__ __half g_qh[(size_t)M_ROWS * QN];
__device__ __half g_kh[(size_t)M_ROWS * KN];
__device__ __half g_vT[(size_t)B * HKV * HD * S];  // [b][hk][d][s]
__device__ __half g_attnh[(size_t)M_ROWS * QN];

#define MMA_F16(c, a, b)                                                      \
  asm("mma.sync.aligned.m16n8k16.row.col.f32.f16.f16.f32 "                    \
      "{%0,%1,%2,%3},{%4,%5,%6,%7},{%8,%9},{%0,%1,%2,%3};"                    \
      : "+f"(c[0]), "+f"(c[1]), "+f"(c[2]), "+f"(c[3])                        \
      : "r"(a[0]), "r"(a[1]), "r"(a[2]), "r"(a[3]), "r"(b[0]), "r"(b[1]))

#define LDSM4(r0, r1, r2, r3, addr)                                           \
  asm volatile("ldmatrix.sync.aligned.m8n8.x4.shared.b16 {%0,%1,%2,%3}, [%4];"\
               : "=r"(r0), "=r"(r1), "=r"(r2), "=r"(r3) : "r"(addr))

#define CP16(dst, src)                                                        \
  asm volatile("cp.async.cg.shared.global [%0], [%1], 16;" ::"r"(dst), "l"(src))
#define CP_COMMIT() asm volatile("cp.async.commit_group;")
#define CP_WAIT1()  asm volatile("cp.async.wait_group 1;")
#define CP_WAIT2()  asm volatile("cp.async.wait_group 2;")
#define CP_WAIT3()  asm volatile("cp.async.wait_group 3;")

// ---------------------------------------------------------------------------
// fp32 -> fp16 convert (x), batched tiled transpose+convert (all 4 weights)
// ---------------------------------------------------------------------------
__global__ void conv_half(const float* __restrict__ src,
                          __half* __restrict__ dst, int n4) {
  int i = blockIdx.x * blockDim.x + threadIdx.x;
  if (i < n4) {
    float4 v = *(const float4*)(src + 4 * (size_t)i);
    *(__half2*)(dst + 4 * (size_t)i) = __floats2half2_rn(v.x, v.y);
    *(__half2*)(dst + 4 * (size_t)i + 2) = __floats2half2_rn(v.z, v.w);
  }
}

__global__ void transpose_all(const float* __restrict__ Wq,
                              const float* __restrict__ Wk,
                              const float* __restrict__ Wv,
                              const float* __restrict__ Wo,
                              __half* __restrict__ wqT, __half* __restrict__ wkT,
                              __half* __restrict__ wvT, __half* __restrict__ woT) {
  __shared__ float t[32][33];
  const float* src;
  __half* dst;
  int R, C;
  switch (blockIdx.z) {
    case 0: src = Wq; dst = wqT; R = D;  C = QN; break;
    case 1: src = Wk; dst = wkT; R = D;  C = KN; break;
    case 2: src = Wv; dst = wvT; R = D;  C = KN; break;
    default: src = Wo; dst = woT; R = QN; C = D;  break;
  }
  int c0 = blockIdx.x * 32, r0 = blockIdx.y * 32;
  if (c0 >= C || r0 >= R) return;
  int x = threadIdx.x, y = threadIdx.y;
#pragma unroll
  for (int i = 0; i < 32; i += 8)
    t[y + i][x] = src[(size_t)(r0 + y + i) * C + c0 + x];
  __syncthreads();
#pragma unroll
  for (int i = 0; i < 32; i += 8)
    dst[(size_t)(c0 + y + i) * R + r0 + x] = __float2half_rn(t[x][y + i]);
}

// ---------------------------------------------------------------------------
// fp16 MMA GEMM (unchanged from R7): 256x128x32 tile, 2-stage cp.async,
// ldmatrix fragments, 8 warps (4M x 2N), warp 64x64.
// ---------------------------------------------------------------------------
#define AS_STRIDE 40
#define BS_STRIDE 40
#define AS_SZ (256 * AS_STRIDE)
#define BS_SZ (128 * BS_STRIDE)
#define GEMM_SMEM_BYTES ((2 * AS_SZ + 2 * BS_SZ) * 2)

__device__ __forceinline__ void gemm_issue_slab(
    int tid, const __half* __restrict__ A, const __half* __restrict__ BT,
    int K, int row0, int col0, int k0, __half* as, __half* bs) {
#pragma unroll
  for (int l = 0; l < 4; l++) {
    int idx = tid + l * 256;
    int ar = idx >> 2, ac = (idx & 3) << 3;
    const __half* asrc = A + (size_t)(row0 + ar) * K + k0 + ac;
    uint32_t adst = (uint32_t)__cvta_generic_to_shared(as + ar * AS_STRIDE + ac);
    CP16(adst, asrc);
  }
#pragma unroll
  for (int l = 0; l < 2; l++) {
    int idx = tid + l * 256;
    int br = idx >> 2, bc = (idx & 3) << 3;
    const __half* bsrc = BT + (size_t)(col0 + br) * K + k0 + bc;
    uint32_t bdst = (uint32_t)__cvta_generic_to_shared(bs + br * BS_STRIDE + bc);
    CP16(bdst, bsrc);
  }
}

template <int MODE>
__device__ __forceinline__ void gemm_body(
    const __half* __restrict__ A, const __half* __restrict__ BT,
    void* __restrict__ Cv, int N, int K, int row0, int col0, __half* smp,
    int vb_base) {
  __half* As = smp;
  __half* Bs = smp + 2 * AS_SZ;

  const int tid = threadIdx.x;
  const int lane = tid & 31;
  const int w = tid >> 5;
  const int g = lane >> 2;
  const int t4 = lane & 3;
  const int warp_m = w & 3, warp_n = w >> 2;
  const int m0w = warp_m * 64, n0w = warp_n * 64;

  const int a_lrow = (lane & 7) + ((lane >> 3) & 1) * 8;
  const int a_koff = (lane >> 4) * 8;
  const int b_lrow = (lane & 7) + (lane >> 4) * 8;
  const int b_koff = ((lane >> 3) & 1) * 8;

  float acc[4][8][4];
#pragma unroll
  for (int mi = 0; mi < 4; mi++)
#pragma unroll
    for (int ni = 0; ni < 8; ni++)
#pragma unroll
      for (int e = 0; e < 4; e++) acc[mi][ni][e] = 0.f;

  gemm_issue_slab(tid, A, BT, K, row0, col0, 0, As, Bs);
  CP_COMMIT();
  gemm_issue_slab(tid, A, BT, K, row0, col0, 32, As + AS_SZ, Bs + BS_SZ);
  CP_COMMIT();

  const uint32_t asu0 = (uint32_t)__cvta_generic_to_shared(As);
  const uint32_t bsu0 = (uint32_t)__cvta_generic_to_shared(Bs);

  const int nslab = K >> 5;
  for (int it = 0; it < nslab; it++) {
    CP_WAIT1();
    __syncthreads();
    const uint32_t asu = asu0 + (it & 1) * AS_SZ * 2;
    const uint32_t bsu = bsu0 + (it & 1) * BS_SZ * 2;
#pragma unroll
    for (int ks = 0; ks < 2; ks++) {
      const int kk = ks * 16;
      uint32_t a[4][4];
#pragma unroll
      for (int mi = 0; mi < 4; mi++) {
        uint32_t ad = asu +
            ((m0w + mi * 16 + a_lrow) * AS_STRIDE + kk + a_koff) * 2;
        LDSM4(a[mi][0], a[mi][1], a[mi][2], a[mi][3], ad);
      }
      uint32_t b[8][2];
#pragma unroll
      for (int nip = 0; nip < 4; nip++) {
        uint32_t bd = bsu +
            ((n0w + nip * 16 + b_lrow) * BS_STRIDE + kk + b_koff) * 2;
        LDSM4(b[2 * nip][0], b[2 * nip][1], b[2 * nip + 1][0],
              b[2 * nip + 1][1], bd);
      }
#pragma unroll
      for (int mi = 0; mi < 4; mi++)
#pragma unroll
        for (int ni = 0; ni < 8; ni++) MMA_F16(acc[mi][ni], a[mi], b[ni]);
    }
    __syncthreads();
    int kn = (it + 2) << 5;
    if (kn < K)
      gemm_issue_slab(tid, A, BT, K, row0, col0, kn,
                      As + (it & 1) * AS_SZ, Bs + (it & 1) * BS_SZ);
    CP_COMMIT();
  }

#pragma unroll
  for (int mi = 0; mi < 4; mi++) {
    int r0 = row0 + m0w + mi * 16 + g;
#pragma unroll
    for (int ni = 0; ni < 8; ni++) {
      int col = col0 + n0w + ni * 8 + 2 * t4;
      if (MODE == 0) {
        __half* C = (__half*)Cv;
        *(__half2*)(C + (size_t)r0 * N + col) =
            __floats2half2_rn(acc[mi][ni][0], acc[mi][ni][1]);
        *(__half2*)(C + (size_t)(r0 + 8) * N + col) =
            __floats2half2_rn(acc[mi][ni][2], acc[mi][ni][3]);
      } else if (MODE == 1) {
        __half* C = (__half*)Cv;
        int s0 = r0 & (S - 1);
        int b0 = r0 >> 11;
        int d = col & (HD - 1);
        __half* base = C + ((size_t)(b0 * HKV) + vb_base) * HD * S;
        base[(size_t)d * S + s0] = __float2half_rn(acc[mi][ni][0]);
        base[(size_t)(d + 1) * S + s0] = __float2half_rn(acc[mi][ni][1]);
        base[(size_t)d * S + s0 + 8] = __float2half_rn(acc[mi][ni][2]);
        base[(size_t)(d + 1) * S + s0 + 8] = __float2half_rn(acc[mi][ni][3]);
      } else {
        float* C = (float*)Cv;
        *(float2*)(C + (size_t)r0 * N + col) =
            make_float2(acc[mi][ni][0], acc[mi][ni][1]);
        *(float2*)(C + (size_t)(r0 + 8) * N + col) =
            make_float2(acc[mi][ni][2], acc[mi][ni][3]);
      }
    }
  }
}

__global__ void __launch_bounds__(256, 1)
qkv_gemm(const __half* __restrict__ xh, const __half* __restrict__ wqT,
         const __half* __restrict__ wkT, const __half* __restrict__ wvT,
         __half* __restrict__ q, __half* __restrict__ k,
         __half* __restrict__ vT) {
  extern __shared__ __half smp[];
  const int bx = blockIdx.x;
  const int row0 = blockIdx.y * 256;
  if (bx < 16) {
    gemm_body<0>(xh, wqT, q, QN, D, row0, bx * 128, smp, 0);
  } else if (bx < 20) {
    gemm_body<0>(xh, wkT, k, KN, D, row0, (bx - 16) * 128, smp, 0);
  } else {
    int col0 = (bx - 20) * 128;
    gemm_body<1>(xh, wvT, vT, KN, D, row0, col0, smp, col0 >> 7);
  }
}

__global__ void __launch_bounds__(256, 1)
o_gemm(const __half* __restrict__ attnh, const __half* __restrict__ woT,
       float* __restrict__ out) {
  extern __shared__ __half smp[];
  gemm_body<2>(attnh, woT, out, D, QN, blockIdx.y * 256, blockIdx.x * 128, smp, 0);
}

// ---------------------------------------------------------------------------
// RoPE (unchanged)
// ---------------------------------------------------------------------------
__global__ void __launch_bounds__(256)
rope_kernel(__half* __restrict__ q, __half* __restrict__ k) {
  const int row = blockIdx.x * 4 + (threadIdx.x >> 6);
  const int nh = H + HKV;
  const int bs = row / nh;
  const int hh = row - bs * nh;
  const int s = bs & (S - 1);
  __half* p = (hh < H) ? (q + (size_t)bs * QN + hh * HD)
                       : (k + (size_t)bs * KN + (hh - H) * HD);
  const int j = threadIdx.x & 63;
  const float x1 = __half2float(p[2 * j]);
  const float x2 = __half2float(p[2 * j + 1]);
  const float theta = exp2f(-(float)j * 0.20762050593045983f);
  const float ang = (float)s * theta;
  float sn, cs;
  sincosf(ang, &sn, &cs);
  __syncthreads();
  p[j] = __float2half_rn(x1 * cs - x2 * sn);
  p[j + 64] = __float2half_rn(x1 * sn + x2 * cs);
}

// ---------------------------------------------------------------------------
// Flash attention: FA2-style register softmax. 8 warps x 16 q-rows x 64 cols.
// Double-buffered K/V via cp.async groups (Q+K0 | V0 | K1 | V1 | ...).
// P never touches smem: QK C-fragments are repacked in-register into PV
// A-fragments.
// ---------------------------------------------------------------------------
#define QS_STRIDE 136
#define KS_STRIDE 136
#define VT_STRIDE 72
#define KS_SZ (64 * KS_STRIDE)     // halves, one buffer
#define VS_SZ (128 * VT_STRIDE)
#define ATTN_SMEM_BYTES ((128 * QS_STRIDE + 2 * KS_SZ + 2 * VS_SZ) * 2)

__device__ __forceinline__ void attn_issue_k(int tid, const __half* src,
                                             __half* dst) {
#pragma unroll
  for (int i = 0; i < 4; i++) {
    int idx = tid + i * 256;
    int n = idx >> 4, c8 = (idx & 15) << 3;
    uint32_t d = (uint32_t)__cvta_generic_to_shared(dst + n * KS_STRIDE + c8);
    CP16(d, src + (size_t)n * KN + c8);
  }
}
__device__ __forceinline__ void attn_issue_v(int tid, const __half* src,
                                             __half* dst) {
#pragma unroll
  for (int i = 0; i < 4; i++) {
    int idx = tid + i * 256;
    int dd = idx >> 3, c8 = (idx & 7) << 3;
    uint32_t d = (uint32_t)__cvta_generic_to_shared(dst + dd * VT_STRIDE + c8);
    CP16(d, src + (size_t)dd * S + c8);
  }
}

__global__ void __launch_bounds__(256, 1)
attn_kernel(const __half* __restrict__ Q, const __half* __restrict__ K,
            const __half* __restrict__ VT, __half* __restrict__ O) {
  extern __shared__ __half smh[];
  __half* Qs = smh;                      // [128][136]
  __half* Ks = Qs + 128 * QS_STRIDE;     // 2 x [64][136]
  __half* Vs = Ks + 2 * KS_SZ;           // 2 x [128][72]

  const int tid = threadIdx.x;
  const int lane = tid & 31;
  const int w = tid >> 5;
  const int g = lane >> 2;
  const int t4 = lane & 3;
  const int m0 = w * 16;                 // warp owns rows m0..m0+15, all 64 cols

  const int a_lrow = (lane & 7) + ((lane >> 3) & 1) * 8;
  const int a_koff = (lane >> 4) * 8;
  const int b_lrow = (lane & 7) + (lane >> 4) * 8;
  const int b_koff = ((lane >> 3) & 1) * 8;

  const uint32_t qsu = (uint32_t)__cvta_generic_to_shared(Qs);
  const uint32_t ksu0 = (uint32_t)__cvta_generic_to_shared(Ks);
  const uint32_t vsu0 = (uint32_t)__cvta_generic_to_shared(Vs);

  const int qi = (int)gridDim.x - 1 - (int)blockIdx.x;
  const int bh = blockIdx.y;
  const int b = bh >> 4;
  const int h = bh & 15;
  const int hk = h >> 2;
  const int q0 = qi * 128;

  const __half* qb = Q + (size_t)b * S * QN + h * HD;
  const __half* kb = K + (size_t)b * S * KN + hk * HD;
  const __half* vtb = VT + ((size_t)(b * HKV + hk)) * HD * S;

  const int T = (q0 >> 6) + 2;

  // Prologue groups: G1 = Q + K0, G2 = V0, G3 = K1, G4 = V1  (T >= 2 always)
#pragma unroll
  for (int i = 0; i < 8; i++) {
    int idx = tid + i * 256;
    int r = idx >> 4, c8 = (idx & 15) << 3;
    uint32_t d = (uint32_t)__cvta_generic_to_shared(Qs + r * QS_STRIDE + c8);
    CP16(d, qb + (size_t)(q0 + r) * QN + c8);
  }
  attn_issue_k(tid, kb, Ks);
  CP_COMMIT();
  attn_issue_v(tid, vtb, Vs);
  CP_COMMIT();
  attn_issue_k(tid, kb + (size_t)64 * KN, Ks + KS_SZ);
  CP_COMMIT();
  attn_issue_v(tid, vtb + 64, Vs + VS_SZ);
  CP_COMMIT();

  float oacc[16][4];
#pragma unroll
  for (int ni = 0; ni < 16; ni++)
#pragma unroll
    for (int e = 0; e < 4; e++) oacc[ni][e] = 0.f;

  float m0r = -INFINITY, m1r = -INFINITY;   // rows g, g+8 (replicated x4)
  float l0r = 0.f, l1r = 0.f;

  const float qk_scale = 0.08838834764831845f;

  for (int t = 0; t < T; t++) {
    const int k0 = t << 6;
    const uint32_t ksu = ksu0 + (t & 1) * KS_SZ * 2;
    const uint32_t vsu = vsu0 + (t & 1) * VS_SZ * 2;

    CP_WAIT3();         // K_t (and Q on t=0) ready
    __syncthreads();

    // ---- scores: 16 rows x 64 cols (8 ni tiles), k = 128 ----
    float sacc[8][4];
#pragma unroll
    for (int ni = 0; ni < 8; ni++)
#pragma unroll
      for (int e = 0; e < 4; e++) sacc[ni][e] = 0.f;

#pragma unroll
    for (int ks = 0; ks < 8; ks++) {
      const int kk = ks * 16;
      uint32_t a[4];
      uint32_t ad = qsu + ((m0 + a_lrow) * QS_STRIDE + kk + a_koff) * 2;
      LDSM4(a[0], a[1], a[2], a[3], ad);
      uint32_t bfr[8][2];
#pragma unroll
      for (int nip = 0; nip < 4; nip++) {
        uint32_t bd = ksu + ((nip * 16 + b_lrow) * KS_STRIDE + kk + b_koff) * 2;
        LDSM4(bfr[2 * nip][0], bfr[2 * nip][1], bfr[2 * nip + 1][0],
              bfr[2 * nip + 1][1], bd);
      }
#pragma unroll
      for (int ni = 0; ni < 8; ni++) MMA_F16(sacc[ni], a, bfr[ni]);
    }

    // ---- scale + causal mask (registers) ----
    const bool diag = (k0 + 63 > q0);
    const int qr0 = q0 + m0 + g, qr1 = qr0 + 8;
#pragma unroll
    for (int ni = 0; ni < 8; ni++) {
      float v0 = sacc[ni][0] * qk_scale;
      float v1 = sacc[ni][1] * qk_scale;
      float v2 = sacc[ni][2] * qk_scale;
      float v3 = sacc[ni][3] * qk_scale;
      if (diag) {
        int kc = k0 + ni * 8 + 2 * t4;
        if (kc > qr0) v0 = -1e30f;
        if (kc + 1 > qr0) v1 = -1e30f;
        if (kc > qr1) v2 = -1e30f;
        if (kc + 1 > qr1) v3 = -1e30f;
      }
      sacc[ni][0] = v0; sacc[ni][1] = v1; sacc[ni][2] = v2; sacc[ni][3] = v3;
    }

    // ---- register softmax (rows g and g+8; reduce across quad t4) ----
    float mx0 = -INFINITY, mx1 = -INFINITY;
#pragma unroll
    for (int ni = 0; ni < 8; ni++) {
      mx0 = fmaxf(mx0, fmaxf(sacc[ni][0], sacc[ni][1]));
      mx1 = fmaxf(mx1, fmaxf(sacc[ni][2], sacc[ni][3]));
    }
    mx0 = fmaxf(mx0, __shfl_xor_sync(0xffffffffu, mx0, 1));
    mx0 = fmaxf(mx0, __shfl_xor_sync(0xffffffffu, mx0, 2));
    mx1 = fmaxf(mx1, __shfl_xor_sync(0xffffffffu, mx1, 1));
    mx1 = fmaxf(mx1, __shfl_xor_sync(0xffffffffu, mx1, 2));
    const float mn0 = fmaxf(m0r, mx0);
    const float mn1 = fmaxf(m1r, mx1);

    uint32_t ph0[8], ph1[8];   // half2 P fragments, rows g / g+8
    float s0 = 0.f, s1 = 0.f;
#pragma unroll
    for (int ni = 0; ni < 8; ni++) {
      __half2 e01 = __floats2half2_rn(__expf(sacc[ni][0] - mn0),
                                      __expf(sacc[ni][1] - mn0));
      __half2 e23 = __floats2half2_rn(__expf(sacc[ni][2] - mn1),
                                      __expf(sacc[ni][3] - mn1));
      ph0[ni] = *(uint32_t*)&e01;
      ph1[ni] = *(uint32_t*)&e23;
      float2 f01 = __half22float2(e01);
      float2 f23 = __half22float2(e23);
      s0 += f01.x + f01.y;
      s1 += f23.x + f23.y;
    }
    s0 += __shfl_xor_sync(0xffffffffu, s0, 1);
    s0 += __shfl_xor_sync(0xffffffffu, s0, 2);
    s1 += __shfl_xor_sync(0xffffffffu, s1, 1);
    s1 += __shfl_xor_sync(0xffffffffu, s1, 2);
    const float al0 = __expf(m0r - mn0);   // 0 on first tile
    const float al1 = __expf(m1r - mn1);
    m0r = mn0; m1r = mn1;
    l0r = l0r * al0 + s0;
    l1r = l1r * al1 + s1;
#pragma unroll
    for (int ni = 0; ni < 16; ni++) {
      oacc[ni][0] *= al0;
      oacc[ni][1] *= al0;
      oacc[ni][2] *= al1;
      oacc[ni][3] *= al1;
    }

    // V_t ready; all warps done reading K_t before K_{t+2} overwrite
    CP_WAIT2();
    __syncthreads();

    // Prefetch K_{t+2} into this K buffer (now free)
    if (t + 2 < T) attn_issue_k(tid, kb + (size_t)(k0 + 128) * KN, 
                                Ks + (t & 1) * KS_SZ);
    CP_COMMIT();

    // ---- PV: A from registers (ph), B = V^T tiles from smem ----
#pragma unroll
    for (int ks = 0; ks < 4; ks++) {
      const int kk = ks * 16;
      uint32_t a[4];
      a[0] = ph0[2 * ks];
      a[1] = ph1[2 * ks];
      a[2] = ph0[2 * ks + 1];
      a[3] = ph1[2 * ks + 1];
      uint32_t bfr[16][2];
#pragma unroll
      for (int nip = 0; nip < 8; nip++) {
        uint32_t bd = vsu + ((nip * 16 + b_lrow) * VT_STRIDE + kk + b_koff) * 2;
        LDSM4(bfr[2 * nip][0], bfr[2 * nip][1], bfr[2 * nip + 1][0],
              bfr[2 * nip + 1][1], bd);
      }
#pragma unroll
      for (int ni = 0; ni < 16; ni++) MMA_F16(oacc[ni], a, bfr[ni]);
    }
    __syncthreads();   // all warps done reading V_t

    // Prefetch V_{t+2} into this V buffer
    if (t + 2 < T) attn_issue_v(tid, vtb + k0 + 128, Vs + (t & 1) * VS_SZ);
    CP_COMMIT();
  }

  // ---- finalize: O = half(oacc / l) ----
  {
    const float inv0 = 1.f / l0r;
    const float inv1 = 1.f / l1r;
    __half* o0 = O + (size_t)(b * S + q0 + m0 + g) * QN + h * HD + 2 * t4;
    __half* o1 = o0 + (size_t)8 * QN;
#pragma unroll
    for (int ni = 0; ni < 16; ni++) {
      *(__half2*)(o0 + ni * 8) =
          __floats2half2_rn(oacc[ni][0] * inv0, oacc[ni][1] * inv0);
      *(__half2*)(o1 + ni * 8) =
          __floats2half2_rn(oacc[ni][2] * inv1, oacc[ni][3] * inv1);
    }
  }
}

// ---------------------------------------------------------------------------
extern "C" void kernel_launch(void* const* d_in, const int* in_sizes, int n_in,
                              void* d_out, int out_size) {
  const float* x  = (const float*)d_in[0];
  const float* Wq = (const float*)d_in[1];
  const float* Wk = (const float*)d_in[2];
  const float* Wv = (const float*)d_in[3];
  const float* Wo = (const float*)d_in[4];
  float* out = (float*)d_out;

  __half *xh, *wqT, *wkT, *wvT, *woT, *qh, *kh, *vT, *attnh;
  cudaGetSymbolAddress((void**)&xh, g_xh);
  cudaGetSymbolAddress((void**)&wqT, g_wqT);
  cudaGetSymbolAddress((void**)&wkT, g_wkT);
  cudaGetSymbolAddress((void**)&wvT, g_wvT);
  cudaGetSymbolAddress((void**)&woT, g_woT);
  cudaGetSymbolAddress((void**)&qh, g_qh);
  cudaGetSymbolAddress((void**)&kh, g_kh);
  cudaGetSymbolAddress((void**)&vT, g_vT);
  cudaGetSymbolAddress((void**)&attnh, g_attnh);

  cudaFuncSetAttribute(qkv_gemm, cudaFuncAttributeMaxDynamicSharedMemorySize,
                       GEMM_SMEM_BYTES);
  cudaFuncSetAttribute(o_gemm, cudaFuncAttributeMaxDynamicSharedMemorySize,
                       GEMM_SMEM_BYTES);
  cudaFuncSetAttribute(attn_kernel, cudaFuncAttributeMaxDynamicSharedMemorySize,
                       ATTN_SMEM_BYTES);

  conv_half<<<(M_ROWS * D / 4 + 255) / 256, 256>>>(x, xh, M_ROWS * D / 4);
  transpose_all<<<dim3(64, 64, 4), dim3(32, 8)>>>(Wq, Wk, Wv, Wo,
                                                  wqT, wkT, wvT, woT);

  dim3 blk(256);
  qkv_gemm<<<dim3(24, M_ROWS / 256), blk, GEMM_SMEM_BYTES>>>(xh, wqT, wkT, wvT,
                                                             qh, kh, vT);
  rope_kernel<<<B * S * (H + HKV) / 4, blk>>>(qh, kh);
  attn_kernel<<<dim3(S / 128, B * H), blk, ATTN_SMEM_BYTES>>>(qh, kh, vT, attnh);
  o_gemm<<<dim3(D / 128, M_ROWS / 256), blk, GEMM_SMEM_BYTES>>>(attnh, woT, out);
}

// round 10
// speedup vs baseline: 5.8680x; 1.0285x over previous
#include <cuda_runtime.h>
#include <cuda_fp16.h>
#include <math.h>
#include <stdint.h>

#define B 2
#define S 2048
#define D 2048
#define H 16
#define HKV 4
#define HD 128
#define M_ROWS (B*S)     // 4096
#define QN (H*HD)        // 2048
#define KN (HKV*HD)      // 512

// Scratch (allocation-free: device globals), fp16 operands everywhere
__device__ __half g_xh[(size_t)M_ROWS * D];
__device__ __half g_wqT[(size_t)QN * D];    // [N][K]
__device__ __half g_wkT[(size_t)KN * D];
__device__ __half g_wvT[(size_t)KN * D];
__device__ __half g_woT[(size_t)D * QN];
__device__ __half g_qh[(size_t)M_ROWS * QN];
__device__ __half g_kh[(size_t)M_ROWS * KN];
__device__ __half g_vT[(size_t)B * HKV * HD * S];  // [b][hk][d][s]
__device__ __half g_attnh[(size_t)M_ROWS * QN];

#define MMA_F16(c, a, b)                                                      \
  asm("mma.sync.aligned.m16n8k16.row.col.f32.f16.f16.f32 "                    \
      "{%0,%1,%2,%3},{%4,%5,%6,%7},{%8,%9},{%0,%1,%2,%3};"                    \
      : "+f"(c[0]), "+f"(c[1]), "+f"(c[2]), "+f"(c[3])                        \
      : "r"(a[0]), "r"(a[1]), "r"(a[2]), "r"(a[3]), "r"(b[0]), "r"(b[1]))

#define LDSM4(r0, r1, r2, r3, addr)                                           \
  asm volatile("ldmatrix.sync.aligned.m8n8.x4.shared.b16 {%0,%1,%2,%3}, [%4];"\
               : "=r"(r0), "=r"(r1), "=r"(r2), "=r"(r3) : "r"(addr))

#define CP16(dst, src)                                                        \
  asm volatile("cp.async.cg.shared.global [%0], [%1], 16;" ::"r"(dst), "l"(src))
#define CP_COMMIT() asm volatile("cp.async.commit_group;")
#define CP_WAIT1()  asm volatile("cp.async.wait_group 1;")
#define CP_WAIT2()  asm volatile("cp.async.wait_group 2;")
#define CP_WAIT3()  asm volatile("cp.async.wait_group 3;")

// ---------------------------------------------------------------------------
// fp32 -> fp16 convert (x), batched tiled transpose+convert (all 4 weights)
// ---------------------------------------------------------------------------
__global__ void conv_half(const float* __restrict__ src,
                          __half* __restrict__ dst, int n4) {
  int i = blockIdx.x * blockDim.x + threadIdx.x;
  if (i < n4) {
    float4 v = *(const float4*)(src + 4 * (size_t)i);
    *(__half2*)(dst + 4 * (size_t)i) = __floats2half2_rn(v.x, v.y);
    *(__half2*)(dst + 4 * (size_t)i + 2) = __floats2half2_rn(v.z, v.w);
  }
}

__global__ void transpose_all(const float* __restrict__ Wq,
                              const float* __restrict__ Wk,
                              const float* __restrict__ Wv,
                              const float* __restrict__ Wo,
                              __half* __restrict__ wqT, __half* __restrict__ wkT,
                              __half* __restrict__ wvT, __half* __restrict__ woT) {
  __shared__ float t[32][33];
  const float* src;
  __half* dst;
  int R, C;
  switch (blockIdx.z) {
    case 0: src = Wq; dst = wqT; R = D;  C = QN; break;
    case 1: src = Wk; dst = wkT; R = D;  C = KN; break;
    case 2: src = Wv; dst = wvT; R = D;  C = KN; break;
    default: src = Wo; dst = woT; R = QN; C = D;  break;
  }
  int c0 = blockIdx.x * 32, r0 = blockIdx.y * 32;
  if (c0 >= C || r0 >= R) return;
  int x = threadIdx.x, y = threadIdx.y;
#pragma unroll
  for (int i = 0; i < 32; i += 8)
    t[y + i][x] = src[(size_t)(r0 + y + i) * C + c0 + x];
  __syncthreads();
#pragma unroll
  for (int i = 0; i < 32; i += 8)
    dst[(size_t)(c0 + y + i) * R + r0 + x] = __float2half_rn(t[x][y + i]);
}

// ---------------------------------------------------------------------------
// fp16 MMA GEMM: 256x128x32 block tile, 3-buffer single-barrier cp.async
// pipeline, ldmatrix fragments, 8 warps (4M x 2N), warp 64x64.
// Epilogues: 0 half, 1 V^T half, 2 fp32.
// ---------------------------------------------------------------------------
#define AS_STRIDE 40
#define BS_STRIDE 40
#define AS_SZ (256 * AS_STRIDE)
#define BS_SZ (128 * BS_STRIDE)
#define GEMM_SMEM_BYTES (3 * (AS_SZ + BS_SZ) * 2)

__device__ __forceinline__ void gemm_issue_slab(
    int tid, const __half* __restrict__ A, const __half* __restrict__ BT,
    int K, int row0, int col0, int k0, __half* as, __half* bs) {
#pragma unroll
  for (int l = 0; l < 4; l++) {
    int idx = tid + l * 256;
    int ar = idx >> 2, ac = (idx & 3) << 3;
    const __half* asrc = A + (size_t)(row0 + ar) * K + k0 + ac;
    uint32_t adst = (uint32_t)__cvta_generic_to_shared(as + ar * AS_STRIDE + ac);
    CP16(adst, asrc);
  }
#pragma unroll
  for (int l = 0; l < 2; l++) {
    int idx = tid + l * 256;
    int br = idx >> 2, bc = (idx & 3) << 3;
    const __half* bsrc = BT + (size_t)(col0 + br) * K + k0 + bc;
    uint32_t bdst = (uint32_t)__cvta_generic_to_shared(bs + br * BS_STRIDE + bc);
    CP16(bdst, bsrc);
  }
}

template <int MODE>
__device__ __forceinline__ void gemm_body(
    const __half* __restrict__ A, const __half* __restrict__ BT,
    void* __restrict__ Cv, int N, int K, int row0, int col0, __half* smp,
    int vb_base) {
  __half* As = smp;                 // 3 x [256][40]
  __half* Bs = smp + 3 * AS_SZ;     // 3 x [128][40]

  const int tid = threadIdx.x;
  const int lane = tid & 31;
  const int w = tid >> 5;
  const int g = lane >> 2;
  const int t4 = lane & 3;
  const int warp_m = w & 3, warp_n = w >> 2;
  const int m0w = warp_m * 64, n0w = warp_n * 64;

  const int a_lrow = (lane & 7) + ((lane >> 3) & 1) * 8;
  const int a_koff = (lane >> 4) * 8;
  const int b_lrow = (lane & 7) + (lane >> 4) * 8;
  const int b_koff = ((lane >> 3) & 1) * 8;

  float acc[4][8][4];
#pragma unroll
  for (int mi = 0; mi < 4; mi++)
#pragma unroll
    for (int ni = 0; ni < 8; ni++)
#pragma unroll
      for (int e = 0; e < 4; e++) acc[mi][ni][e] = 0.f;

  gemm_issue_slab(tid, A, BT, K, row0, col0, 0, As, Bs);
  CP_COMMIT();
  gemm_issue_slab(tid, A, BT, K, row0, col0, 32, As + AS_SZ, Bs + BS_SZ);
  CP_COMMIT();

  const uint32_t asu0 = (uint32_t)__cvta_generic_to_shared(As);
  const uint32_t bsu0 = (uint32_t)__cvta_generic_to_shared(Bs);

  const int nslab = K >> 5;
  for (int it = 0; it < nslab; it++) {
    CP_WAIT1();           // slab it's fill complete (this thread's groups)
    __syncthreads();      // all fills visible; all warps done with it-1
    // refill buf (it+2)%3 == (it-1)%3 (freed by the barrier above)
    int kn = it + 2;
    if (kn < nslab)
      gemm_issue_slab(tid, A, BT, K, row0, col0, kn << 5,
                      As + (kn % 3) * AS_SZ, Bs + (kn % 3) * BS_SZ);
    CP_COMMIT();

    const uint32_t asu = asu0 + (it % 3) * AS_SZ * 2;
    const uint32_t bsu = bsu0 + (it % 3) * BS_SZ * 2;
#pragma unroll
    for (int ks = 0; ks < 2; ks++) {
      const int kk = ks * 16;
      uint32_t a[4][4];
#pragma unroll
      for (int mi = 0; mi < 4; mi++) {
        uint32_t ad = asu +
            ((m0w + mi * 16 + a_lrow) * AS_STRIDE + kk + a_koff) * 2;
        LDSM4(a[mi][0], a[mi][1], a[mi][2], a[mi][3], ad);
      }
      uint32_t b[8][2];
#pragma unroll
      for (int nip = 0; nip < 4; nip++) {
        uint32_t bd = bsu +
            ((n0w + nip * 16 + b_lrow) * BS_STRIDE + kk + b_koff) * 2;
        LDSM4(b[2 * nip][0], b[2 * nip][1], b[2 * nip + 1][0],
              b[2 * nip + 1][1], bd);
      }
#pragma unroll
      for (int mi = 0; mi < 4; mi++)
#pragma unroll
        for (int ni = 0; ni < 8; ni++) MMA_F16(acc[mi][ni], a[mi], b[ni]);
    }
  }

#pragma unroll
  for (int mi = 0; mi < 4; mi++) {
    int r0 = row0 + m0w + mi * 16 + g;
#pragma unroll
    for (int ni = 0; ni < 8; ni++) {
      int col = col0 + n0w + ni * 8 + 2 * t4;
      if (MODE == 0) {
        __half* C = (__half*)Cv;
        *(__half2*)(C + (size_t)r0 * N + col) =
            __floats2half2_rn(acc[mi][ni][0], acc[mi][ni][1]);
        *(__half2*)(C + (size_t)(r0 + 8) * N + col) =
            __floats2half2_rn(acc[mi][ni][2], acc[mi][ni][3]);
      } else if (MODE == 1) {
        __half* C = (__half*)Cv;
        int s0 = r0 & (S - 1);
        int b0 = r0 >> 11;
        int d = col & (HD - 1);
        __half* base = C + ((size_t)(b0 * HKV) + vb_base) * HD * S;
        base[(size_t)d * S + s0] = __float2half_rn(acc[mi][ni][0]);
        base[(size_t)(d + 1) * S + s0] = __float2half_rn(acc[mi][ni][1]);
        base[(size_t)d * S + s0 + 8] = __float2half_rn(acc[mi][ni][2]);
        base[(size_t)(d + 1) * S + s0 + 8] = __float2half_rn(acc[mi][ni][3]);
      } else {
        float* C = (float*)Cv;
        *(float2*)(C + (size_t)r0 * N + col) =
            make_float2(acc[mi][ni][0], acc[mi][ni][1]);
        *(float2*)(C + (size_t)(r0 + 8) * N + col) =
            make_float2(acc[mi][ni][2], acc[mi][ni][3]);
      }
    }
  }
}

__global__ void __launch_bounds__(256, 1)
qkv_gemm(const __half* __restrict__ xh, const __half* __restrict__ wqT,
         const __half* __restrict__ wkT, const __half* __restrict__ wvT,
         __half* __restrict__ q, __half* __restrict__ k,
         __half* __restrict__ vT) {
  extern __shared__ __half smp[];
  const int bx = blockIdx.x;
  const int row0 = blockIdx.y * 256;
  if (bx < 16) {
    gemm_body<0>(xh, wqT, q, QN, D, row0, bx * 128, smp, 0);
  } else if (bx < 20) {
    gemm_body<0>(xh, wkT, k, KN, D, row0, (bx - 16) * 128, smp, 0);
  } else {
    int col0 = (bx - 20) * 128;
    gemm_body<1>(xh, wvT, vT, KN, D, row0, col0, smp, col0 >> 7);
  }
}

__global__ void __launch_bounds__(256, 1)
o_gemm(const __half* __restrict__ attnh, const __half* __restrict__ woT,
       float* __restrict__ out) {
  extern __shared__ __half smp[];
  gemm_body<2>(attnh, woT, out, D, QN, blockIdx.y * 256, blockIdx.x * 128, smp, 0);
}

// ---------------------------------------------------------------------------
// RoPE (unchanged)
// ---------------------------------------------------------------------------
__global__ void __launch_bounds__(256)
rope_kernel(__half* __restrict__ q, __half* __restrict__ k) {
  const int row = blockIdx.x * 4 + (threadIdx.x >> 6);
  const int nh = H + HKV;
  const int bs = row / nh;
  const int hh = row - bs * nh;
  const int s = bs & (S - 1);
  __half* p = (hh < H) ? (q + (size_t)bs * QN + hh * HD)
                       : (k + (size_t)bs * KN + (hh - H) * HD);
  const int j = threadIdx.x & 63;
  const float x1 = __half2float(p[2 * j]);
  const float x2 = __half2float(p[2 * j + 1]);
  const float theta = exp2f(-(float)j * 0.20762050593045983f);
  const float ang = (float)s * theta;
  float sn, cs;
  sincosf(ang, &sn, &cs);
  __syncthreads();
  p[j] = __float2half_rn(x1 * cs - x2 * sn);
  p[j + 64] = __float2half_rn(x1 * sn + x2 * cs);
}

// ---------------------------------------------------------------------------
// Flash attention: FA2 register softmax, k-tile = 128 cols (halved softmax /
// barrier overhead vs 64). 8 warps x 16 q-rows. Double-buffered K/V.
// ---------------------------------------------------------------------------
#define QS_STRIDE 136
#define KS_STRIDE 136
#define VT_STRIDE 136
#define KS_SZ (128 * KS_STRIDE)
#define VS_SZ (128 * VT_STRIDE)
#define ATTN_SMEM_BYTES ((128 * QS_STRIDE + 2 * KS_SZ + 2 * VS_SZ) * 2)

__device__ __forceinline__ void attn_issue_k(int tid, const __half* src,
                                             __half* dst) {
#pragma unroll
  for (int i = 0; i < 8; i++) {
    int idx = tid + i * 256;
    int n = idx >> 4, c8 = (idx & 15) << 3;
    uint32_t d = (uint32_t)__cvta_generic_to_shared(dst + n * KS_STRIDE + c8);
    CP16(d, src + (size_t)n * KN + c8);
  }
}
// V^T tile: 128 d-rows x 128 s-cols
__device__ __forceinline__ void attn_issue_v(int tid, const __half* src,
                                             __half* dst) {
#pragma unroll
  for (int i = 0; i < 8; i++) {
    int idx = tid + i * 256;
    int dd = idx >> 4, c8 = (idx & 15) << 3;
    uint32_t d = (uint32_t)__cvta_generic_to_shared(dst + dd * VT_STRIDE + c8);
    CP16(d, src + (size_t)dd * S + c8);
  }
}

__global__ void __launch_bounds__(256, 1)
attn_kernel(const __half* __restrict__ Q, const __half* __restrict__ K,
            const __half* __restrict__ VT, __half* __restrict__ O) {
  extern __shared__ __half smh[];
  __half* Qs = smh;                      // [128][136]
  __half* Ks = Qs + 128 * QS_STRIDE;     // 2 x [128][136]
  __half* Vs = Ks + 2 * KS_SZ;           // 2 x [128][136]

  const int tid = threadIdx.x;
  const int lane = tid & 31;
  const int w = tid >> 5;
  const int g = lane >> 2;
  const int t4 = lane & 3;
  const int m0 = w * 16;

  const int a_lrow = (lane & 7) + ((lane >> 3) & 1) * 8;
  const int a_koff = (lane >> 4) * 8;
  const int b_lrow = (lane & 7) + (lane >> 4) * 8;
  const int b_koff = ((lane >> 3) & 1) * 8;

  const uint32_t qsu = (uint32_t)__cvta_generic_to_shared(Qs);
  const uint32_t ksu0 = (uint32_t)__cvta_generic_to_shared(Ks);
  const uint32_t vsu0 = (uint32_t)__cvta_generic_to_shared(Vs);

  const int qi = (int)gridDim.x - 1 - (int)blockIdx.x;
  const int bh = blockIdx.y;
  const int b = bh >> 4;
  const int h = bh & 15;
  const int hk = h >> 2;
  const int q0 = qi * 128;

  const __half* qb = Q + (size_t)b * S * QN + h * HD;
  const __half* kb = K + (size_t)b * S * KN + hk * HD;
  const __half* vtb = VT + ((size_t)(b * HKV + hk)) * HD * S;

  const int T = qi + 1;

  // Prologue groups: G1 = Q + K0, G2 = V0, G3 = K1, G4 = V1
  // (tile-1 loads read valid memory even when T == 1; data unused)
#pragma unroll
  for (int i = 0; i < 8; i++) {
    int idx = tid + i * 256;
    int r = idx >> 4, c8 = (idx & 15) << 3;
    uint32_t d = (uint32_t)__cvta_generic_to_shared(Qs + r * QS_STRIDE + c8);
    CP16(d, qb + (size_t)(q0 + r) * QN + c8);
  }
  attn_issue_k(tid, kb, Ks);
  CP_COMMIT();
  attn_issue_v(tid, vtb, Vs);
  CP_COMMIT();
  attn_issue_k(tid, kb + (size_t)128 * KN, Ks + KS_SZ);
  CP_COMMIT();
  attn_issue_v(tid, vtb + 128, Vs + VS_SZ);
  CP_COMMIT();

  float oacc[16][4];
#pragma unroll
  for (int ni = 0; ni < 16; ni++)
#pragma unroll
    for (int e = 0; e < 4; e++) oacc[ni][e] = 0.f;

  float m0r = -INFINITY, m1r = -INFINITY;
  float l0r = 0.f, l1r = 0.f;

  const float qk_scale = 0.08838834764831845f;

  for (int t = 0; t < T; t++) {
    const int k0 = t << 7;
    const uint32_t ksu = ksu0 + (t & 1) * KS_SZ * 2;
    const uint32_t vsu = vsu0 + (t & 1) * VS_SZ * 2;

    CP_WAIT3();         // K_t (and Q on t=0) ready
    __syncthreads();

    // ---- scores: 16 rows x 128 cols (16 ni tiles), k = 128 ----
    float sacc[16][4];
#pragma unroll
    for (int ni = 0; ni < 16; ni++)
#pragma unroll
      for (int e = 0; e < 4; e++) sacc[ni][e] = 0.f;

#pragma unroll
    for (int ks = 0; ks < 8; ks++) {
      const int kk = ks * 16;
      uint32_t a[4];
      uint32_t ad = qsu + ((m0 + a_lrow) * QS_STRIDE + kk + a_koff) * 2;
      LDSM4(a[0], a[1], a[2], a[3], ad);
      uint32_t bfr[16][2];
#pragma unroll
      for (int nip = 0; nip < 8; nip++) {
        uint32_t bd = ksu + ((nip * 16 + b_lrow) * KS_STRIDE + kk + b_koff) * 2;
        LDSM4(bfr[2 * nip][0], bfr[2 * nip][1], bfr[2 * nip + 1][0],
              bfr[2 * nip + 1][1], bd);
      }
#pragma unroll
      for (int ni = 0; ni < 16; ni++) MMA_F16(sacc[ni], a, bfr[ni]);
    }

    // ---- scale + causal mask (registers) ----
    const bool diag = (k0 + 127 > q0);
    const int qr0 = q0 + m0 + g, qr1 = qr0 + 8;
#pragma unroll
    for (int ni = 0; ni < 16; ni++) {
      float v0 = sacc[ni][0] * qk_scale;
      float v1 = sacc[ni][1] * qk_scale;
      float v2 = sacc[ni][2] * qk_scale;
      float v3 = sacc[ni][3] * qk_scale;
      if (diag) {
        int kc = k0 + ni * 8 + 2 * t4;
        if (kc > qr0) v0 = -1e30f;
        if (kc + 1 > qr0) v1 = -1e30f;
        if (kc > qr1) v2 = -1e30f;
        if (kc + 1 > qr1) v3 = -1e30f;
      }
      sacc[ni][0] = v0; sacc[ni][1] = v1; sacc[ni][2] = v2; sacc[ni][3] = v3;
    }

    // ---- register softmax (rows g and g+8; reduce across quad t4) ----
    float mx0 = -INFINITY, mx1 = -INFINITY;
#pragma unroll
    for (int ni = 0; ni < 16; ni++) {
      mx0 = fmaxf(mx0, fmaxf(sacc[ni][0], sacc[ni][1]));
      mx1 = fmaxf(mx1, fmaxf(sacc[ni][2], sacc[ni][3]));
    }
    mx0 = fmaxf(mx0, __shfl_xor_sync(0xffffffffu, mx0, 1));
    mx0 = fmaxf(mx0, __shfl_xor_sync(0xffffffffu, mx0, 2));
    mx1 = fmaxf(mx1, __shfl_xor_sync(0xffffffffu, mx1, 1));
    mx1 = fmaxf(mx1, __shfl_xor_sync(0xffffffffu, mx1, 2));
    const float mn0 = fmaxf(m0r, mx0);
    const float mn1 = fmaxf(m1r, mx1);

    uint32_t ph0[16], ph1[16];
    float s0 = 0.f, s1 = 0.f;
#pragma unroll
    for (int ni = 0; ni < 16; ni++) {
      __half2 e01 = __floats2half2_rn(__expf(sacc[ni][0] - mn0),
                                      __expf(sacc[ni][1] - mn0));
      __half2 e23 = __floats2half2_rn(__expf(sacc[ni][2] - mn1),
                                      __expf(sacc[ni][3] - mn1));
      ph0[ni] = *(uint32_t*)&e01;
      ph1[ni] = *(uint32_t*)&e23;
      float2 f01 = __half22float2(e01);
      float2 f23 = __half22float2(e23);
      s0 += f01.x + f01.y;
      s1 += f23.x + f23.y;
    }
    s0 += __shfl_xor_sync(0xffffffffu, s0, 1);
    s0 += __shfl_xor_sync(0xffffffffu, s0, 2);
    s1 += __shfl_xor_sync(0xffffffffu, s1, 1);
    s1 += __shfl_xor_sync(0xffffffffu, s1, 2);
    const float al0 = __expf(m0r - mn0);
    const float al1 = __expf(m1r - mn1);
    m0r = mn0; m1r = mn1;
    l0r = l0r * al0 + s0;
    l1r = l1r * al1 + s1;
#pragma unroll
    for (int ni = 0; ni < 16; ni++) {
      oacc[ni][0] *= al0;
      oacc[ni][1] *= al0;
      oacc[ni][2] *= al1;
      oacc[ni][3] *= al1;
    }

    CP_WAIT2();         // V_t ready
    __syncthreads();    // everyone done reading K_t

    // Prefetch K_{t+2} into the K buffer just freed
    if (t + 2 < T) attn_issue_k(tid, kb + (size_t)(k0 + 256) * KN,
                                Ks + (t & 1) * KS_SZ);
    CP_COMMIT();

    // ---- PV: A from registers (ph), B = V^T tiles from smem, k = 128 ----
#pragma unroll
    for (int ks = 0; ks < 8; ks++) {
      const int kk = ks * 16;
      uint32_t a[4];
      a[0] = ph0[2 * ks];
      a[1] = ph1[2 * ks];
      a[2] = ph0[2 * ks + 1];
      a[3] = ph1[2 * ks + 1];
      uint32_t bfr[16][2];
#pragma unroll
      for (int nip = 0; nip < 8; nip++) {
        uint32_t bd = vsu + ((nip * 16 + b_lrow) * VT_STRIDE + kk + b_koff) * 2;
        LDSM4(bfr[2 * nip][0], bfr[2 * nip][1], bfr[2 * nip + 1][0],
              bfr[2 * nip + 1][1], bd);
      }
#pragma unroll
      for (int ni = 0; ni < 16; ni++) MMA_F16(oacc[ni], a, bfr[ni]);
    }
    __syncthreads();    // everyone done reading V_t

    // Prefetch V_{t+2} into the V buffer just freed
    if (t + 2 < T) attn_issue_v(tid, vtb + k0 + 256, Vs + (t & 1) * VS_SZ);
    CP_COMMIT();
  }

  // ---- finalize: O = half(oacc / l) ----
  {
    const float inv0 = 1.f / l0r;
    const float inv1 = 1.f / l1r;
    __half* o0 = O + (size_t)(b * S + q0 + m0 + g) * QN + h * HD + 2 * t4;
    __half* o1 = o0 + (size_t)8 * QN;
#pragma unroll
    for (int ni = 0; ni < 16; ni++) {
      *(__half2*)(o0 + ni * 8) =
          __floats2half2_rn(oacc[ni][0] * inv0, oacc[ni][1] * inv0);
      *(__half2*)(o1 + ni * 8) =
          __floats2half2_rn(oacc[ni][2] * inv1, oacc[ni][3] * inv1);
    }
  }
}

// ---------------------------------------------------------------------------
extern "C" void kernel_launch(void* const* d_in, const int* in_sizes, int n_in,
                              void* d_out, int out_size) {
  const float* x  = (const float*)d_in[0];
  const float* Wq = (const float*)d_in[1];
  const float* Wk = (const float*)d_in[2];
  const float* Wv = (const float*)d_in[3];
  const float* Wo = (const float*)d_in[4];
  float* out = (float*)d_out;

  __half *xh, *wqT, *wkT, *wvT, *woT, *qh, *kh, *vT, *attnh;
  cudaGetSymbolAddress((void**)&xh, g_xh);
  cudaGetSymbolAddress((void**)&wqT, g_wqT);
  cudaGetSymbolAddress((void**)&wkT, g_wkT);
  cudaGetSymbolAddress((void**)&wvT, g_wvT);
  cudaGetSymbolAddress((void**)&woT, g_woT);
  cudaGetSymbolAddress((void**)&qh, g_qh);
  cudaGetSymbolAddress((void**)&kh, g_kh);
  cudaGetSymbolAddress((void**)&vT, g_vT);
  cudaGetSymbolAddress((void**)&attnh, g_attnh);

  cudaFuncSetAttribute(qkv_gemm, cudaFuncAttributeMaxDynamicSharedMemorySize,
                       GEMM_SMEM_BYTES);
  cudaFuncSetAttribute(o_gemm, cudaFuncAttributeMaxDynamicSharedMemorySize,
                       GEMM_SMEM_BYTES);
  cudaFuncSetAttribute(attn_kernel, cudaFuncAttributeMaxDynamicSharedMemorySize,
                       ATTN_SMEM_BYTES);

  conv_half<<<(M_ROWS * D / 4 + 255) / 256, 256>>>(x, xh, M_ROWS * D / 4);
  transpose_all<<<dim3(64, 64, 4), dim3(32, 8)>>>(Wq, Wk, Wv, Wo,
                                                  wqT, wkT, wvT, woT);

  dim3 blk(256);
  qkv_gemm<<<dim3(24, M_ROWS / 256), blk, GEMM_SMEM_BYTES>>>(xh, wqT, wkT, wvT,
                                                             qh, kh, vT);
  rope_kernel<<<B * S * (H + HKV) / 4, blk>>>(qh, kh);
  attn_kernel<<<dim3(S / 128, B * H), blk, ATTN_SMEM_BYTES>>>(qh, kh, vT, attnh);
  o_gemm<<<dim3(D / 128, M_ROWS / 256), blk, GEMM_SMEM_BYTES>>>(attnh, woT, out);
}

// round 11
// speedup vs baseline: 6.8189x; 1.1620x over previous
#include <cuda_runtime.h>
#include <cuda_fp16.h>
#include <math.h>
#include <stdint.h>

#define B 2
#define S 2048
#define D 2048
#define H 16
#define HKV 4
#define HD 128
#define M_ROWS (B*S)     // 4096
#define QN (H*HD)        // 2048
#define KN (HKV*HD)      // 512

// Scratch (allocation-free: device globals), fp16 operands everywhere
__device__ __half g_xh[(size_t)M_ROWS * D];
__device__ __half g_wqT[(size_t)QN * D];    // [N][K]
__device__ __half g_wkT[(size_t)KN * D];
__device__ __half g_wvT[(size_t)KN * D];
__device__ __half g_woT[(size_t)D * QN];
__device__ __half g_qh[(size_t)M_ROWS * QN];
__device__ __half g_kh[(size_t)M_ROWS * KN];
__device__ __half g_vT[(size_t)B * HKV * HD * S];  // [b][hk][d][s]
__device__ __half g_attnh[(size_t)M_ROWS * QN];

#define MMA_F16(c, a, b)                                                      \
  asm("mma.sync.aligned.m16n8k16.row.col.f32.f16.f16.f32 "                    \
      "{%0,%1,%2,%3},{%4,%5,%6,%7},{%8,%9},{%0,%1,%2,%3};"                    \
      : "+f"(c[0]), "+f"(c[1]), "+f"(c[2]), "+f"(c[3])                        \
      : "r"(a[0]), "r"(a[1]), "r"(a[2]), "r"(a[3]), "r"(b[0]), "r"(b[1]))

#define LDSM4(r0, r1, r2, r3, addr)                                           \
  asm volatile("ldmatrix.sync.aligned.m8n8.x4.shared.b16 {%0,%1,%2,%3}, [%4];"\
               : "=r"(r0), "=r"(r1), "=r"(r2), "=r"(r3) : "r"(addr))

#define CP16(dst, src)                                                        \
  asm volatile("cp.async.cg.shared.global [%0], [%1], 16;" ::"r"(dst), "l"(src))
#define CP_COMMIT() asm volatile("cp.async.commit_group;")
#define CP_WAIT1()  asm volatile("cp.async.wait_group 1;")
#define CP_WAIT2()  asm volatile("cp.async.wait_group 2;")
#define CP_WAIT3()  asm volatile("cp.async.wait_group 3;")

// ---------------------------------------------------------------------------
// fp32 -> fp16 convert (x), batched tiled transpose+convert (all 4 weights)
// ---------------------------------------------------------------------------
__global__ void conv_half(const float* __restrict__ src,
                          __half* __restrict__ dst, int n4) {
  int i = blockIdx.x * blockDim.x + threadIdx.x;
  if (i < n4) {
    float4 v = *(const float4*)(src + 4 * (size_t)i);
    *(__half2*)(dst + 4 * (size_t)i) = __floats2half2_rn(v.x, v.y);
    *(__half2*)(dst + 4 * (size_t)i + 2) = __floats2half2_rn(v.z, v.w);
  }
}

__global__ void transpose_all(const float* __restrict__ Wq,
                              const float* __restrict__ Wk,
                              const float* __restrict__ Wv,
                              const float* __restrict__ Wo,
                              __half* __restrict__ wqT, __half* __restrict__ wkT,
                              __half* __restrict__ wvT, __half* __restrict__ woT) {
  __shared__ float t[32][33];
  const float* src;
  __half* dst;
  int R, C;
  switch (blockIdx.z) {
    case 0: src = Wq; dst = wqT; R = D;  C = QN; break;
    case 1: src = Wk; dst = wkT; R = D;  C = KN; break;
    case 2: src = Wv; dst = wvT; R = D;  C = KN; break;
    default: src = Wo; dst = woT; R = QN; C = D;  break;
  }
  int c0 = blockIdx.x * 32, r0 = blockIdx.y * 32;
  if (c0 >= C || r0 >= R) return;
  int x = threadIdx.x, y = threadIdx.y;
#pragma unroll
  for (int i = 0; i < 32; i += 8)
    t[y + i][x] = src[(size_t)(r0 + y + i) * C + c0 + x];
  __syncthreads();
#pragma unroll
  for (int i = 0; i < 32; i += 8)
    dst[(size_t)(c0 + y + i) * R + r0 + x] = __float2half_rn(t[x][y + i]);
}

// ---------------------------------------------------------------------------
// fp16 MMA GEMM: 128x128x32 block tile, 128 threads (4 warps, warp 64x64),
// 3-buffer single-barrier cp.async pipeline, ldmatrix fragments.
// 61 KB smem -> 2 CTAs/SM (4 warps/SMSP) for latency hiding.
// Epilogues: 0 half, 1 V^T half, 2 fp32.
// ---------------------------------------------------------------------------
#define AS_STRIDE 40
#define BS_STRIDE 40
#define AS_SZ (128 * AS_STRIDE)
#define BS_SZ (128 * BS_STRIDE)
#define GEMM_SMEM_BYTES (3 * (AS_SZ + BS_SZ) * 2)

__device__ __forceinline__ void gemm_issue_slab(
    int tid, const __half* __restrict__ A, const __half* __restrict__ BT,
    int K, int row0, int col0, int k0, __half* as, __half* bs) {
#pragma unroll
  for (int l = 0; l < 4; l++) {
    int idx = tid + l * 128;
    int ar = idx >> 2, ac = (idx & 3) << 3;
    const __half* asrc = A + (size_t)(row0 + ar) * K + k0 + ac;
    uint32_t adst = (uint32_t)__cvta_generic_to_shared(as + ar * AS_STRIDE + ac);
    CP16(adst, asrc);
  }
#pragma unroll
  for (int l = 0; l < 4; l++) {
    int idx = tid + l * 128;
    int br = idx >> 2, bc = (idx & 3) << 3;
    const __half* bsrc = BT + (size_t)(col0 + br) * K + k0 + bc;
    uint32_t bdst = (uint32_t)__cvta_generic_to_shared(bs + br * BS_STRIDE + bc);
    CP16(bdst, bsrc);
  }
}

template <int MODE>
__device__ __forceinline__ void gemm_body(
    const __half* __restrict__ A, const __half* __restrict__ BT,
    void* __restrict__ Cv, int N, int K, int row0, int col0, __half* smp,
    int vb_base) {
  __half* As = smp;                 // 3 x [128][40]
  __half* Bs = smp + 3 * AS_SZ;     // 3 x [128][40]

  const int tid = threadIdx.x;
  const int lane = tid & 31;
  const int w = tid >> 5;
  const int g = lane >> 2;
  const int t4 = lane & 3;
  const int warp_m = w & 1, warp_n = w >> 1;
  const int m0w = warp_m * 64, n0w = warp_n * 64;

  const int a_lrow = (lane & 7) + ((lane >> 3) & 1) * 8;
  const int a_koff = (lane >> 4) * 8;
  const int b_lrow = (lane & 7) + (lane >> 4) * 8;
  const int b_koff = ((lane >> 3) & 1) * 8;

  float acc[4][8][4];
#pragma unroll
  for (int mi = 0; mi < 4; mi++)
#pragma unroll
    for (int ni = 0; ni < 8; ni++)
#pragma unroll
      for (int e = 0; e < 4; e++) acc[mi][ni][e] = 0.f;

  gemm_issue_slab(tid, A, BT, K, row0, col0, 0, As, Bs);
  CP_COMMIT();
  gemm_issue_slab(tid, A, BT, K, row0, col0, 32, As + AS_SZ, Bs + BS_SZ);
  CP_COMMIT();

  const uint32_t asu0 = (uint32_t)__cvta_generic_to_shared(As);
  const uint32_t bsu0 = (uint32_t)__cvta_generic_to_shared(Bs);

  const int nslab = K >> 5;
  for (int it = 0; it < nslab; it++) {
    CP_WAIT1();           // slab it's fill complete (this thread's groups)
    __syncthreads();      // all fills visible; all warps done with it-1
    // refill buf (it+2)%3 == (it-1)%3 (freed by the barrier above)
    int kn = it + 2;
    if (kn < nslab)
      gemm_issue_slab(tid, A, BT, K, row0, col0, kn << 5,
                      As + (kn % 3) * AS_SZ, Bs + (kn % 3) * BS_SZ);
    CP_COMMIT();

    const uint32_t asu = asu0 + (it % 3) * AS_SZ * 2;
    const uint32_t bsu = bsu0 + (it % 3) * BS_SZ * 2;
#pragma unroll
    for (int ks = 0; ks < 2; ks++) {
      const int kk = ks * 16;
      uint32_t a[4][4];
#pragma unroll
      for (int mi = 0; mi < 4; mi++) {
        uint32_t ad = asu +
            ((m0w + mi * 16 + a_lrow) * AS_STRIDE + kk + a_koff) * 2;
        LDSM4(a[mi][0], a[mi][1], a[mi][2], a[mi][3], ad);
      }
      uint32_t b[8][2];
#pragma unroll
      for (int nip = 0; nip < 4; nip++) {
        uint32_t bd = bsu +
            ((n0w + nip * 16 + b_lrow) * BS_STRIDE + kk + b_koff) * 2;
        LDSM4(b[2 * nip][0], b[2 * nip][1], b[2 * nip + 1][0],
              b[2 * nip + 1][1], bd);
      }
#pragma unroll
      for (int mi = 0; mi < 4; mi++)
#pragma unroll
        for (int ni = 0; ni < 8; ni++) MMA_F16(acc[mi][ni], a[mi], b[ni]);
    }
  }

#pragma unroll
  for (int mi = 0; mi < 4; mi++) {
    int r0 = row0 + m0w + mi * 16 + g;
#pragma unroll
    for (int ni = 0; ni < 8; ni++) {
      int col = col0 + n0w + ni * 8 + 2 * t4;
      if (MODE == 0) {
        __half* C = (__half*)Cv;
        *(__half2*)(C + (size_t)r0 * N + col) =
            __floats2half2_rn(acc[mi][ni][0], acc[mi][ni][1]);
        *(__half2*)(C + (size_t)(r0 + 8) * N + col) =
            __floats2half2_rn(acc[mi][ni][2], acc[mi][ni][3]);
      } else if (MODE == 1) {
        __half* C = (__half*)Cv;
        int s0 = r0 & (S - 1);
        int b0 = r0 >> 11;
        int d = col & (HD - 1);
        __half* base = C + ((size_t)(b0 * HKV) + vb_base) * HD * S;
        base[(size_t)d * S + s0] = __float2half_rn(acc[mi][ni][0]);
        base[(size_t)(d + 1) * S + s0] = __float2half_rn(acc[mi][ni][1]);
        base[(size_t)d * S + s0 + 8] = __float2half_rn(acc[mi][ni][2]);
        base[(size_t)(d + 1) * S + s0 + 8] = __float2half_rn(acc[mi][ni][3]);
      } else {
        float* C = (float*)Cv;
        *(float2*)(C + (size_t)r0 * N + col) =
            make_float2(acc[mi][ni][0], acc[mi][ni][1]);
        *(float2*)(C + (size_t)(r0 + 8) * N + col) =
            make_float2(acc[mi][ni][2], acc[mi][ni][3]);
      }
    }
  }
}

__global__ void __launch_bounds__(128, 2)
qkv_gemm(const __half* __restrict__ xh, const __half* __restrict__ wqT,
         const __half* __restrict__ wkT, const __half* __restrict__ wvT,
         __half* __restrict__ q, __half* __restrict__ k,
         __half* __restrict__ vT) {
  extern __shared__ __half smp[];
  const int bx = blockIdx.x;
  const int row0 = blockIdx.y * 128;
  if (bx < 16) {
    gemm_body<0>(xh, wqT, q, QN, D, row0, bx * 128, smp, 0);
  } else if (bx < 20) {
    gemm_body<0>(xh, wkT, k, KN, D, row0, (bx - 16) * 128, smp, 0);
  } else {
    int col0 = (bx - 20) * 128;
    gemm_body<1>(xh, wvT, vT, KN, D, row0, col0, smp, col0 >> 7);
  }
}

__global__ void __launch_bounds__(128, 2)
o_gemm(const __half* __restrict__ attnh, const __half* __restrict__ woT,
       float* __restrict__ out) {
  extern __shared__ __half smp[];
  gemm_body<2>(attnh, woT, out, D, QN, blockIdx.y * 128, blockIdx.x * 128, smp, 0);
}

// ---------------------------------------------------------------------------
// RoPE (unchanged)
// ---------------------------------------------------------------------------
__global__ void __launch_bounds__(256)
rope_kernel(__half* __restrict__ q, __half* __restrict__ k) {
  const int row = blockIdx.x * 4 + (threadIdx.x >> 6);
  const int nh = H + HKV;
  const int bs = row / nh;
  const int hh = row - bs * nh;
  const int s = bs & (S - 1);
  __half* p = (hh < H) ? (q + (size_t)bs * QN + hh * HD)
                       : (k + (size_t)bs * KN + (hh - H) * HD);
  const int j = threadIdx.x & 63;
  const float x1 = __half2float(p[2 * j]);
  const float x2 = __half2float(p[2 * j + 1]);
  const float theta = exp2f(-(float)j * 0.20762050593045983f);
  const float ang = (float)s * theta;
  float sn, cs;
  sincosf(ang, &sn, &cs);
  __syncthreads();
  p[j] = __float2half_rn(x1 * cs - x2 * sn);
  p[j + 64] = __float2half_rn(x1 * sn + x2 * cs);
}

// ---------------------------------------------------------------------------
// Flash attention (R10 verbatim): FA2 register softmax, k-tile = 128,
// double-buffered K/V.
// ---------------------------------------------------------------------------
#define QS_STRIDE 136
#define KS_STRIDE 136
#define VT_STRIDE 136
#define KS_SZ (128 * KS_STRIDE)
#define VS_SZ (128 * VT_STRIDE)
#define ATTN_SMEM_BYTES ((128 * QS_STRIDE + 2 * KS_SZ + 2 * VS_SZ) * 2)

__device__ __forceinline__ void attn_issue_k(int tid, const __half* src,
                                             __half* dst) {
#pragma unroll
  for (int i = 0; i < 8; i++) {
    int idx = tid + i * 256;
    int n = idx >> 4, c8 = (idx & 15) << 3;
    uint32_t d = (uint32_t)__cvta_generic_to_shared(dst + n * KS_STRIDE + c8);
    CP16(d, src + (size_t)n * KN + c8);
  }
}
__device__ __forceinline__ void attn_issue_v(int tid, const __half* src,
                                             __half* dst) {
#pragma unroll
  for (int i = 0; i < 8; i++) {
    int idx = tid + i * 256;
    int dd = idx >> 4, c8 = (idx & 15) << 3;
    uint32_t d = (uint32_t)__cvta_generic_to_shared(dst + dd * VT_STRIDE + c8);
    CP16(d, src + (size_t)dd * S + c8);
  }
}

__global__ void __launch_bounds__(256, 1)
attn_kernel(const __half* __restrict__ Q, const __half* __restrict__ K,
            const __half* __restrict__ VT, __half* __restrict__ O) {
  extern __shared__ __half smh[];
  __half* Qs = smh;
  __half* Ks = Qs + 128 * QS_STRIDE;
  __half* Vs = Ks + 2 * KS_SZ;

  const int tid = threadIdx.x;
  const int lane = tid & 31;
  const int w = tid >> 5;
  const int g = lane >> 2;
  const int t4 = lane & 3;
  const int m0 = w * 16;

  const int a_lrow = (lane & 7) + ((lane >> 3) & 1) * 8;
  const int a_koff = (lane >> 4) * 8;
  const int b_lrow = (lane & 7) + (lane >> 4) * 8;
  const int b_koff = ((lane >> 3) & 1) * 8;

  const uint32_t qsu = (uint32_t)__cvta_generic_to_shared(Qs);
  const uint32_t ksu0 = (uint32_t)__cvta_generic_to_shared(Ks);
  const uint32_t vsu0 = (uint32_t)__cvta_generic_to_shared(Vs);

  const int qi = (int)gridDim.x - 1 - (int)blockIdx.x;
  const int bh = blockIdx.y;
  const int b = bh >> 4;
  const int h = bh & 15;
  const int hk = h >> 2;
  const int q0 = qi * 128;

  const __half* qb = Q + (size_t)b * S * QN + h * HD;
  const __half* kb = K + (size_t)b * S * KN + hk * HD;
  const __half* vtb = VT + ((size_t)(b * HKV + hk)) * HD * S;

  const int T = qi + 1;

#pragma unroll
  for (int i = 0; i < 8; i++) {
    int idx = tid + i * 256;
    int r = idx >> 4, c8 = (idx & 15) << 3;
    uint32_t d = (uint32_t)__cvta_generic_to_shared(Qs + r * QS_STRIDE + c8);
    CP16(d, qb + (size_t)(q0 + r) * QN + c8);
  }
  attn_issue_k(tid, kb, Ks);
  CP_COMMIT();
  attn_issue_v(tid, vtb, Vs);
  CP_COMMIT();
  attn_issue_k(tid, kb + (size_t)128 * KN, Ks + KS_SZ);
  CP_COMMIT();
  attn_issue_v(tid, vtb + 128, Vs + VS_SZ);
  CP_COMMIT();

  float oacc[16][4];
#pragma unroll
  for (int ni = 0; ni < 16; ni++)
#pragma unroll
    for (int e = 0; e < 4; e++) oacc[ni][e] = 0.f;

  float m0r = -INFINITY, m1r = -INFINITY;
  float l0r = 0.f, l1r = 0.f;

  const float qk_scale = 0.08838834764831845f;

  for (int t = 0; t < T; t++) {
    const int k0 = t << 7;
    const uint32_t ksu = ksu0 + (t & 1) * KS_SZ * 2;
    const uint32_t vsu = vsu0 + (t & 1) * VS_SZ * 2;

    CP_WAIT3();
    __syncthreads();

    float sacc[16][4];
#pragma unroll
    for (int ni = 0; ni < 16; ni++)
#pragma unroll
      for (int e = 0; e < 4; e++) sacc[ni][e] = 0.f;

#pragma unroll
    for (int ks = 0; ks < 8; ks++) {
      const int kk = ks * 16;
      uint32_t a[4];
      uint32_t ad = qsu + ((m0 + a_lrow) * QS_STRIDE + kk + a_koff) * 2;
      LDSM4(a[0], a[1], a[2], a[3], ad);
      uint32_t bfr[16][2];
#pragma unroll
      for (int nip = 0; nip < 8; nip++) {
        uint32_t bd = ksu + ((nip * 16 + b_lrow) * KS_STRIDE + kk + b_koff) * 2;
        LDSM4(bfr[2 * nip][0], bfr[2 * nip][1], bfr[2 * nip + 1][0],
              bfr[2 * nip + 1][1], bd);
      }
#pragma unroll
      for (int ni = 0; ni < 16; ni++) MMA_F16(sacc[ni], a, bfr[ni]);
    }

    const bool diag = (k0 + 127 > q0);
    const int qr0 = q0 + m0 + g, qr1 = qr0 + 8;
#pragma unroll
    for (int ni = 0; ni < 16; ni++) {
      float v0 = sacc[ni][0] * qk_scale;
      float v1 = sacc[ni][1] * qk_scale;
      float v2 = sacc[ni][2] * qk_scale;
      float v3 = sacc[ni][3] * qk_scale;
      if (diag) {
        int kc = k0 + ni * 8 + 2 * t4;
        if (kc > qr0) v0 = -1e30f;
        if (kc + 1 > qr0) v1 = -1e30f;
        if (kc > qr1) v2 = -1e30f;
        if (kc + 1 > qr1) v3 = -1e30f;
      }
      sacc[ni][0] = v0; sacc[ni][1] = v1; sacc[ni][2] = v2; sacc[ni][3] = v3;
    }

    float mx0 = -INFINITY, mx1 = -INFINITY;
#pragma unroll
    for (int ni = 0; ni < 16; ni++) {
      mx0 = fmaxf(mx0, fmaxf(sacc[ni][0], sacc[ni][1]));
      mx1 = fmaxf(mx1, fmaxf(sacc[ni][2], sacc[ni][3]));
    }
    mx0 = fmaxf(mx0, __shfl_xor_sync(0xffffffffu, mx0, 1));
    mx0 = fmaxf(mx0, __shfl_xor_sync(0xffffffffu, mx0, 2));
    mx1 = fmaxf(mx1, __shfl_xor_sync(0xffffffffu, mx1, 1));
    mx1 = fmaxf(mx1, __shfl_xor_sync(0xffffffffu, mx1, 2));
    const float mn0 = fmaxf(m0r, mx0);
    const float mn1 = fmaxf(m1r, mx1);

    uint32_t ph0[16], ph1[16];
    float s0 = 0.f, s1 = 0.f;
#pragma unroll
    for (int ni = 0; ni < 16; ni++) {
      __half2 e01 = __floats2half2_rn(__expf(sacc[ni][0] - mn0),
                                      __expf(sacc[ni][1] - mn0));
      __half2 e23 = __floats2half2_rn(__expf(sacc[ni][2] - mn1),
                                      __expf(sacc[ni][3] - mn1));
      ph0[ni] = *(uint32_t*)&e01;
      ph1[ni] = *(uint32_t*)&e23;
      float2 f01 = __half22float2(e01);
      float2 f23 = __half22float2(e23);
      s0 += f01.x + f01.y;
      s1 += f23.x + f23.y;
    }
    s0 += __shfl_xor_sync(0xffffffffu, s0, 1);
    s0 += __shfl_xor_sync(0xffffffffu, s0, 2);
    s1 += __shfl_xor_sync(0xffffffffu, s1, 1);
    s1 += __shfl_xor_sync(0xffffffffu, s1, 2);
    const float al0 = __expf(m0r - mn0);
    const float al1 = __expf(m1r - mn1);
    m0r = mn0; m1r = mn1;
    l0r = l0r * al0 + s0;
    l1r = l1r * al1 + s1;
#pragma unroll
    for (int ni = 0; ni < 16; ni++) {
      oacc[ni][0] *= al0;
      oacc[ni][1] *= al0;
      oacc[ni][2] *= al1;
      oacc[ni][3] *= al1;
    }

    CP_WAIT2();
    __syncthreads();

    if (t + 2 < T) attn_issue_k(tid, kb + (size_t)(k0 + 256) * KN,
                                Ks + (t & 1) * KS_SZ);
    CP_COMMIT();

#pragma unroll
    for (int ks = 0; ks < 8; ks++) {
      const int kk = ks * 16;
      uint32_t a[4];
      a[0] = ph0[2 * ks];
      a[1] = ph1[2 * ks];
      a[2] = ph0[2 * ks + 1];
      a[3] = ph1[2 * ks + 1];
      uint32_t bfr[16][2];
#pragma unroll
      for (int nip = 0; nip < 8; nip++) {
        uint32_t bd = vsu + ((nip * 16 + b_lrow) * VT_STRIDE + kk + b_koff) * 2;
        LDSM4(bfr[2 * nip][0], bfr[2 * nip][1], bfr[2 * nip + 1][0],
              bfr[2 * nip + 1][1], bd);
      }
#pragma unroll
      for (int ni = 0; ni < 16; ni++) MMA_F16(oacc[ni], a, bfr[ni]);
    }
    __syncthreads();

    if (t + 2 < T) attn_issue_v(tid, vtb + k0 + 256, Vs + (t & 1) * VS_SZ);
    CP_COMMIT();
  }

  {
    const float inv0 = 1.f / l0r;
    const float inv1 = 1.f / l1r;
    __half* o0 = O + (size_t)(b * S + q0 + m0 + g) * QN + h * HD + 2 * t4;
    __half* o1 = o0 + (size_t)8 * QN;
#pragma unroll
    for (int ni = 0; ni < 16; ni++) {
      *(__half2*)(o0 + ni * 8) =
          __floats2half2_rn(oacc[ni][0] * inv0, oacc[ni][1] * inv0);
      *(__half2*)(o1 + ni * 8) =
          __floats2half2_rn(oacc[ni][2] * inv1, oacc[ni][3] * inv1);
    }
  }
}

// ---------------------------------------------------------------------------
extern "C" void kernel_launch(void* const* d_in, const int* in_sizes, int n_in,
                              void* d_out, int out_size) {
  const float* x  = (const float*)d_in[0];
  const float* Wq = (const float*)d_in[1];
  const float* Wk = (const float*)d_in[2];
  const float* Wv = (const float*)d_in[3];
  const float* Wo = (const float*)d_in[4];
  float* out = (float*)d_out;

  __half *xh, *wqT, *wkT, *wvT, *woT, *qh, *kh, *vT, *attnh;
  cudaGetSymbolAddress((void**)&xh, g_xh);
  cudaGetSymbolAddress((void**)&wqT, g_wqT);
  cudaGetSymbolAddress((void**)&wkT, g_wkT);
  cudaGetSymbolAddress((void**)&wvT, g_wvT);
  cudaGetSymbolAddress((void**)&woT, g_woT);
  cudaGetSymbolAddress((void**)&qh, g_qh);
  cudaGetSymbolAddress((void**)&kh, g_kh);
  cudaGetSymbolAddress((void**)&vT, g_vT);
  cudaGetSymbolAddress((void**)&attnh, g_attnh);

  cudaFuncSetAttribute(qkv_gemm, cudaFuncAttributeMaxDynamicSharedMemorySize,
                       GEMM_SMEM_BYTES);
  cudaFuncSetAttribute(o_gemm, cudaFuncAttributeMaxDynamicSharedMemorySize,
                       GEMM_SMEM_BYTES);
  cudaFuncSetAttribute(attn_kernel, cudaFuncAttributeMaxDynamicSharedMemorySize,
                       ATTN_SMEM_BYTES);

  conv_half<<<(M_ROWS * D / 4 + 255) / 256, 256>>>(x, xh, M_ROWS * D / 4);
  transpose_all<<<dim3(64, 64, 4), dim3(32, 8)>>>(Wq, Wk, Wv, Wo,
                                                  wqT, wkT, wvT, woT);

  qkv_gemm<<<dim3(24, M_ROWS / 128), 128, GEMM_SMEM_BYTES>>>(xh, wqT, wkT, wvT,
                                                             qh, kh, vT);
  rope_kernel<<<B * S * (H + HKV) / 4, 256>>>(qh, kh);
  attn_kernel<<<dim3(S / 128, B * H), 256, ATTN_SMEM_BYTES>>>(qh, kh, vT, attnh);
  o_gemm<<<dim3(D / 128, M_ROWS / 128), 128, GEMM_SMEM_BYTES>>>(attnh, woT, out);
}

// round 12
// speedup vs baseline: 6.8194x; 1.0001x over previous
#include <cuda_runtime.h>
#include <cuda_fp16.h>
#include <math.h>
#include <stdint.h>

#define B 2
#define S 2048
#define D 2048
#define H 16
#define HKV 4
#define HD 128
#define M_ROWS (B*S)     // 4096
#define QN (H*HD)        // 2048
#define KN (HKV*HD)      // 512

// Scratch (allocation-free: device globals), fp16 operands everywhere
__device__ __half g_xh[(size_t)M_ROWS * D];
__device__ __half g_wqT[(size_t)QN * D];    // [N][K]
__device__ __half g_wkT[(size_t)KN * D];
__device__ __half g_wvT[(size_t)KN * D];
__device__ __half g_woT[(size_t)D * QN];
__device__ __half g_qh[(size_t)M_ROWS * QN];
__device__ __half g_kh[(size_t)M_ROWS * KN];
__device__ __half g_vT[(size_t)B * HKV * HD * S];  // [b][hk][d][s]
__device__ __half g_attnh[(size_t)M_ROWS * QN];

#define MMA_F16(c, a, b)                                                      \
  asm("mma.sync.aligned.m16n8k16.row.col.f32.f16.f16.f32 "                    \
      "{%0,%1,%2,%3},{%4,%5,%6,%7},{%8,%9},{%0,%1,%2,%3};"                    \
      : "+f"(c[0]), "+f"(c[1]), "+f"(c[2]), "+f"(c[3])                        \
      : "r"(a[0]), "r"(a[1]), "r"(a[2]), "r"(a[3]), "r"(b[0]), "r"(b[1]))

#define LDSM4(r0, r1, r2, r3, addr)                                           \
  asm volatile("ldmatrix.sync.aligned.m8n8.x4.shared.b16 {%0,%1,%2,%3}, [%4];"\
               : "=r"(r0), "=r"(r1), "=r"(r2), "=r"(r3) : "r"(addr))

#define CP16(dst, src)                                                        \
  asm volatile("cp.async.cg.shared.global [%0], [%1], 16;" ::"r"(dst), "l"(src))
#define CP_COMMIT() asm volatile("cp.async.commit_group;")
#define CP_WAIT1()  asm volatile("cp.async.wait_group 1;")

// ---------------------------------------------------------------------------
// fp32 -> fp16 convert (x), batched tiled transpose+convert (all 4 weights)
// ---------------------------------------------------------------------------
__global__ void conv_half(const float* __restrict__ src,
                          __half* __restrict__ dst, int n4) {
  int i = blockIdx.x * blockDim.x + threadIdx.x;
  if (i < n4) {
    float4 v = *(const float4*)(src + 4 * (size_t)i);
    *(__half2*)(dst + 4 * (size_t)i) = __floats2half2_rn(v.x, v.y);
    *(__half2*)(dst + 4 * (size_t)i + 2) = __floats2half2_rn(v.z, v.w);
  }
}

__global__ void transpose_all(const float* __restrict__ Wq,
                              const float* __restrict__ Wk,
                              const float* __restrict__ Wv,
                              const float* __restrict__ Wo,
                              __half* __restrict__ wqT, __half* __restrict__ wkT,
                              __half* __restrict__ wvT, __half* __restrict__ woT) {
  __shared__ float t[32][33];
  const float* src;
  __half* dst;
  int R, C;
  switch (blockIdx.z) {
    case 0: src = Wq; dst = wqT; R = D;  C = QN; break;
    case 1: src = Wk; dst = wkT; R = D;  C = KN; break;
    case 2: src = Wv; dst = wvT; R = D;  C = KN; break;
    default: src = Wo; dst = woT; R = QN; C = D;  break;
  }
  int c0 = blockIdx.x * 32, r0 = blockIdx.y * 32;
  if (c0 >= C || r0 >= R) return;
  int x = threadIdx.x, y = threadIdx.y;
#pragma unroll
  for (int i = 0; i < 32; i += 8)
    t[y + i][x] = src[(size_t)(r0 + y + i) * C + c0 + x];
  __syncthreads();
#pragma unroll
  for (int i = 0; i < 32; i += 8)
    dst[(size_t)(c0 + y + i) * R + r0 + x] = __float2half_rn(t[x][y + i]);
}

// ---------------------------------------------------------------------------
// fp16 MMA GEMM: 128x128x32 block tile, 128 threads (4 warps, warp 64x64),
// 3-buffer single-barrier cp.async pipeline, ldmatrix fragments, 2 CTAs/SM.
// Epilogues: 0 half, 1 V^T half, 2 fp32, 3 half + fused RoPE (Q/K proj).
// ---------------------------------------------------------------------------
#define AS_STRIDE 40
#define BS_STRIDE 40
#define AS_SZ (128 * AS_STRIDE)
#define BS_SZ (128 * BS_STRIDE)
#define GEMM_SMEM_BYTES (3 * (AS_SZ + BS_SZ) * 2)

__device__ __forceinline__ void gemm_issue_slab(
    int tid, const __half* __restrict__ A, const __half* __restrict__ BT,
    int K, int row0, int col0, int k0, __half* as, __half* bs) {
#pragma unroll
  for (int l = 0; l < 4; l++) {
    int idx = tid + l * 128;
    int ar = idx >> 2, ac = (idx & 3) << 3;
    const __half* asrc = A + (size_t)(row0 + ar) * K + k0 + ac;
    uint32_t adst = (uint32_t)__cvta_generic_to_shared(as + ar * AS_STRIDE + ac);
    CP16(adst, asrc);
  }
#pragma unroll
  for (int l = 0; l < 4; l++) {
    int idx = tid + l * 128;
    int br = idx >> 2, bc = (idx & 3) << 3;
    const __half* bsrc = BT + (size_t)(col0 + br) * K + k0 + bc;
    uint32_t bdst = (uint32_t)__cvta_generic_to_shared(bs + br * BS_STRIDE + bc);
    CP16(bdst, bsrc);
  }
}

template <int MODE>
__device__ __forceinline__ void gemm_body(
    const __half* __restrict__ A, const __half* __restrict__ BT,
    void* __restrict__ Cv, int N, int K, int row0, int col0, __half* smp,
    int vb_base) {
  __half* As = smp;                 // 3 x [128][40]
  __half* Bs = smp + 3 * AS_SZ;     // 3 x [128][40]

  const int tid = threadIdx.x;
  const int lane = tid & 31;
  const int w = tid >> 5;
  const int g = lane >> 2;
  const int t4 = lane & 3;
  const int warp_m = w & 1, warp_n = w >> 1;
  const int m0w = warp_m * 64, n0w = warp_n * 64;

  const int a_lrow = (lane & 7) + ((lane >> 3) & 1) * 8;
  const int a_koff = (lane >> 4) * 8;
  const int b_lrow = (lane & 7) + (lane >> 4) * 8;
  const int b_koff = ((lane >> 3) & 1) * 8;

  float acc[4][8][4];
#pragma unroll
  for (int mi = 0; mi < 4; mi++)
#pragma unroll
    for (int ni = 0; ni < 8; ni++)
#pragma unroll
      for (int e = 0; e < 4; e++) acc[mi][ni][e] = 0.f;

  gemm_issue_slab(tid, A, BT, K, row0, col0, 0, As, Bs);
  CP_COMMIT();
  gemm_issue_slab(tid, A, BT, K, row0, col0, 32, As + AS_SZ, Bs + BS_SZ);
  CP_COMMIT();

  const uint32_t asu0 = (uint32_t)__cvta_generic_to_shared(As);
  const uint32_t bsu0 = (uint32_t)__cvta_generic_to_shared(Bs);

  const int nslab = K >> 5;
  for (int it = 0; it < nslab; it++) {
    CP_WAIT1();
    __syncthreads();
    int kn = it + 2;
    if (kn < nslab)
      gemm_issue_slab(tid, A, BT, K, row0, col0, kn << 5,
                      As + (kn % 3) * AS_SZ, Bs + (kn % 3) * BS_SZ);
    CP_COMMIT();

    const uint32_t asu = asu0 + (it % 3) * AS_SZ * 2;
    const uint32_t bsu = bsu0 + (it % 3) * BS_SZ * 2;
#pragma unroll
    for (int ks = 0; ks < 2; ks++) {
      const int kk = ks * 16;
      uint32_t a[4][4];
#pragma unroll
      for (int mi = 0; mi < 4; mi++) {
        uint32_t ad = asu +
            ((m0w + mi * 16 + a_lrow) * AS_STRIDE + kk + a_koff) * 2;
        LDSM4(a[mi][0], a[mi][1], a[mi][2], a[mi][3], ad);
      }
      uint32_t b[8][2];
#pragma unroll
      for (int nip = 0; nip < 4; nip++) {
        uint32_t bd = bsu +
            ((n0w + nip * 16 + b_lrow) * BS_STRIDE + kk + b_koff) * 2;
        LDSM4(b[2 * nip][0], b[2 * nip][1], b[2 * nip + 1][0],
              b[2 * nip + 1][1], bd);
      }
#pragma unroll
      for (int mi = 0; mi < 4; mi++)
#pragma unroll
        for (int ni = 0; ni < 8; ni++) MMA_F16(acc[mi][ni], a[mi], b[ni]);
    }
  }

#pragma unroll
  for (int mi = 0; mi < 4; mi++) {
    int r0 = row0 + m0w + mi * 16 + g;
#pragma unroll
    for (int ni = 0; ni < 8; ni++) {
      int col = col0 + n0w + ni * 8 + 2 * t4;
      if (MODE == 0) {
        __half* C = (__half*)Cv;
        *(__half2*)(C + (size_t)r0 * N + col) =
            __floats2half2_rn(acc[mi][ni][0], acc[mi][ni][1]);
        *(__half2*)(C + (size_t)(r0 + 8) * N + col) =
            __floats2half2_rn(acc[mi][ni][2], acc[mi][ni][3]);
      } else if (MODE == 1) {
        __half* C = (__half*)Cv;
        int s0 = r0 & (S - 1);
        int b0 = r0 >> 11;
        int d = col & (HD - 1);
        __half* base = C + ((size_t)(b0 * HKV) + vb_base) * HD * S;
        base[(size_t)d * S + s0] = __float2half_rn(acc[mi][ni][0]);
        base[(size_t)(d + 1) * S + s0] = __float2half_rn(acc[mi][ni][1]);
        base[(size_t)d * S + s0 + 8] = __float2half_rn(acc[mi][ni][2]);
        base[(size_t)(d + 1) * S + s0 + 8] = __float2half_rn(acc[mi][ni][3]);
      } else if (MODE == 2) {
        float* C = (float*)Cv;
        *(float2*)(C + (size_t)r0 * N + col) =
            make_float2(acc[mi][ni][0], acc[mi][ni][1]);
        *(float2*)(C + (size_t)(r0 + 8) * N + col) =
            make_float2(acc[mi][ni][2], acc[mi][ni][3]);
      } else {  // MODE 3: fused RoPE. Thread holds cols (2j, 2j+1) of one head.
        __half* C = (__half*)Cv;
        const int s0 = r0 & (S - 1);
        const int jj = (col & 127) >> 1;
        const int cb = col - (col & 127);  // head base column
        const float theta = exp2f(-(float)jj * 0.20762050593045983f);
        float sn0, cs0, sn1, cs1;
        sincosf((float)s0 * theta, &sn0, &cs0);
        sincosf((float)(s0 + 8) * theta, &sn1, &cs1);
        __half* p0 = C + (size_t)r0 * N + cb + jj;
        __half* p1 = C + (size_t)(r0 + 8) * N + cb + jj;
        p0[0]  = __float2half_rn(acc[mi][ni][0] * cs0 - acc[mi][ni][1] * sn0);
        p0[64] = __float2half_rn(acc[mi][ni][0] * sn0 + acc[mi][ni][1] * cs0);
        p1[0]  = __float2half_rn(acc[mi][ni][2] * cs1 - acc[mi][ni][3] * sn1);
        p1[64] = __float2half_rn(acc[mi][ni][2] * sn1 + acc[mi][ni][3] * cs1);
      }
    }
  }
}

__global__ void __launch_bounds__(128, 2)
qkv_gemm(const __half* __restrict__ xh, const __half* __restrict__ wqT,
         const __half* __restrict__ wkT, const __half* __restrict__ wvT,
         __half* __restrict__ q, __half* __restrict__ k,
         __half* __restrict__ vT) {
  extern __shared__ __half smp[];
  const int bx = blockIdx.x;
  const int row0 = blockIdx.y * 128;
  if (bx < 16) {
    gemm_body<3>(xh, wqT, q, QN, D, row0, bx * 128, smp, 0);      // Q + RoPE
  } else if (bx < 20) {
    gemm_body<3>(xh, wkT, k, KN, D, row0, (bx - 16) * 128, smp, 0); // K + RoPE
  } else {
    int col0 = (bx - 20) * 128;
    gemm_body<1>(xh, wvT, vT, KN, D, row0, col0, smp, col0 >> 7);
  }
}

__global__ void __launch_bounds__(128, 2)
o_gemm(const __half* __restrict__ attnh, const __half* __restrict__ woT,
       float* __restrict__ out) {
  extern __shared__ __half smp[];
  gemm_body<2>(attnh, woT, out, D, QN, blockIdx.y * 128, blockIdx.x * 128, smp, 0);
}

// ---------------------------------------------------------------------------
// Flash attention: 128 threads (4 warps x 16 q-rows = 64 q-rows), k-tile 128,
// single-buffered K/V with phase-overlapped prefetch, register softmax.
// 87 KB smem + ~200 regs -> 2 CTAs/SM.
// ---------------------------------------------------------------------------
#define QS_STRIDE 136
#define KS_STRIDE 136
#define VT_STRIDE 136
#define ATTN_SMEM_BYTES ((64 * QS_STRIDE + 128 * KS_STRIDE + 128 * VT_STRIDE) * 2)

__device__ __forceinline__ void attn_issue_k(int tid, const __half* src,
                                             __half* dst) {
#pragma unroll
  for (int i = 0; i < 16; i++) {
    int idx = tid + i * 128;
    int n = idx >> 4, c8 = (idx & 15) << 3;
    uint32_t d = (uint32_t)__cvta_generic_to_shared(dst + n * KS_STRIDE + c8);
    CP16(d, src + (size_t)n * KN + c8);
  }
}
__device__ __forceinline__ void attn_issue_v(int tid, const __half* src,
                                             __half* dst) {
#pragma unroll
  for (int i = 0; i < 16; i++) {
    int idx = tid + i * 128;
    int dd = idx >> 4, c8 = (idx & 15) << 3;
    uint32_t d = (uint32_t)__cvta_generic_to_shared(dst + dd * VT_STRIDE + c8);
    CP16(d, src + (size_t)dd * S + c8);
  }
}

__global__ void __launch_bounds__(128, 2)
attn_kernel(const __half* __restrict__ Q, const __half* __restrict__ K,
            const __half* __restrict__ VT, __half* __restrict__ O) {
  extern __shared__ __half smh[];
  __half* Qs = smh;                      // [64][136]
  __half* Ks = Qs + 64 * QS_STRIDE;      // [128][136]
  __half* Vs = Ks + 128 * KS_STRIDE;     // [128][136] (V^T)

  const int tid = threadIdx.x;
  const int lane = tid & 31;
  const int w = tid >> 5;                // 0..3
  const int g = lane >> 2;
  const int t4 = lane & 3;
  const int m0 = w * 16;

  const int a_lrow = (lane & 7) + ((lane >> 3) & 1) * 8;
  const int a_koff = (lane >> 4) * 8;
  const int b_lrow = (lane & 7) + (lane >> 4) * 8;
  const int b_koff = ((lane >> 3) & 1) * 8;

  const uint32_t qsu = (uint32_t)__cvta_generic_to_shared(Qs);
  const uint32_t ksu = (uint32_t)__cvta_generic_to_shared(Ks);
  const uint32_t vsu = (uint32_t)__cvta_generic_to_shared(Vs);

  const int qi = (int)gridDim.x - 1 - (int)blockIdx.x;  // heavy tiles first
  const int bh = blockIdx.y;
  const int b = bh >> 4;
  const int h = bh & 15;
  const int hk = h >> 2;
  const int q0 = qi * 64;

  const __half* qb = Q + (size_t)b * S * QN + h * HD;
  const __half* kb = K + (size_t)b * S * KN + hk * HD;
  const __half* vtb = VT + ((size_t)(b * HKV + hk)) * HD * S;

  const int T = (q0 >> 7) + 1;

  // Prologue: G1 = Q + K0, G2 = V0
#pragma unroll
  for (int i = 0; i < 8; i++) {
    int idx = tid + i * 128;
    int r = idx >> 4, c8 = (idx & 15) << 3;
    uint32_t d = (uint32_t)__cvta_generic_to_shared(Qs + r * QS_STRIDE + c8);
    CP16(d, qb + (size_t)(q0 + r) * QN + c8);
  }
  attn_issue_k(tid, kb, Ks);
  CP_COMMIT();
  attn_issue_v(tid, vtb, Vs);
  CP_COMMIT();

  float oacc[16][4];
#pragma unroll
  for (int ni = 0; ni < 16; ni++)
#pragma unroll
    for (int e = 0; e < 4; e++) oacc[ni][e] = 0.f;

  float m0r = -INFINITY, m1r = -INFINITY;
  float l0r = 0.f, l1r = 0.f;

  const float qk_scale = 0.08838834764831845f;

  for (int t = 0; t < T; t++) {
    const int k0 = t << 7;

    CP_WAIT1();         // K_t (and Q on t=0) ready; V_t may be in flight
    __syncthreads();

    // ---- scores: 16 rows x 128 cols, k = 128 ----
    float sacc[16][4];
#pragma unroll
    for (int ni = 0; ni < 16; ni++)
#pragma unroll
      for (int e = 0; e < 4; e++) sacc[ni][e] = 0.f;

#pragma unroll
    for (int ks = 0; ks < 8; ks++) {
      const int kk = ks * 16;
      uint32_t a[4];
      uint32_t ad = qsu + ((m0 + a_lrow) * QS_STRIDE + kk + a_koff) * 2;
      LDSM4(a[0], a[1], a[2], a[3], ad);
      uint32_t bfr[16][2];
#pragma unroll
      for (int nip = 0; nip < 8; nip++) {
        uint32_t bd = ksu + ((nip * 16 + b_lrow) * KS_STRIDE + kk + b_koff) * 2;
        LDSM4(bfr[2 * nip][0], bfr[2 * nip][1], bfr[2 * nip + 1][0],
              bfr[2 * nip + 1][1], bd);
      }
#pragma unroll
      for (int ni = 0; ni < 16; ni++) MMA_F16(sacc[ni], a, bfr[ni]);
    }
    __syncthreads();    // all warps done reading Ks

    // Prefetch K_{t+1} (overlaps softmax below + PV)
    if (t + 1 < T) attn_issue_k(tid, kb + (size_t)(k0 + 128) * KN, Ks);
    CP_COMMIT();

    // ---- scale + causal mask (registers) ----
    const bool diag = (k0 + 127 > q0);
    const int qr0 = q0 + m0 + g, qr1 = qr0 + 8;
#pragma unroll
    for (int ni = 0; ni < 16; ni++) {
      float v0 = sacc[ni][0] * qk_scale;
      float v1 = sacc[ni][1] * qk_scale;
      float v2 = sacc[ni][2] * qk_scale;
      float v3 = sacc[ni][3] * qk_scale;
      if (diag) {
        int kc = k0 + ni * 8 + 2 * t4;
        if (kc > qr0) v0 = -1e30f;
        if (kc + 1 > qr0) v1 = -1e30f;
        if (kc > qr1) v2 = -1e30f;
        if (kc + 1 > qr1) v3 = -1e30f;
      }
      sacc[ni][0] = v0; sacc[ni][1] = v1; sacc[ni][2] = v2; sacc[ni][3] = v3;
    }

    // ---- register softmax (rows g, g+8; reduce across quad t4) ----
    float mx0 = -INFINITY, mx1 = -INFINITY;
#pragma unroll
    for (int ni = 0; ni < 16; ni++) {
      mx0 = fmaxf(mx0, fmaxf(sacc[ni][0], sacc[ni][1]));
      mx1 = fmaxf(mx1, fmaxf(sacc[ni][2], sacc[ni][3]));
    }
    mx0 = fmaxf(mx0, __shfl_xor_sync(0xffffffffu, mx0, 1));
    mx0 = fmaxf(mx0, __shfl_xor_sync(0xffffffffu, mx0, 2));
    mx1 = fmaxf(mx1, __shfl_xor_sync(0xffffffffu, mx1, 1));
    mx1 = fmaxf(mx1, __shfl_xor_sync(0xffffffffu, mx1, 2));
    const float mn0 = fmaxf(m0r, mx0);
    const float mn1 = fmaxf(m1r, mx1);

    uint32_t ph0[16], ph1[16];
    float s0 = 0.f, s1 = 0.f;
#pragma unroll
    for (int ni = 0; ni < 16; ni++) {
      __half2 e01 = __floats2half2_rn(__expf(sacc[ni][0] - mn0),
                                      __expf(sacc[ni][1] - mn0));
      __half2 e23 = __floats2half2_rn(__expf(sacc[ni][2] - mn1),
                                      __expf(sacc[ni][3] - mn1));
      ph0[ni] = *(uint32_t*)&e01;
      ph1[ni] = *(uint32_t*)&e23;
      float2 f01 = __half22float2(e01);
      float2 f23 = __half22float2(e23);
      s0 += f01.x + f01.y;
      s1 += f23.x + f23.y;
    }
    s0 += __shfl_xor_sync(0xffffffffu, s0, 1);
    s0 += __shfl_xor_sync(0xffffffffu, s0, 2);
    s1 += __shfl_xor_sync(0xffffffffu, s1, 1);
    s1 += __shfl_xor_sync(0xffffffffu, s1, 2);
    const float al0 = __expf(m0r - mn0);
    const float al1 = __expf(m1r - mn1);
    m0r = mn0; m1r = mn1;
    l0r = l0r * al0 + s0;
    l1r = l1r * al1 + s1;
#pragma unroll
    for (int ni = 0; ni < 16; ni++) {
      oacc[ni][0] *= al0;
      oacc[ni][1] *= al0;
      oacc[ni][2] *= al1;
      oacc[ni][3] *= al1;
    }

    CP_WAIT1();         // V_t ready (K_{t+1} may remain in flight)
    __syncthreads();

    // ---- PV: A from registers (ph), B = V^T tiles from smem, k = 128 ----
#pragma unroll
    for (int ks = 0; ks < 8; ks++) {
      const int kk = ks * 16;
      uint32_t a[4];
      a[0] = ph0[2 * ks];
      a[1] = ph1[2 * ks];
      a[2] = ph0[2 * ks + 1];
      a[3] = ph1[2 * ks + 1];
      uint32_t bfr[16][2];
#pragma unroll
      for (int nip = 0; nip < 8; nip++) {
        uint32_t bd = vsu + ((nip * 16 + b_lrow) * VT_STRIDE + kk + b_koff) * 2;
        LDSM4(bfr[2 * nip][0], bfr[2 * nip][1], bfr[2 * nip + 1][0],
              bfr[2 * nip + 1][1], bd);
      }
#pragma unroll
      for (int ni = 0; ni < 16; ni++) MMA_F16(oacc[ni], a, bfr[ni]);
    }
    __syncthreads();    // all warps done reading Vs

    // Prefetch V_{t+1} (overlaps next scores)
    if (t + 1 < T) attn_issue_v(tid, vtb + k0 + 128, Vs);
    CP_COMMIT();
  }

  // ---- finalize: O = half(oacc / l) ----
  {
    const float inv0 = 1.f / l0r;
    const float inv1 = 1.f / l1r;
    __half* o0 = O + (size_t)(b * S + q0 + m0 + g) * QN + h * HD + 2 * t4;
    __half* o1 = o0 + (size_t)8 * QN;
#pragma unroll
    for (int ni = 0; ni < 16; ni++) {
      *(__half2*)(o0 + ni * 8) =
          __floats2half2_rn(oacc[ni][0] * inv0, oacc[ni][1] * inv0);
      *(__half2*)(o1 + ni * 8) =
          __floats2half2_rn(oacc[ni][2] * inv1, oacc[ni][3] * inv1);
    }
  }
}

// ---------------------------------------------------------------------------
extern "C" void kernel_launch(void* const* d_in, const int* in_sizes, int n_in,
                              void* d_out, int out_size) {
  const float* x  = (const float*)d_in[0];
  const float* Wq = (const float*)d_in[1];
  const float* Wk = (const float*)d_in[2];
  const float* Wv = (const float*)d_in[3];
  const float* Wo = (const float*)d_in[4];
  float* out = (float*)d_out;

  __half *xh, *wqT, *wkT, *wvT, *woT, *qh, *kh, *vT, *attnh;
  cudaGetSymbolAddress((void**)&xh, g_xh);
  cudaGetSymbolAddress((void**)&wqT, g_wqT);
  cudaGetSymbolAddress((void**)&wkT, g_wkT);
  cudaGetSymbolAddress((void**)&wvT, g_wvT);
  cudaGetSymbolAddress((void**)&woT, g_woT);
  cudaGetSymbolAddress((void**)&qh, g_qh);
  cudaGetSymbolAddress((void**)&kh, g_kh);
  cudaGetSymbolAddress((void**)&vT, g_vT);
  cudaGetSymbolAddress((void**)&attnh, g_attnh);

  cudaFuncSetAttribute(qkv_gemm, cudaFuncAttributeMaxDynamicSharedMemorySize,
                       GEMM_SMEM_BYTES);
  cudaFuncSetAttribute(o_gemm, cudaFuncAttributeMaxDynamicSharedMemorySize,
                       GEMM_SMEM_BYTES);
  cudaFuncSetAttribute(attn_kernel, cudaFuncAttributeMaxDynamicSharedMemorySize,
                       ATTN_SMEM_BYTES);

  conv_half<<<(M_ROWS * D / 4 + 255) / 256, 256>>>(x, xh, M_ROWS * D / 4);
  transpose_all<<<dim3(64, 64, 4), dim3(32, 8)>>>(Wq, Wk, Wv, Wo,
                                                  wqT, wkT, wvT, woT);

  qkv_gemm<<<dim3(24, M_ROWS / 128), 128, GEMM_SMEM_BYTES>>>(xh, wqT, wkT, wvT,
                                                             qh, kh, vT);
  attn_kernel<<<dim3(S / 64, B * H), 128, ATTN_SMEM_BYTES>>>(qh, kh, vT, attnh);
  o_gemm<<<dim3(D / 128, M_ROWS / 128), 128, GEMM_SMEM_BYTES>>>(attnh, woT, out);
}